// round 9
// baseline (speedup 1.0000x reference)
#include <cuda_runtime.h>
#include <cuda_bf16.h>
#include <math.h>
#include <stdint.h>

#define NH     12
#define DH     64
#define DM     768
#define NB     256
#define LEN    1024
#define BATCH  8

typedef __nv_bfloat16 bf16;

#define NBDM   (NB * DM)        // 196608
#define LDM_C  (LEN * DM)       // 786432

// ---------------- device scratch (static; no allocations) ----------------
__device__ __align__(16) bf16 g_xt0[BATCH * DM * LEN];
__device__ __align__(16) bf16 g_xt1[BATCH * DM * LEN];
__device__ __align__(16) bf16 g_Gt0[NB * LEN];
__device__ __align__(16) bf16 g_Gt1[NB * LEN];
__device__ __align__(16) bf16 g_Wv0[DM * DM]; __device__ __align__(16) bf16 g_Wv1[DM * DM];
__device__ __align__(16) bf16 g_Wo0[DM * DM]; __device__ __align__(16) bf16 g_Wo1[DM * DM];
__device__ __align__(16) bf16 g_B0 [BATCH * NBDM];
__device__ __align__(16) bf16 g_B1 [BATCH * NBDM];
__device__ __align__(16) float g_Bp[BATCH * 4 * NBDM];   // Bmat split-K partials (25 MB)
__device__ __align__(16) float g_Vp[BATCH * 3 * NBDM];   // V split-K partials (19 MB)
__device__ __align__(16) float g_Op[BATCH * 2 * LDM_C];  // out split-K partials (50 MB)
__device__ __align__(16) bf16 g_Vt0[BATCH * NH * DH * NB];
__device__ __align__(16) bf16 g_Vt1[BATCH * NH * DH * NB];
__device__ float g_C [BATCH * 2 * DM];
__device__ float g_KW[BATCH * 2 * DM];
__device__ float g_T [BATCH * 24 * DM];
__device__ float g_mu[BATCH * NH * LEN];
__device__ float g_ss[BATCH * NH * LEN];
__device__ __align__(16) bf16 g_ctx0[BATCH * LDM_C];
__device__ __align__(16) bf16 g_ctx1[BATCH * LDM_C];

// ---------------- helpers ----------------
__device__ __forceinline__ uint32_t smem_u32(const void* p)
{
    uint32_t a;
    asm("{ .reg .u64 t; cvta.to.shared.u64 t, %1; cvt.u32.u64 %0, t; }"
        : "=r"(a) : "l"(p));
    return a;
}
__device__ __forceinline__ void mma16816(float* c, const uint32_t* a, const uint32_t* b)
{
    asm volatile("mma.sync.aligned.m16n8k16.row.col.f32.bf16.bf16.f32 "
                 "{%0,%1,%2,%3}, {%4,%5,%6,%7}, {%8,%9}, {%0,%1,%2,%3};"
                 : "+f"(c[0]), "+f"(c[1]), "+f"(c[2]), "+f"(c[3])
                 : "r"(a[0]), "r"(a[1]), "r"(a[2]), "r"(a[3]), "r"(b[0]), "r"(b[1]));
}
__device__ __forceinline__ void ldsm4(uint32_t* r, const bf16* p)
{
    uint32_t a = smem_u32(p);
    asm volatile("ldmatrix.sync.aligned.m8n8.x4.shared.b16 {%0,%1,%2,%3}, [%4];"
                 : "=r"(r[0]), "=r"(r[1]), "=r"(r[2]), "=r"(r[3]) : "r"(a));
}
__device__ __forceinline__ void cpa16(bf16* s, const bf16* g)
{
    uint32_t sa = smem_u32(s);
    asm volatile("cp.async.cg.shared.global [%0], [%1], 16;" :: "r"(sa), "l"(g));
}

// ---------------- split / transpose conversions ----------------
__global__ __launch_bounds__(256)
void split_kernel(const float* __restrict__ src, bf16* __restrict__ d0,
                  bf16* __restrict__ d1, int n)
{
    int i = (blockIdx.x * 256 + threadIdx.x) * 4;
    if (i >= n) return;
    float4 v = *(const float4*)(src + i);
    bf16 h0 = __float2bfloat16(v.x), h1 = __float2bfloat16(v.y);
    bf16 h2 = __float2bfloat16(v.z), h3 = __float2bfloat16(v.w);
    bf16 l0 = __float2bfloat16(v.x - __bfloat162float(h0));
    bf16 l1 = __float2bfloat16(v.y - __bfloat162float(h1));
    bf16 l2 = __float2bfloat16(v.z - __bfloat162float(h2));
    bf16 l3 = __float2bfloat16(v.w - __bfloat162float(h3));
    *(__nv_bfloat162*)(d0 + i)     = __nv_bfloat162(h0, h1);
    *(__nv_bfloat162*)(d0 + i + 2) = __nv_bfloat162(h2, h3);
    *(__nv_bfloat162*)(d1 + i)     = __nv_bfloat162(l0, l1);
    *(__nv_bfloat162*)(d1 + i + 2) = __nv_bfloat162(l2, l3);
}

__global__ __launch_bounds__(256)
void tsplit_kernel(const float* __restrict__ src, long long sb_in, int ldin,
                   bf16* __restrict__ d0, bf16* __restrict__ d1,
                   long long sb_out, int ldout)
{
    __shared__ float tile[32][33];
    int b = blockIdx.z;
    const float* s = src + (long long)b * sb_in;
    int m0 = blockIdx.y * 32, n0 = blockIdx.x * 32;
#pragma unroll
    for (int i = 0; i < 4; i++) {
        int m = m0 + threadIdx.y + i * 8;
        tile[threadIdx.y + i * 8][threadIdx.x] = s[(long long)m * ldin + n0 + threadIdx.x];
    }
    __syncthreads();
#pragma unroll
    for (int i = 0; i < 4; i++) {
        int n = n0 + threadIdx.y + i * 8;
        float v = tile[threadIdx.x][threadIdx.y + i * 8];
        long long o = (long long)b * sb_out + (long long)n * ldout + m0 + threadIdx.x;
        bf16 h = __float2bfloat16(v);
        d0[o] = h;
        d1[o] = __float2bfloat16(v - __bfloat162float(h));
    }
}

// combine 4 Bmat split-K partials -> split bf16 B0/B1
__global__ __launch_bounds__(256)
void combineB_kernel(const float* __restrict__ Bp,
                     bf16* __restrict__ B0, bf16* __restrict__ B1)
{
    int e = (blockIdx.x * 256 + threadIdx.x) * 4;   // over BATCH*NBDM
    int b = e / NBDM, j = e - b * NBDM;
    const float* base = Bp + (long long)b * 4 * NBDM + j;
    float4 v0 = *(const float4*)(base);
    float4 v1 = *(const float4*)(base + NBDM);
    float4 v2 = *(const float4*)(base + 2 * NBDM);
    float4 v3 = *(const float4*)(base + 3 * NBDM);
    float s0 = v0.x + v1.x + v2.x + v3.x;
    float s1 = v0.y + v1.y + v2.y + v3.y;
    float s2 = v0.z + v1.z + v2.z + v3.z;
    float s3 = v0.w + v1.w + v2.w + v3.w;
    long long o = (long long)b * NBDM + j;
    bf16 h0 = __float2bfloat16(s0), h1 = __float2bfloat16(s1);
    bf16 h2 = __float2bfloat16(s2), h3 = __float2bfloat16(s3);
    *(__nv_bfloat162*)(B0 + o)     = __nv_bfloat162(h0, h1);
    *(__nv_bfloat162*)(B0 + o + 2) = __nv_bfloat162(h2, h3);
    *(__nv_bfloat162*)(B1 + o) = __nv_bfloat162(
        __float2bfloat16(s0 - __bfloat162float(h0)),
        __float2bfloat16(s1 - __bfloat162float(h1)));
    *(__nv_bfloat162*)(B1 + o + 2) = __nv_bfloat162(
        __float2bfloat16(s2 - __bfloat162float(h2)),
        __float2bfloat16(s3 - __bfloat162float(h3)));
}

// combine 2 out split-K partials -> fp32 out
__global__ __launch_bounds__(256)
void combineO_kernel(const float* __restrict__ Op, float* __restrict__ out)
{
    int e = (blockIdx.x * 256 + threadIdx.x) * 4;   // over BATCH*LDM_C
    int b = e / LDM_C, j = e - b * LDM_C;
    const float* base = Op + (long long)b * 2 * LDM_C + j;
    float4 v0 = *(const float4*)(base);
    float4 v1 = *(const float4*)(base + LDM_C);
    float4 r = make_float4(v0.x + v1.x, v0.y + v1.y, v0.z + v1.z, v0.w + v1.w);
    *(float4*)(out + (long long)b * LDM_C + j) = r;
}

// V: sum 3 split-K partials + per-head transpose + split -> Vt[bh][d][n]
__global__ void vtrans_kernel(const float* __restrict__ Vp,
                              bf16* __restrict__ Vt0, bf16* __restrict__ Vt1)
{
    __shared__ float tile[32][33];
    int bh = blockIdx.z;
    int b = bh / NH, h = bh - b * NH;
    int n0 = blockIdx.x * 32, d0 = blockIdx.y * 32;
    const float* src = Vp + (long long)b * 3 * NBDM + h * DH;
#pragma unroll
    for (int i = 0; i < 4; i++) {
        int n = n0 + threadIdx.y + i * 8;
        long long o = (long long)n * DM + d0 + threadIdx.x;
        tile[threadIdx.y + i * 8][threadIdx.x] =
            src[o] + src[o + NBDM] + src[o + 2 * NBDM];
    }
    __syncthreads();
#pragma unroll
    for (int i = 0; i < 4; i++) {
        int d = d0 + threadIdx.y + i * 8;
        float v = tile[threadIdx.x][threadIdx.y + i * 8];
        long long o = ((long long)bh * DH + d) * NB + n0 + threadIdx.x;
        bf16 hh = __float2bfloat16(v);
        Vt0[o] = hh;
        Vt1[o] = __float2bfloat16(v - __bfloat162float(hh));
    }
}

// ---------------- split-bf16 tensor-core GEMM (K32, 80KB, 2 CTA/SM) ----
// blockIdx.z = z1*nz2 + z2: z1 = batch, z2 = split-K chunk (or secondary batch).
#define LDS_ROW 40
#define TSZ     (128 * LDS_ROW)
#define STAGE_H (4 * TSZ)
#define GSMEM_BYTES (2 * STAGE_H * 2)

__global__ __launch_bounds__(256)
void mma_gemm(int K,
              const bf16* __restrict__ A0, const bf16* __restrict__ A1,
              long long lda, long long sAb1, long long sAb2,
              const bf16* __restrict__ B0, const bf16* __restrict__ B1,
              long long ldb, long long sBb1, long long sBb2,
              float* __restrict__ C, bf16* __restrict__ C0, bf16* __restrict__ C1,
              long long ldc, long long sCb1, long long sCb2,
              int nz2, float alpha, int mode)
{
    extern __shared__ bf16 sm[];

    int z = blockIdx.z, z1 = z / nz2, z2 = z - z1 * nz2;
    A0 += z1 * sAb1 + z2 * sAb2;  A1 += z1 * sAb1 + z2 * sAb2;
    B0 += z1 * sBb1 + z2 * sBb2;  B1 += z1 * sBb1 + z2 * sBb2;
    const long long coff = z1 * sCb1 + z2 * sCb2;

    const int m0 = blockIdx.y * 128, n0 = blockIdx.x * 128;
    const int tid = threadIdx.x, lane = tid & 31, wid = tid >> 5;
    const int wm = (wid >> 2) * 64, wn = (wid & 3) * 32;

    float acc[4][4][4];
#pragma unroll
    for (int mt = 0; mt < 4; mt++)
#pragma unroll
        for (int nt = 0; nt < 4; nt++)
#pragma unroll
            for (int i = 0; i < 4; i++) acc[mt][nt][i] = 0.f;

    const int nstages = K >> 5;

    const int lrow = tid >> 2, lseg = tid & 3;
    auto load_stage = [&](int st, int k0) {
        bf16* base = sm + st * STAGE_H;
#pragma unroll
        for (int it = 0; it < 2; it++) {
            int row = lrow + it * 64;
            int so = row * LDS_ROW + lseg * 8;
            long long goA = (long long)(m0 + row) * lda + k0 + lseg * 8;
            long long goB = (long long)(n0 + row) * ldb + k0 + lseg * 8;
            cpa16(base + so,           A0 + goA);
            cpa16(base + TSZ + so,     A1 + goA);
            cpa16(base + 2 * TSZ + so, B0 + goB);
            cpa16(base + 3 * TSZ + so, B1 + goB);
        }
        asm volatile("cp.async.commit_group;");
    };

    load_stage(0, 0);

    const int arow = lane & 15, acol8 = (lane >> 4) * 8;
    const int brow = ((lane >> 4) << 3) + (lane & 7), bcol8 = ((lane >> 3) & 1) * 8;

    for (int s = 0; s < nstages; s++) {
        if (s + 1 < nstages) {
            load_stage((s + 1) & 1, (s + 1) << 5);
            asm volatile("cp.async.wait_group 1;");
        } else {
            asm volatile("cp.async.wait_group 0;");
        }
        __syncthreads();

        const bf16* As0 = sm + (s & 1) * STAGE_H;
        const bf16* As1 = As0 + TSZ;
        const bf16* Bs0 = As0 + 2 * TSZ;
        const bf16* Bs1 = As0 + 3 * TSZ;

#pragma unroll
        for (int kk = 0; kk < 2; kk++) {
            const int ac = kk * 16 + acol8;
            const int bc = kk * 16 + bcol8;
            uint32_t af[4][4], bf0[4][2], bf1[4][2];
#pragma unroll
            for (int mt = 0; mt < 4; mt++)
                ldsm4(af[mt], As0 + (wm + mt * 16 + arow) * LDS_ROW + ac);
#pragma unroll
            for (int np = 0; np < 2; np++) {
                uint32_t r[4];
                ldsm4(r, Bs0 + (wn + np * 16 + brow) * LDS_ROW + bc);
                bf0[np * 2][0] = r[0]; bf0[np * 2][1] = r[1];
                bf0[np * 2 + 1][0] = r[2]; bf0[np * 2 + 1][1] = r[3];
                ldsm4(r, Bs1 + (wn + np * 16 + brow) * LDS_ROW + bc);
                bf1[np * 2][0] = r[0]; bf1[np * 2][1] = r[1];
                bf1[np * 2 + 1][0] = r[2]; bf1[np * 2 + 1][1] = r[3];
            }
#pragma unroll
            for (int mt = 0; mt < 4; mt++)
#pragma unroll
                for (int nt = 0; nt < 4; nt++) mma16816(acc[mt][nt], af[mt], bf0[nt]);
#pragma unroll
            for (int mt = 0; mt < 4; mt++)
#pragma unroll
                for (int nt = 0; nt < 4; nt++) mma16816(acc[mt][nt], af[mt], bf1[nt]);
#pragma unroll
            for (int mt = 0; mt < 4; mt++)
                ldsm4(af[mt], As1 + (wm + mt * 16 + arow) * LDS_ROW + ac);
#pragma unroll
            for (int mt = 0; mt < 4; mt++)
#pragma unroll
                for (int nt = 0; nt < 4; nt++) mma16816(acc[mt][nt], af[mt], bf0[nt]);
        }
        __syncthreads();
    }

    const int g = lane >> 2, c2 = (lane & 3) * 2;
#pragma unroll
    for (int mt = 0; mt < 4; mt++) {
#pragma unroll
        for (int nt = 0; nt < 4; nt++) {
            int row = m0 + wm + mt * 16 + g;
            int col = n0 + wn + nt * 8 + c2;
            float v0 = alpha * acc[mt][nt][0], v1 = alpha * acc[mt][nt][1];
            float v2 = alpha * acc[mt][nt][2], v3 = alpha * acc[mt][nt][3];
            long long o0 = coff + (long long)row * ldc + col;
            long long o1 = coff + (long long)(row + 8) * ldc + col;
            if (mode != 1) {
                *(float2*)&C[o0] = make_float2(v0, v1);
                *(float2*)&C[o1] = make_float2(v2, v3);
            }
            if (mode != 0) {
                bf16 h0 = __float2bfloat16(v0), h1 = __float2bfloat16(v1);
                bf16 h2 = __float2bfloat16(v2), h3 = __float2bfloat16(v3);
                bf16 l0 = __float2bfloat16(v0 - __bfloat162float(h0));
                bf16 l1 = __float2bfloat16(v1 - __bfloat162float(h1));
                bf16 l2 = __float2bfloat16(v2 - __bfloat162float(h2));
                bf16 l3 = __float2bfloat16(v3 - __bfloat162float(h3));
                *(__nv_bfloat162*)(C0 + o0) = __nv_bfloat162(h0, h1);
                *(__nv_bfloat162*)(C0 + o1) = __nv_bfloat162(h2, h3);
                *(__nv_bfloat162*)(C1 + o0) = __nv_bfloat162(l0, l1);
                *(__nv_bfloat162*)(C1 + o1) = __nv_bfloat162(l2, l3);
            }
        }
    }
}

// ---------------- A: c[b][s][j] = sum_n (B0+B1)[b][n][j] * w_s[n] ------------
__global__ __launch_bounds__(256)
void cvec_kernel(const bf16* __restrict__ B0, const bf16* __restrict__ B1,
                 const float* __restrict__ w_mu,
                 const float* __restrict__ w_sigma,
                 float* __restrict__ C)
{
    __shared__ float wm[NB], ws[NB];
    __shared__ float red[2][256];
    int tid = threadIdx.x;
    int b = blockIdx.y;
    int j = blockIdx.x * 128 + (tid & 127);
    int g = tid >> 7;
    if (tid < NB) { wm[tid] = w_mu[tid]; ws[tid] = w_sigma[tid]; }
    __syncthreads();

    const bf16* p0 = B0 + (long long)b * NBDM + j;
    const bf16* p1 = B1 + (long long)b * NBDM + j;
    float am = 0.f, as = 0.f;
    for (int n = g; n < NB; n += 2) {
        float xv = __bfloat162float(p0[(long long)n * DM]) +
                   __bfloat162float(p1[(long long)n * DM]);
        am += xv * wm[n];
        as += xv * ws[n];
    }
    red[0][tid] = am; red[1][tid] = as;
    __syncthreads();
    if (tid < 128) {
        C[(long long)b * 2 * DM + j]      = red[0][tid] + red[0][tid + 128];
        C[(long long)b * 2 * DM + DM + j] = red[1][tid] + red[1][tid + 128];
    }
}

// ---------------- B: kw[bs][i] = sum_j Wk[i][j] * c[bs][j] ----------------
__global__ __launch_bounds__(256)
void kw_kernel(const float* __restrict__ Wk, const float* __restrict__ C,
               float* __restrict__ KW)
{
    __shared__ float wt[64][65];
    __shared__ float cs[16][64];
    int tid = threadIdx.x;
    int i0 = blockIdx.x * 64;
    int i = tid & 63, qg = tid >> 6;
    float acc[4] = {0.f, 0.f, 0.f, 0.f};

    for (int jc = 0; jc < DM; jc += 64) {
#pragma unroll
        for (int t = 0; t < 16; t++) {
            int idx = tid + t * 256;
            wt[idx >> 6][idx & 63] = Wk[(long long)(i0 + (idx >> 6)) * DM + jc + (idx & 63)];
        }
#pragma unroll
        for (int t = 0; t < 4; t++) {
            int idx = tid + t * 256;
            cs[idx >> 6][idx & 63] = C[(long long)(idx >> 6) * DM + jc + (idx & 63)];
        }
        __syncthreads();
#pragma unroll
        for (int jj = 0; jj < 64; jj++) {
            float w = wt[i][jj];
            acc[0] += w * cs[qg][jj];
            acc[1] += w * cs[qg + 4][jj];
            acc[2] += w * cs[qg + 8][jj];
            acc[3] += w * cs[qg + 12][jj];
        }
        __syncthreads();
    }
#pragma unroll
    for (int t = 0; t < 4; t++)
        KW[(long long)(qg + t * 4) * DM + i0 + i] = acc[t];
}

// ---------------- C: T[b][h*2+s][j] = sum_i Wq[h*64+i][j] * kw[b][s][h*64+i] ----
__global__ __launch_bounds__(128)
void tvec_kernel(const float* __restrict__ Wq, const float* __restrict__ KW,
                 float* __restrict__ T)
{
    __shared__ float kws[16][64];
    int tid = threadIdx.x;
    int h = blockIdx.y;
    int j = blockIdx.x * 128 + tid;
#pragma unroll
    for (int t = 0; t < 8; t++) {
        int idx = tid + t * 128;
        kws[idx >> 6][idx & 63] = KW[(long long)(idx >> 6) * DM + h * 64 + (idx & 63)];
    }
    __syncthreads();
    float acc[16];
#pragma unroll
    for (int v = 0; v < 16; v++) acc[v] = 0.f;
    for (int ii = 0; ii < 64; ii++) {
        float w = Wq[(long long)(h * 64 + ii) * DM + j];
#pragma unroll
        for (int v = 0; v < 16; v++) acc[v] += w * kws[v][ii];
    }
#pragma unroll
    for (int v = 0; v < 16; v++) {
        int b = v >> 1, s = v & 1;
        T[((long long)b * 24 + h * 2 + s) * DM + j] = acc[v];
    }
}

// ---------------- D: mu/ss ----------------
__global__ __launch_bounds__(256)
void musig_kernel(const float* __restrict__ qin, const float* __restrict__ T,
                  float* __restrict__ mu_out, float* __restrict__ ss_out)
{
    __shared__ float Tc[24][132];
    int tid = threadIdx.x, lane = tid & 31, warp = tid >> 5;
    int rb = blockIdx.x * 8 + warp;
    int b = rb >> 10, qrow = rb & 1023;
    const float* qr = qin + (long long)qrow * (BATCH * DM) + (long long)b * DM;
    const float* Tb = T + (long long)b * 24 * DM;

    float acc[24];
#pragma unroll
    for (int v = 0; v < 24; v++) acc[v] = 0.f;

    for (int kc = 0; kc < 6; kc++) {
        __syncthreads();
#pragma unroll
        for (int t = 0; t < 12; t++) {
            int idx = tid + t * 256;
            Tc[idx >> 7][idx & 127] = Tb[(long long)(idx >> 7) * DM + kc * 128 + (idx & 127)];
        }
        __syncthreads();
        float4 qv = *(const float4*)(qr + kc * 128 + lane * 4);
#pragma unroll
        for (int v = 0; v < 24; v++) {
            float4 tv = *(const float4*)&Tc[v][lane * 4];
            acc[v] += qv.x * tv.x + qv.y * tv.y + qv.z * tv.z + qv.w * tv.w;
        }
    }
#pragma unroll
    for (int v = 0; v < 24; v++)
#pragma unroll
        for (int o = 16; o; o >>= 1)
            acc[v] += __shfl_xor_sync(0xffffffffu, acc[v], o);

    if (lane == 0) {
#pragma unroll
        for (int v = 0; v < 24; v++) {
            int h = v >> 1;
            float d = acc[v] * 0.125f;
            long long o = ((long long)b * NH + h) * LEN + qrow;
            if ((v & 1) == 0) mu_out[o] = 1.f / (1.f + __expf(-d));
            else              ss_out[o] = (d > 20.f) ? d : log1pf(__expf(d));
        }
    }
}

// ---------------- fused r + ctx = r@V : per-chunk-reseeded recurrence + mma --
__global__ __launch_bounds__(256)
void rv_mma_kernel(const float* __restrict__ mu,
                   const float* __restrict__ ss,
                   const float* __restrict__ mu_b,
                   const float* __restrict__ sigma_b,
                   const bf16* __restrict__ Vt0, const bf16* __restrict__ Vt1,
                   bf16* __restrict__ ctx0, bf16* __restrict__ ctx1)
{
    __shared__ __align__(16) bf16 rs0[128 * LDS_ROW];
    __shared__ __align__(16) bf16 rs1[128 * LDS_ROW];
    __shared__ __align__(16) bf16 vs0[64 * LDS_ROW];
    __shared__ __align__(16) bf16 vs1[64 * LDS_ROW];
    __shared__ float invs[128][2];
    __shared__ float mus[128];

    const int tid = threadIdx.x, lane = tid & 31, wid = tid >> 5;
    const int bh = blockIdx.y;
    const int b = bh / NH, h = bh - b * NH;
    const int m0 = blockIdx.x * 128;
    const int rowbase = bh * LEN + m0;

    if (tid < 128) mus[tid] = mu[rowbase + tid];
    {
        int row = tid >> 1, p = tid & 1;
        float sb = sigma_b[p];
        invs[row][p] = rsqrtf(sb * sb + ss[rowbase + row]);
    }
    __syncthreads();

    const float DELTA = 1.0f / 127.0f;
    const float C_PHI = 0.3989422804014327f;
    const int rm = tid >> 1, rp = tid & 1;
    const float r_mu = mus[rm];
    const float r_iv = invs[rm][rp];
    const float rscale = C_PHI * r_iv;
    const float ivd = r_iv * r_iv * DELTA;
    const float Wr = __expf(-ivd * DELTA);

    const int wm = (wid >> 1) * 32, wn = (wid & 1) * 32;
    float acc[2][4][4];
#pragma unroll
    for (int mt = 0; mt < 2; mt++)
#pragma unroll
        for (int nt = 0; nt < 4; nt++)
#pragma unroll
            for (int i = 0; i < 4; i++) acc[mt][nt][i] = 0.f;

    const bf16* vt0 = Vt0 + (long long)bh * DH * NB;
    const bf16* vt1 = Vt1 + (long long)bh * DH * NB;

    const int vrow = tid >> 2, vseg = tid & 3;

    const int brow = ((lane >> 4) << 3) + (lane & 7), bcol8 = ((lane >> 3) & 1) * 8;
    const int arow = lane & 15, acol8 = (lane >> 4) * 8;

    for (int nc = 0; nc < 8; nc++) {
        cpa16(vs0 + vrow * LDS_ROW + vseg * 8, vt0 + (long long)vrow * NB + nc * 32 + vseg * 8);
        cpa16(vs1 + vrow * LDS_ROW + vseg * 8, vt1 + (long long)vrow * NB + nc * 32 + vseg * 8);
        asm volatile("cp.async.commit_group;");

        float dmu = r_mu - (float)(nc * 16) * DELTA;
        float t0 = dmu * r_iv;
        float rv = rscale * __expf(-0.5f * t0 * t0);
        float rR = __expf(ivd * (dmu - 0.5f * DELTA));
        bf16* q0 = rs0 + rm * LDS_ROW + rp;
        bf16* q1 = rs1 + rm * LDS_ROW + rp;
#pragma unroll
        for (int jj = 0; jj < 16; jj++) {
            bf16 hh = __float2bfloat16(rv);
            q0[2 * jj] = hh;
            q1[2 * jj] = __float2bfloat16(rv - __bfloat162float(hh));
            rv *= rR;
            rR *= Wr;
        }
        asm volatile("cp.async.wait_group 0;");
        __syncthreads();

#pragma unroll
        for (int kk = 0; kk < 2; kk++) {
            const int ac = kk * 16 + acol8;
            const int bc = kk * 16 + bcol8;
            uint32_t a0[2][4], a1[2][4], b0[4][2], b1[4][2];
#pragma unroll
            for (int mt = 0; mt < 2; mt++) {
                ldsm4(a0[mt], rs0 + (wm + mt * 16 + arow) * LDS_ROW + ac);
                ldsm4(a1[mt], rs1 + (wm + mt * 16 + arow) * LDS_ROW + ac);
            }
#pragma unroll
            for (int np = 0; np < 2; np++) {
                uint32_t r[4];
                ldsm4(r, vs0 + (wn + np * 16 + brow) * LDS_ROW + bc);
                b0[np * 2][0] = r[0]; b0[np * 2][1] = r[1];
                b0[np * 2 + 1][0] = r[2]; b0[np * 2 + 1][1] = r[3];
                ldsm4(r, vs1 + (wn + np * 16 + brow) * LDS_ROW + bc);
                b1[np * 2][0] = r[0]; b1[np * 2][1] = r[1];
                b1[np * 2 + 1][0] = r[2]; b1[np * 2 + 1][1] = r[3];
            }
#pragma unroll
            for (int mt = 0; mt < 2; mt++)
#pragma unroll
                for (int nt = 0; nt < 4; nt++) {
                    mma16816(acc[mt][nt], a0[mt], b0[nt]);
                    mma16816(acc[mt][nt], a0[mt], b1[nt]);
                    mma16816(acc[mt][nt], a1[mt], b0[nt]);
                }
        }
        __syncthreads();
    }

    const int g = lane >> 2, c2 = (lane & 3) * 2;
#pragma unroll
    for (int mt = 0; mt < 2; mt++) {
#pragma unroll
        for (int nt = 0; nt < 4; nt++) {
            int row = m0 + wm + mt * 16 + g;
            int col = h * DH + wn + nt * 8 + c2;
            float v0 = acc[mt][nt][0], v1 = acc[mt][nt][1];
            float v2 = acc[mt][nt][2], v3 = acc[mt][nt][3];
            long long o0 = (long long)b * LDM_C + (long long)row * DM + col;
            long long o1 = o0 + 8LL * DM;
            bf16 h0 = __float2bfloat16(v0), h1 = __float2bfloat16(v1);
            bf16 h2 = __float2bfloat16(v2), h3 = __float2bfloat16(v3);
            bf16 l0 = __float2bfloat16(v0 - __bfloat162float(h0));
            bf16 l1 = __float2bfloat16(v1 - __bfloat162float(h1));
            bf16 l2 = __float2bfloat16(v2 - __bfloat162float(h2));
            bf16 l3 = __float2bfloat16(v3 - __bfloat162float(h3));
            *(__nv_bfloat162*)(ctx0 + o0) = __nv_bfloat162(h0, h1);
            *(__nv_bfloat162*)(ctx0 + o1) = __nv_bfloat162(h2, h3);
            *(__nv_bfloat162*)(ctx1 + o0) = __nv_bfloat162(l0, l1);
            *(__nv_bfloat162*)(ctx1 + o1) = __nv_bfloat162(l2, l3);
        }
    }
}

// ---------------- launch ----------------
extern "C" void kernel_launch(void* const* d_in, const int* in_sizes, int n_in,
                              void* d_out, int out_size)
{
    const float* x       = (const float*)d_in[0];
    const float* q       = (const float*)d_in[1];
    const float* Wq      = (const float*)d_in[2];
    const float* Wk      = (const float*)d_in[3];
    const float* Wv      = (const float*)d_in[4];
    const float* Wo      = (const float*)d_in[5];
    const float* w_mu    = (const float*)d_in[6];
    const float* w_sigma = (const float*)d_in[7];
    const float* mu_b    = (const float*)d_in[8];
    const float* sigma_b = (const float*)d_in[9];
    const float* G       = (const float*)d_in[10];
    float* out = (float*)d_out;

    cudaFuncSetAttribute(mma_gemm, cudaFuncAttributeMaxDynamicSharedMemorySize, GSMEM_BYTES);

    void *pxt0, *pxt1, *pGt0, *pGt1, *pWv0, *pWv1, *pWo0, *pWo1;
    void *pB0, *pB1, *pBp, *pVp, *pOp, *pVt0, *pVt1;
    void *pC, *pKW, *pT, *pMu, *pSs, *pC0, *pC1;
    cudaGetSymbolAddress(&pxt0, g_xt0); cudaGetSymbolAddress(&pxt1, g_xt1);
    cudaGetSymbolAddress(&pGt0, g_Gt0); cudaGetSymbolAddress(&pGt1, g_Gt1);
    cudaGetSymbolAddress(&pWv0, g_Wv0); cudaGetSymbolAddress(&pWv1, g_Wv1);
    cudaGetSymbolAddress(&pWo0, g_Wo0); cudaGetSymbolAddress(&pWo1, g_Wo1);
    cudaGetSymbolAddress(&pB0, g_B0);   cudaGetSymbolAddress(&pB1, g_B1);
    cudaGetSymbolAddress(&pBp, g_Bp);   cudaGetSymbolAddress(&pVp, g_Vp);
    cudaGetSymbolAddress(&pOp, g_Op);
    cudaGetSymbolAddress(&pVt0, g_Vt0); cudaGetSymbolAddress(&pVt1, g_Vt1);
    cudaGetSymbolAddress(&pC, g_C);     cudaGetSymbolAddress(&pKW, g_KW);
    cudaGetSymbolAddress(&pT, g_T);
    cudaGetSymbolAddress(&pMu, g_mu);   cudaGetSymbolAddress(&pSs, g_ss);
    cudaGetSymbolAddress(&pC0, g_ctx0); cudaGetSymbolAddress(&pC1, g_ctx1);

    const long long DMLN = (long long)DM * LEN;
    dim3 blk(256);

    // ---- input conversions ----
    int nW = DM * DM;
    split_kernel<<<nW / 1024, blk>>>(Wv, (bf16*)pWv0, (bf16*)pWv1, nW);
    split_kernel<<<nW / 1024, blk>>>(Wo, (bf16*)pWo0, (bf16*)pWo1, nW);
    tsplit_kernel<<<dim3(DM / 32, LEN / 32, BATCH), dim3(32, 8)>>>(
        x, DM, BATCH * DM, (bf16*)pxt0, (bf16*)pxt1, DMLN, LEN);
    tsplit_kernel<<<dim3(NB / 32, LEN / 32, 1), dim3(32, 8)>>>(
        G, 0, NB, (bf16*)pGt0, (bf16*)pGt1, 0, LEN);

    // ---- 1. Bmat split-K=4 (fp32 partials), grid 384 CTAs ----
    mma_gemm<<<dim3(DM / 128, NB / 128, BATCH * 4), blk, GSMEM_BYTES>>>(
        256,
        (bf16*)pGt0, (bf16*)pGt1, LEN, 0, 256,
        (bf16*)pxt0, (bf16*)pxt1, LEN, DMLN, 256,
        (float*)pBp, nullptr, nullptr, DM, 4LL * NBDM, NBDM,
        4, 1.0f, 0);
    combineB_kernel<<<(BATCH * NBDM) / 1024, blk>>>(
        (const float*)pBp, (bf16*)pB0, (bf16*)pB1);

    // ---- 2. V split-K=3 (fp32 partials), grid 288 CTAs ----
    mma_gemm<<<dim3(DM / 128, NB / 128, BATCH * 3), blk, GSMEM_BYTES>>>(
        256,
        (bf16*)pB0, (bf16*)pB1, DM, NBDM, 256,
        (bf16*)pWv0, (bf16*)pWv1, DM, 0, 256,
        (float*)pVp, nullptr, nullptr, DM, 3LL * NBDM, NBDM,
        3, 1.0f, 0);

    // ---- 2b. V combine + transpose + split ----
    vtrans_kernel<<<dim3(NB / 32, DH / 32, BATCH * NH), dim3(32, 8)>>>(
        (const float*)pVp, (bf16*)pVt0, (bf16*)pVt1);

    // ---- 3. tiny fp32 chain ----
    cvec_kernel<<<dim3(DM / 128, BATCH), blk>>>(
        (const bf16*)pB0, (const bf16*)pB1, w_mu, w_sigma, (float*)pC);
    kw_kernel<<<DM / 64, blk>>>(Wk, (const float*)pC, (float*)pKW);
    tvec_kernel<<<dim3(DM / 128, NH), dim3(128)>>>(Wq, (const float*)pKW, (float*)pT);
    musig_kernel<<<(BATCH * LEN) / 8, blk>>>(q, (const float*)pT,
                                             (float*)pMu, (float*)pSs);

    // ---- 4. fused r + ctx = r @ V ----
    rv_mma_kernel<<<dim3(LEN / 128, BATCH * NH), blk>>>(
        (const float*)pMu, (const float*)pSs, mu_b, sigma_b,
        (const bf16*)pVt0, (const bf16*)pVt1, (bf16*)pC0, (bf16*)pC1);

    // ---- 5. out split-K=2 (fp32 partials), grid 768 CTAs ----
    mma_gemm<<<dim3(DM / 128, LEN / 128, BATCH * 2), blk, GSMEM_BYTES>>>(
        384,
        (bf16*)pC0, (bf16*)pC1, DM, (long long)LDM_C, 384,
        (bf16*)pWo0, (bf16*)pWo1, DM, 0, 384,
        (float*)pOp, nullptr, nullptr, DM, 2LL * LDM_C, LDM_C,
        2, 1.0f, 0);
    combineO_kernel<<<(BATCH * LDM_C) / 1024, blk>>>((const float*)pOp, out);
}

// round 10
// speedup vs baseline: 1.0208x; 1.0208x over previous
#include <cuda_runtime.h>
#include <cuda_bf16.h>
#include <math.h>
#include <stdint.h>

#define NH     12
#define DH     64
#define DM     768
#define NB     256
#define LEN    1024
#define BATCH  8

typedef __nv_bfloat16 bf16;

#define NBDM   (NB * DM)        // 196608
#define LDM_C  (LEN * DM)       // 786432

// ---------------- device scratch (static; no allocations) ----------------
__device__ __align__(16) bf16 g_xt0[BATCH * DM * LEN];
__device__ __align__(16) bf16 g_xt1[BATCH * DM * LEN];
__device__ __align__(16) bf16 g_Gt0[NB * LEN];
__device__ __align__(16) bf16 g_Gt1[NB * LEN];
__device__ __align__(16) bf16 g_Wv0[DM * DM]; __device__ __align__(16) bf16 g_Wv1[DM * DM];
__device__ __align__(16) bf16 g_Wo0[DM * DM]; __device__ __align__(16) bf16 g_Wo1[DM * DM];
__device__ __align__(16) bf16 g_B0 [BATCH * NBDM];
__device__ __align__(16) bf16 g_B1 [BATCH * NBDM];
__device__ __align__(16) bf16 g_Vt0[BATCH * NH * DH * NB];
__device__ __align__(16) bf16 g_Vt1[BATCH * NH * DH * NB];
__device__ float g_C [BATCH * 2 * DM];
__device__ float g_KW[BATCH * 2 * DM];
__device__ float g_T [BATCH * 24 * DM];
__device__ float g_mu[BATCH * NH * LEN];
__device__ float g_ss[BATCH * NH * LEN];
__device__ __align__(16) bf16 g_ctx0[BATCH * LDM_C];
__device__ __align__(16) bf16 g_ctx1[BATCH * LDM_C];

// ---------------- helpers ----------------
__device__ __forceinline__ uint32_t smem_u32(const void* p)
{
    uint32_t a;
    asm("{ .reg .u64 t; cvta.to.shared.u64 t, %1; cvt.u32.u64 %0, t; }"
        : "=r"(a) : "l"(p));
    return a;
}
__device__ __forceinline__ void mma16816(float* c, const uint32_t* a, const uint32_t* b)
{
    asm volatile("mma.sync.aligned.m16n8k16.row.col.f32.bf16.bf16.f32 "
                 "{%0,%1,%2,%3}, {%4,%5,%6,%7}, {%8,%9}, {%0,%1,%2,%3};"
                 : "+f"(c[0]), "+f"(c[1]), "+f"(c[2]), "+f"(c[3])
                 : "r"(a[0]), "r"(a[1]), "r"(a[2]), "r"(a[3]), "r"(b[0]), "r"(b[1]));
}
__device__ __forceinline__ void ldsm4(uint32_t* r, const bf16* p)
{
    uint32_t a = smem_u32(p);
    asm volatile("ldmatrix.sync.aligned.m8n8.x4.shared.b16 {%0,%1,%2,%3}, [%4];"
                 : "=r"(r[0]), "=r"(r[1]), "=r"(r[2]), "=r"(r[3]) : "r"(a));
}
__device__ __forceinline__ void cpa16(bf16* s, const bf16* g)
{
    uint32_t sa = smem_u32(s);
    asm volatile("cp.async.cg.shared.global [%0], [%1], 16;" :: "r"(sa), "l"(g));
}

// ---------------- conversions ----------------
// merged Wv/Wo split: blockIdx.y selects which matrix
__global__ __launch_bounds__(256)
void splitWW_kernel(const float* __restrict__ Wv, const float* __restrict__ Wo,
                    bf16* __restrict__ v0, bf16* __restrict__ v1,
                    bf16* __restrict__ o0, bf16* __restrict__ o1)
{
    const float* src = blockIdx.y ? Wo : Wv;
    bf16* d0 = blockIdx.y ? o0 : v0;
    bf16* d1 = blockIdx.y ? o1 : v1;
    int i = (blockIdx.x * 256 + threadIdx.x) * 4;
    float4 v = *(const float4*)(src + i);
    bf16 h0 = __float2bfloat16(v.x), h1 = __float2bfloat16(v.y);
    bf16 h2 = __float2bfloat16(v.z), h3 = __float2bfloat16(v.w);
    *(__nv_bfloat162*)(d0 + i)     = __nv_bfloat162(h0, h1);
    *(__nv_bfloat162*)(d0 + i + 2) = __nv_bfloat162(h2, h3);
    *(__nv_bfloat162*)(d1 + i) = __nv_bfloat162(
        __float2bfloat16(v.x - __bfloat162float(h0)),
        __float2bfloat16(v.y - __bfloat162float(h1)));
    *(__nv_bfloat162*)(d1 + i + 2) = __nv_bfloat162(
        __float2bfloat16(v.z - __bfloat162float(h2)),
        __float2bfloat16(v.w - __bfloat162float(h3)));
}

__global__ __launch_bounds__(256)
void tsplit_kernel(const float* __restrict__ src, long long sb_in, int ldin,
                   bf16* __restrict__ d0, bf16* __restrict__ d1,
                   long long sb_out, int ldout)
{
    __shared__ float tile[32][33];
    int b = blockIdx.z;
    const float* s = src + (long long)b * sb_in;
    int m0 = blockIdx.y * 32, n0 = blockIdx.x * 32;
#pragma unroll
    for (int i = 0; i < 4; i++) {
        int m = m0 + threadIdx.y + i * 8;
        tile[threadIdx.y + i * 8][threadIdx.x] = s[(long long)m * ldin + n0 + threadIdx.x];
    }
    __syncthreads();
#pragma unroll
    for (int i = 0; i < 4; i++) {
        int n = n0 + threadIdx.y + i * 8;
        float v = tile[threadIdx.x][threadIdx.y + i * 8];
        long long o = (long long)b * sb_out + (long long)n * ldout + m0 + threadIdx.x;
        bf16 h = __float2bfloat16(v);
        d0[o] = h;
        d1[o] = __float2bfloat16(v - __bfloat162float(h));
    }
}

// ---------------- split-bf16 tensor-core GEMM (K32, 80KB, 2 CTA/SM) ----
// mode 0: fp32 C; mode 1: split bf16 C0/C1; mode 3: V transpose-split epilogue
//         (row = basis n, col = model dim; writes Vt[b*NH + col/64][col%64][row]).
#define LDS_ROW 40
#define TSZ     (128 * LDS_ROW)
#define STAGE_H (4 * TSZ)
#define GSMEM_BYTES (2 * STAGE_H * 2)

__global__ __launch_bounds__(256)
void mma_gemm(int K,
              const bf16* __restrict__ A0, const bf16* __restrict__ A1,
              long long lda, long long sAb1, long long sAb2,
              const bf16* __restrict__ B0, const bf16* __restrict__ B1,
              long long ldb, long long sBb1, long long sBb2,
              float* __restrict__ C, bf16* __restrict__ C0, bf16* __restrict__ C1,
              long long ldc, long long sCb1, long long sCb2,
              int nz2, float alpha, int mode)
{
    extern __shared__ bf16 sm[];

    int z = blockIdx.z, z1 = z / nz2, z2 = z - z1 * nz2;
    A0 += z1 * sAb1 + z2 * sAb2;  A1 += z1 * sAb1 + z2 * sAb2;
    B0 += z1 * sBb1 + z2 * sBb2;  B1 += z1 * sBb1 + z2 * sBb2;
    const long long coff = z1 * sCb1 + z2 * sCb2;

    const int m0 = blockIdx.y * 128, n0 = blockIdx.x * 128;
    const int tid = threadIdx.x, lane = tid & 31, wid = tid >> 5;
    const int wm = (wid >> 2) * 64, wn = (wid & 3) * 32;

    float acc[4][4][4];
#pragma unroll
    for (int mt = 0; mt < 4; mt++)
#pragma unroll
        for (int nt = 0; nt < 4; nt++)
#pragma unroll
            for (int i = 0; i < 4; i++) acc[mt][nt][i] = 0.f;

    const int nstages = K >> 5;

    const int lrow = tid >> 2, lseg = tid & 3;
    auto load_stage = [&](int st, int k0) {
        bf16* base = sm + st * STAGE_H;
#pragma unroll
        for (int it = 0; it < 2; it++) {
            int row = lrow + it * 64;
            int so = row * LDS_ROW + lseg * 8;
            long long goA = (long long)(m0 + row) * lda + k0 + lseg * 8;
            long long goB = (long long)(n0 + row) * ldb + k0 + lseg * 8;
            cpa16(base + so,           A0 + goA);
            cpa16(base + TSZ + so,     A1 + goA);
            cpa16(base + 2 * TSZ + so, B0 + goB);
            cpa16(base + 3 * TSZ + so, B1 + goB);
        }
        asm volatile("cp.async.commit_group;");
    };

    load_stage(0, 0);

    const int arow = lane & 15, acol8 = (lane >> 4) * 8;
    const int brow = ((lane >> 4) << 3) + (lane & 7), bcol8 = ((lane >> 3) & 1) * 8;

    for (int s = 0; s < nstages; s++) {
        if (s + 1 < nstages) {
            load_stage((s + 1) & 1, (s + 1) << 5);
            asm volatile("cp.async.wait_group 1;");
        } else {
            asm volatile("cp.async.wait_group 0;");
        }
        __syncthreads();

        const bf16* As0 = sm + (s & 1) * STAGE_H;
        const bf16* As1 = As0 + TSZ;
        const bf16* Bs0 = As0 + 2 * TSZ;
        const bf16* Bs1 = As0 + 3 * TSZ;

#pragma unroll
        for (int kk = 0; kk < 2; kk++) {
            const int ac = kk * 16 + acol8;
            const int bc = kk * 16 + bcol8;
            uint32_t af[4][4], bf0[4][2], bf1[4][2];
#pragma unroll
            for (int mt = 0; mt < 4; mt++)
                ldsm4(af[mt], As0 + (wm + mt * 16 + arow) * LDS_ROW + ac);
#pragma unroll
            for (int np = 0; np < 2; np++) {
                uint32_t r[4];
                ldsm4(r, Bs0 + (wn + np * 16 + brow) * LDS_ROW + bc);
                bf0[np * 2][0] = r[0]; bf0[np * 2][1] = r[1];
                bf0[np * 2 + 1][0] = r[2]; bf0[np * 2 + 1][1] = r[3];
                ldsm4(r, Bs1 + (wn + np * 16 + brow) * LDS_ROW + bc);
                bf1[np * 2][0] = r[0]; bf1[np * 2][1] = r[1];
                bf1[np * 2 + 1][0] = r[2]; bf1[np * 2 + 1][1] = r[3];
            }
#pragma unroll
            for (int mt = 0; mt < 4; mt++)
#pragma unroll
                for (int nt = 0; nt < 4; nt++) mma16816(acc[mt][nt], af[mt], bf0[nt]);
#pragma unroll
            for (int mt = 0; mt < 4; mt++)
#pragma unroll
                for (int nt = 0; nt < 4; nt++) mma16816(acc[mt][nt], af[mt], bf1[nt]);
#pragma unroll
            for (int mt = 0; mt < 4; mt++)
                ldsm4(af[mt], As1 + (wm + mt * 16 + arow) * LDS_ROW + ac);
#pragma unroll
            for (int mt = 0; mt < 4; mt++)
#pragma unroll
                for (int nt = 0; nt < 4; nt++) mma16816(acc[mt][nt], af[mt], bf0[nt]);
        }
        __syncthreads();
    }

    const int g = lane >> 2, c2 = (lane & 3) * 2;
    if (mode == 3) {
        // V epilogue: element (row=n, col=d) -> Vt[(z1*NH + col/64)][col%64][row]
#pragma unroll
        for (int mt = 0; mt < 4; mt++) {
#pragma unroll
            for (int nt = 0; nt < 4; nt++) {
#pragma unroll
                for (int e = 0; e < 4; e++) {
                    int row = m0 + wm + mt * 16 + g + (e >> 1) * 8;
                    int col = n0 + wn + nt * 8 + c2 + (e & 1);
                    float v = acc[mt][nt][e];
                    long long o = ((long long)(z1 * NH + (col >> 6)) * DH + (col & 63)) * NB + row;
                    bf16 hh = __float2bfloat16(v);
                    C0[o] = hh;
                    C1[o] = __float2bfloat16(v - __bfloat162float(hh));
                }
            }
        }
        return;
    }
#pragma unroll
    for (int mt = 0; mt < 4; mt++) {
#pragma unroll
        for (int nt = 0; nt < 4; nt++) {
            int row = m0 + wm + mt * 16 + g;
            int col = n0 + wn + nt * 8 + c2;
            float v0 = alpha * acc[mt][nt][0], v1 = alpha * acc[mt][nt][1];
            float v2 = alpha * acc[mt][nt][2], v3 = alpha * acc[mt][nt][3];
            long long o0 = coff + (long long)row * ldc + col;
            long long o1 = coff + (long long)(row + 8) * ldc + col;
            if (mode == 0) {
                *(float2*)&C[o0] = make_float2(v0, v1);
                *(float2*)&C[o1] = make_float2(v2, v3);
            } else {
                bf16 h0 = __float2bfloat16(v0), h1 = __float2bfloat16(v1);
                bf16 h2 = __float2bfloat16(v2), h3 = __float2bfloat16(v3);
                bf16 l0 = __float2bfloat16(v0 - __bfloat162float(h0));
                bf16 l1 = __float2bfloat16(v1 - __bfloat162float(h1));
                bf16 l2 = __float2bfloat16(v2 - __bfloat162float(h2));
                bf16 l3 = __float2bfloat16(v3 - __bfloat162float(h3));
                *(__nv_bfloat162*)(C0 + o0) = __nv_bfloat162(h0, h1);
                *(__nv_bfloat162*)(C0 + o1) = __nv_bfloat162(h2, h3);
                *(__nv_bfloat162*)(C1 + o0) = __nv_bfloat162(l0, l1);
                *(__nv_bfloat162*)(C1 + o1) = __nv_bfloat162(l2, l3);
            }
        }
    }
}

// ---------------- A: c[b][s][j] = sum_n (B0+B1)[b][n][j] * w_s[n] ------------
__global__ __launch_bounds__(256)
void cvec_kernel(const bf16* __restrict__ B0, const bf16* __restrict__ B1,
                 const float* __restrict__ w_mu,
                 const float* __restrict__ w_sigma,
                 float* __restrict__ C)
{
    __shared__ float wm[NB], ws[NB];
    __shared__ float red[2][256];
    int tid = threadIdx.x;
    int b = blockIdx.y;
    int j = blockIdx.x * 128 + (tid & 127);
    int g = tid >> 7;
    if (tid < NB) { wm[tid] = w_mu[tid]; ws[tid] = w_sigma[tid]; }
    __syncthreads();

    const bf16* p0 = B0 + (long long)b * NBDM + j;
    const bf16* p1 = B1 + (long long)b * NBDM + j;
    float am = 0.f, as = 0.f;
    for (int n = g; n < NB; n += 2) {
        float xv = __bfloat162float(p0[(long long)n * DM]) +
                   __bfloat162float(p1[(long long)n * DM]);
        am += xv * wm[n];
        as += xv * ws[n];
    }
    red[0][tid] = am; red[1][tid] = as;
    __syncthreads();
    if (tid < 128) {
        C[(long long)b * 2 * DM + j]      = red[0][tid] + red[0][tid + 128];
        C[(long long)b * 2 * DM + DM + j] = red[1][tid] + red[1][tid + 128];
    }
}

// ---------------- B: kw[bs][i] = sum_j Wk[i][j] * c[bs][j] ----------------
__global__ __launch_bounds__(256)
void kw_kernel(const float* __restrict__ Wk, const float* __restrict__ C,
               float* __restrict__ KW)
{
    __shared__ float wt[64][65];
    __shared__ float cs[16][64];
    int tid = threadIdx.x;
    int i0 = blockIdx.x * 64;
    int i = tid & 63, qg = tid >> 6;
    float acc[4] = {0.f, 0.f, 0.f, 0.f};

    for (int jc = 0; jc < DM; jc += 64) {
#pragma unroll
        for (int t = 0; t < 16; t++) {
            int idx = tid + t * 256;
            wt[idx >> 6][idx & 63] = Wk[(long long)(i0 + (idx >> 6)) * DM + jc + (idx & 63)];
        }
#pragma unroll
        for (int t = 0; t < 4; t++) {
            int idx = tid + t * 256;
            cs[idx >> 6][idx & 63] = C[(long long)(idx >> 6) * DM + jc + (idx & 63)];
        }
        __syncthreads();
#pragma unroll
        for (int jj = 0; jj < 64; jj++) {
            float w = wt[i][jj];
            acc[0] += w * cs[qg][jj];
            acc[1] += w * cs[qg + 4][jj];
            acc[2] += w * cs[qg + 8][jj];
            acc[3] += w * cs[qg + 12][jj];
        }
        __syncthreads();
    }
#pragma unroll
    for (int t = 0; t < 4; t++)
        KW[(long long)(qg + t * 4) * DM + i0 + i] = acc[t];
}

// ---------------- C: T[b][h*2+s][j] = sum_i Wq[h*64+i][j] * kw[b][s][h*64+i] ----
__global__ __launch_bounds__(128)
void tvec_kernel(const float* __restrict__ Wq, const float* __restrict__ KW,
                 float* __restrict__ T)
{
    __shared__ float kws[16][64];
    int tid = threadIdx.x;
    int h = blockIdx.y;
    int j = blockIdx.x * 128 + tid;
#pragma unroll
    for (int t = 0; t < 8; t++) {
        int idx = tid + t * 128;
        kws[idx >> 6][idx & 63] = KW[(long long)(idx >> 6) * DM + h * 64 + (idx & 63)];
    }
    __syncthreads();
    float acc[16];
#pragma unroll
    for (int v = 0; v < 16; v++) acc[v] = 0.f;
    for (int ii = 0; ii < 64; ii++) {
        float w = Wq[(long long)(h * 64 + ii) * DM + j];
#pragma unroll
        for (int v = 0; v < 16; v++) acc[v] += w * kws[v][ii];
    }
#pragma unroll
    for (int v = 0; v < 16; v++) {
        int b = v >> 1, s = v & 1;
        T[((long long)b * 24 + h * 2 + s) * DM + j] = acc[v];
    }
}

// ---------------- D: mu/ss ----------------
__global__ __launch_bounds__(256)
void musig_kernel(const float* __restrict__ qin, const float* __restrict__ T,
                  float* __restrict__ mu_out, float* __restrict__ ss_out)
{
    __shared__ float Tc[24][132];
    int tid = threadIdx.x, lane = tid & 31, warp = tid >> 5;
    int rb = blockIdx.x * 8 + warp;
    int b = rb >> 10, qrow = rb & 1023;
    const float* qr = qin + (long long)qrow * (BATCH * DM) + (long long)b * DM;
    const float* Tb = T + (long long)b * 24 * DM;

    float acc[24];
#pragma unroll
    for (int v = 0; v < 24; v++) acc[v] = 0.f;

    for (int kc = 0; kc < 6; kc++) {
        __syncthreads();
#pragma unroll
        for (int t = 0; t < 12; t++) {
            int idx = tid + t * 256;
            Tc[idx >> 7][idx & 127] = Tb[(long long)(idx >> 7) * DM + kc * 128 + (idx & 127)];
        }
        __syncthreads();
        float4 qv = *(const float4*)(qr + kc * 128 + lane * 4);
#pragma unroll
        for (int v = 0; v < 24; v++) {
            float4 tv = *(const float4*)&Tc[v][lane * 4];
            acc[v] += qv.x * tv.x + qv.y * tv.y + qv.z * tv.z + qv.w * tv.w;
        }
    }
#pragma unroll
    for (int v = 0; v < 24; v++)
#pragma unroll
        for (int o = 16; o; o >>= 1)
            acc[v] += __shfl_xor_sync(0xffffffffu, acc[v], o);

    if (lane == 0) {
#pragma unroll
        for (int v = 0; v < 24; v++) {
            int h = v >> 1;
            float d = acc[v] * 0.125f;
            long long o = ((long long)b * NH + h) * LEN + qrow;
            if ((v & 1) == 0) mu_out[o] = 1.f / (1.f + __expf(-d));
            else              ss_out[o] = (d > 20.f) ? d : log1pf(__expf(d));
        }
    }
}

// ---------------- fused r + ctx = r@V : per-chunk-reseeded recurrence + mma --
__global__ __launch_bounds__(256)
void rv_mma_kernel(const float* __restrict__ mu,
                   const float* __restrict__ ss,
                   const float* __restrict__ mu_b,
                   const float* __restrict__ sigma_b,
                   const bf16* __restrict__ Vt0, const bf16* __restrict__ Vt1,
                   bf16* __restrict__ ctx0, bf16* __restrict__ ctx1)
{
    __shared__ __align__(16) bf16 rs0[128 * LDS_ROW];
    __shared__ __align__(16) bf16 rs1[128 * LDS_ROW];
    __shared__ __align__(16) bf16 vs0[64 * LDS_ROW];
    __shared__ __align__(16) bf16 vs1[64 * LDS_ROW];
    __shared__ float invs[128][2];
    __shared__ float mus[128];

    const int tid = threadIdx.x, lane = tid & 31, wid = tid >> 5;
    const int bh = blockIdx.y;
    const int b = bh / NH, h = bh - b * NH;
    const int m0 = blockIdx.x * 128;
    const int rowbase = bh * LEN + m0;

    if (tid < 128) mus[tid] = mu[rowbase + tid];
    {
        int row = tid >> 1, p = tid & 1;
        float sb = sigma_b[p];
        invs[row][p] = rsqrtf(sb * sb + ss[rowbase + row]);
    }
    __syncthreads();

    const float DELTA = 1.0f / 127.0f;
    const float C_PHI = 0.3989422804014327f;
    const int rm = tid >> 1, rp = tid & 1;
    const float r_mu = mus[rm];
    const float r_iv = invs[rm][rp];
    const float rscale = C_PHI * r_iv;
    const float ivd = r_iv * r_iv * DELTA;
    const float Wr = __expf(-ivd * DELTA);

    const int wm = (wid >> 1) * 32, wn = (wid & 1) * 32;
    float acc[2][4][4];
#pragma unroll
    for (int mt = 0; mt < 2; mt++)
#pragma unroll
        for (int nt = 0; nt < 4; nt++)
#pragma unroll
            for (int i = 0; i < 4; i++) acc[mt][nt][i] = 0.f;

    const bf16* vt0 = Vt0 + (long long)bh * DH * NB;
    const bf16* vt1 = Vt1 + (long long)bh * DH * NB;

    const int vrow = tid >> 2, vseg = tid & 3;

    const int brow = ((lane >> 4) << 3) + (lane & 7), bcol8 = ((lane >> 3) & 1) * 8;
    const int arow = lane & 15, acol8 = (lane >> 4) * 8;

    for (int nc = 0; nc < 8; nc++) {
        cpa16(vs0 + vrow * LDS_ROW + vseg * 8, vt0 + (long long)vrow * NB + nc * 32 + vseg * 8);
        cpa16(vs1 + vrow * LDS_ROW + vseg * 8, vt1 + (long long)vrow * NB + nc * 32 + vseg * 8);
        asm volatile("cp.async.commit_group;");

        float dmu = r_mu - (float)(nc * 16) * DELTA;
        float t0 = dmu * r_iv;
        float rv = rscale * __expf(-0.5f * t0 * t0);
        float rR = __expf(ivd * (dmu - 0.5f * DELTA));
        bf16* q0 = rs0 + rm * LDS_ROW + rp;
        bf16* q1 = rs1 + rm * LDS_ROW + rp;
#pragma unroll
        for (int jj = 0; jj < 16; jj++) {
            bf16 hh = __float2bfloat16(rv);
            q0[2 * jj] = hh;
            q1[2 * jj] = __float2bfloat16(rv - __bfloat162float(hh));
            rv *= rR;
            rR *= Wr;
        }
        asm volatile("cp.async.wait_group 0;");
        __syncthreads();

#pragma unroll
        for (int kk = 0; kk < 2; kk++) {
            const int ac = kk * 16 + acol8;
            const int bc = kk * 16 + bcol8;
            uint32_t a0[2][4], a1[2][4], b0[4][2], b1[4][2];
#pragma unroll
            for (int mt = 0; mt < 2; mt++) {
                ldsm4(a0[mt], rs0 + (wm + mt * 16 + arow) * LDS_ROW + ac);
                ldsm4(a1[mt], rs1 + (wm + mt * 16 + arow) * LDS_ROW + ac);
            }
#pragma unroll
            for (int np = 0; np < 2; np++) {
                uint32_t r[4];
                ldsm4(r, vs0 + (wn + np * 16 + brow) * LDS_ROW + bc);
                b0[np * 2][0] = r[0]; b0[np * 2][1] = r[1];
                b0[np * 2 + 1][0] = r[2]; b0[np * 2 + 1][1] = r[3];
                ldsm4(r, vs1 + (wn + np * 16 + brow) * LDS_ROW + bc);
                b1[np * 2][0] = r[0]; b1[np * 2][1] = r[1];
                b1[np * 2 + 1][0] = r[2]; b1[np * 2 + 1][1] = r[3];
            }
#pragma unroll
            for (int mt = 0; mt < 2; mt++)
#pragma unroll
                for (int nt = 0; nt < 4; nt++) {
                    mma16816(acc[mt][nt], a0[mt], b0[nt]);
                    mma16816(acc[mt][nt], a0[mt], b1[nt]);
                    mma16816(acc[mt][nt], a1[mt], b0[nt]);
                }
        }
        __syncthreads();
    }

    const int g = lane >> 2, c2 = (lane & 3) * 2;
#pragma unroll
    for (int mt = 0; mt < 2; mt++) {
#pragma unroll
        for (int nt = 0; nt < 4; nt++) {
            int row = m0 + wm + mt * 16 + g;
            int col = h * DH + wn + nt * 8 + c2;
            float v0 = acc[mt][nt][0], v1 = acc[mt][nt][1];
            float v2 = acc[mt][nt][2], v3 = acc[mt][nt][3];
            long long o0 = (long long)b * LDM_C + (long long)row * DM + col;
            long long o1 = o0 + 8LL * DM;
            bf16 h0 = __float2bfloat16(v0), h1 = __float2bfloat16(v1);
            bf16 h2 = __float2bfloat16(v2), h3 = __float2bfloat16(v3);
            bf16 l0 = __float2bfloat16(v0 - __bfloat162float(h0));
            bf16 l1 = __float2bfloat16(v1 - __bfloat162float(h1));
            bf16 l2 = __float2bfloat16(v2 - __bfloat162float(h2));
            bf16 l3 = __float2bfloat16(v3 - __bfloat162float(h3));
            *(__nv_bfloat162*)(ctx0 + o0) = __nv_bfloat162(h0, h1);
            *(__nv_bfloat162*)(ctx0 + o1) = __nv_bfloat162(h2, h3);
            *(__nv_bfloat162*)(ctx1 + o0) = __nv_bfloat162(l0, l1);
            *(__nv_bfloat162*)(ctx1 + o1) = __nv_bfloat162(l2, l3);
        }
    }
}

// ---------------- launch ----------------
extern "C" void kernel_launch(void* const* d_in, const int* in_sizes, int n_in,
                              void* d_out, int out_size)
{
    const float* x       = (const float*)d_in[0];
    const float* q       = (const float*)d_in[1];
    const float* Wq      = (const float*)d_in[2];
    const float* Wk      = (const float*)d_in[3];
    const float* Wv      = (const float*)d_in[4];
    const float* Wo      = (const float*)d_in[5];
    const float* w_mu    = (const float*)d_in[6];
    const float* w_sigma = (const float*)d_in[7];
    const float* mu_b    = (const float*)d_in[8];
    const float* sigma_b = (const float*)d_in[9];
    const float* G       = (const float*)d_in[10];
    float* out = (float*)d_out;

    cudaFuncSetAttribute(mma_gemm, cudaFuncAttributeMaxDynamicSharedMemorySize, GSMEM_BYTES);

    void *pxt0, *pxt1, *pGt0, *pGt1, *pWv0, *pWv1, *pWo0, *pWo1;
    void *pB0, *pB1, *pVt0, *pVt1;
    void *pC, *pKW, *pT, *pMu, *pSs, *pC0, *pC1;
    cudaGetSymbolAddress(&pxt0, g_xt0); cudaGetSymbolAddress(&pxt1, g_xt1);
    cudaGetSymbolAddress(&pGt0, g_Gt0); cudaGetSymbolAddress(&pGt1, g_Gt1);
    cudaGetSymbolAddress(&pWv0, g_Wv0); cudaGetSymbolAddress(&pWv1, g_Wv1);
    cudaGetSymbolAddress(&pWo0, g_Wo0); cudaGetSymbolAddress(&pWo1, g_Wo1);
    cudaGetSymbolAddress(&pB0, g_B0);   cudaGetSymbolAddress(&pB1, g_B1);
    cudaGetSymbolAddress(&pVt0, g_Vt0); cudaGetSymbolAddress(&pVt1, g_Vt1);
    cudaGetSymbolAddress(&pC, g_C);     cudaGetSymbolAddress(&pKW, g_KW);
    cudaGetSymbolAddress(&pT, g_T);
    cudaGetSymbolAddress(&pMu, g_mu);   cudaGetSymbolAddress(&pSs, g_ss);
    cudaGetSymbolAddress(&pC0, g_ctx0); cudaGetSymbolAddress(&pC1, g_ctx1);

    const long long NBDMll = NBDM;
    const long long DMLN = (long long)DM * LEN;
    dim3 blk(256);

    // ---- 1-2. transposed splits (x, G) ----
    tsplit_kernel<<<dim3(DM / 32, LEN / 32, BATCH), dim3(32, 8)>>>(
        x, DM, BATCH * DM, (bf16*)pxt0, (bf16*)pxt1, DMLN, LEN);
    tsplit_kernel<<<dim3(NB / 32, LEN / 32, 1), dim3(32, 8)>>>(
        G, 0, NB, (bf16*)pGt0, (bf16*)pGt1, 0, LEN);

    // ---- 3. merged Wv/Wo split ----
    splitWW_kernel<<<dim3((DM * DM) / 1024, 2), blk>>>(
        Wv, Wo, (bf16*)pWv0, (bf16*)pWv1, (bf16*)pWo0, (bf16*)pWo1);

    // ---- 4. Bmat[b] = Gt . xt_b^T (split out)  [ncu capture slot] ----
    mma_gemm<<<dim3(DM / 128, NB / 128, BATCH), blk, GSMEM_BYTES>>>(
        LEN,
        (bf16*)pGt0, (bf16*)pGt1, LEN, 0, 0,
        (bf16*)pxt0, (bf16*)pxt1, LEN, DMLN, 0,
        nullptr, (bf16*)pB0, (bf16*)pB1, DM, NBDMll, 0,
        1, 1.0f, 1);

    // ---- 5. V[b] = Bmat_b @ Wv^T with fused transpose-split epilogue -> Vt ----
    mma_gemm<<<dim3(DM / 128, NB / 128, BATCH), blk, GSMEM_BYTES>>>(
        DM,
        (bf16*)pB0, (bf16*)pB1, DM, NBDMll, 0,
        (bf16*)pWv0, (bf16*)pWv1, DM, 0, 0,
        nullptr, (bf16*)pVt0, (bf16*)pVt1, 0, 0, 0,
        1, 1.0f, 3);

    // ---- 6-9. tiny fp32 chain ----
    cvec_kernel<<<dim3(DM / 128, BATCH), blk>>>(
        (const bf16*)pB0, (const bf16*)pB1, w_mu, w_sigma, (float*)pC);
    kw_kernel<<<DM / 64, blk>>>(Wk, (const float*)pC, (float*)pKW);
    tvec_kernel<<<dim3(DM / 128, NH), dim3(128)>>>(Wq, (const float*)pKW, (float*)pT);
    musig_kernel<<<(BATCH * LEN) / 8, blk>>>(q, (const float*)pT,
                                             (float*)pMu, (float*)pSs);

    // ---- 10. fused r + ctx = r @ V ----
    rv_mma_kernel<<<dim3(LEN / 128, BATCH * NH), blk>>>(
        (const float*)pMu, (const float*)pSs, mu_b, sigma_b,
        (const bf16*)pVt0, (const bf16*)pVt1, (bf16*)pC0, (bf16*)pC1);

    // ---- 11. out[b] = ctx_b @ Wo^T (fp32 out) ----
    mma_gemm<<<dim3(DM / 128, LEN / 128, BATCH), blk, GSMEM_BYTES>>>(
        DM,
        (bf16*)pC0, (bf16*)pC1, DM, (long long)LDM_C, 0,
        (bf16*)pWo0, (bf16*)pWo1, DM, 0, 0,
        out, nullptr, nullptr, DM, (long long)LDM_C, 0,
        1, 1.0f, 0);
}

// round 11
// speedup vs baseline: 1.0445x; 1.0232x over previous
#include <cuda_runtime.h>
#include <cuda_bf16.h>
#include <math.h>
#include <stdint.h>

#define NH     12
#define DH     64
#define DM     768
#define NB     256
#define LEN    1024
#define BATCH  8

typedef __nv_bfloat16 bf16;

#define NBDM   (NB * DM)        // 196608
#define LDM_C  (LEN * DM)       // 786432

// ---------------- device scratch (static; no allocations) ----------------
__device__ __align__(16) bf16 g_xt0[BATCH * DM * LEN];
__device__ __align__(16) bf16 g_xt1[BATCH * DM * LEN];
__device__ __align__(16) bf16 g_Gt0[NB * LEN];
__device__ __align__(16) bf16 g_Gt1[NB * LEN];
__device__ __align__(16) bf16 g_Wv0[DM * DM]; __device__ __align__(16) bf16 g_Wv1[DM * DM];
__device__ __align__(16) bf16 g_Wo0[DM * DM]; __device__ __align__(16) bf16 g_Wo1[DM * DM];
__device__ __align__(16) bf16 g_B0 [BATCH * NBDM];
__device__ __align__(16) bf16 g_B1 [BATCH * NBDM];
__device__ __align__(16) float g_Bp[BATCH * 2 * NBDM];   // Bmat split-K partials
__device__ __align__(16) float g_Vp[BATCH * 2 * NBDM];   // V split-K partials
__device__ __align__(16) bf16 g_Vt0[BATCH * NH * DH * NB];
__device__ __align__(16) bf16 g_Vt1[BATCH * NH * DH * NB];
__device__ float g_C [BATCH * 2 * DM];
__device__ float g_KW[BATCH * 2 * DM];
__device__ float g_T [BATCH * 24 * DM];
__device__ float g_mu[BATCH * NH * LEN];
__device__ float g_ss[BATCH * NH * LEN];
__device__ __align__(16) bf16 g_ctx0[BATCH * LDM_C];
__device__ __align__(16) bf16 g_ctx1[BATCH * LDM_C];

// ---------------- helpers ----------------
__device__ __forceinline__ uint32_t smem_u32(const void* p)
{
    uint32_t a;
    asm("{ .reg .u64 t; cvta.to.shared.u64 t, %1; cvt.u32.u64 %0, t; }"
        : "=r"(a) : "l"(p));
    return a;
}
__device__ __forceinline__ void mma16816(float* c, const uint32_t* a, const uint32_t* b)
{
    asm volatile("mma.sync.aligned.m16n8k16.row.col.f32.bf16.bf16.f32 "
                 "{%0,%1,%2,%3}, {%4,%5,%6,%7}, {%8,%9}, {%0,%1,%2,%3};"
                 : "+f"(c[0]), "+f"(c[1]), "+f"(c[2]), "+f"(c[3])
                 : "r"(a[0]), "r"(a[1]), "r"(a[2]), "r"(a[3]), "r"(b[0]), "r"(b[1]));
}
__device__ __forceinline__ void ldsm4(uint32_t* r, const bf16* p)
{
    uint32_t a = smem_u32(p);
    asm volatile("ldmatrix.sync.aligned.m8n8.x4.shared.b16 {%0,%1,%2,%3}, [%4];"
                 : "=r"(r[0]), "=r"(r[1]), "=r"(r[2]), "=r"(r[3]) : "r"(a));
}
__device__ __forceinline__ void cpa16(bf16* s, const bf16* g)
{
    uint32_t sa = smem_u32(s);
    asm volatile("cp.async.cg.shared.global [%0], [%1], 16;" :: "r"(sa), "l"(g));
}

// ---------------- conversions ----------------
__global__ __launch_bounds__(256)
void splitWW_kernel(const float* __restrict__ Wv, const float* __restrict__ Wo,
                    bf16* __restrict__ v0, bf16* __restrict__ v1,
                    bf16* __restrict__ o0, bf16* __restrict__ o1)
{
    const float* src = blockIdx.y ? Wo : Wv;
    bf16* d0 = blockIdx.y ? o0 : v0;
    bf16* d1 = blockIdx.y ? o1 : v1;
    int i = (blockIdx.x * 256 + threadIdx.x) * 4;
    float4 v = *(const float4*)(src + i);
    bf16 h0 = __float2bfloat16(v.x), h1 = __float2bfloat16(v.y);
    bf16 h2 = __float2bfloat16(v.z), h3 = __float2bfloat16(v.w);
    *(__nv_bfloat162*)(d0 + i)     = __nv_bfloat162(h0, h1);
    *(__nv_bfloat162*)(d0 + i + 2) = __nv_bfloat162(h2, h3);
    *(__nv_bfloat162*)(d1 + i) = __nv_bfloat162(
        __float2bfloat16(v.x - __bfloat162float(h0)),
        __float2bfloat16(v.y - __bfloat162float(h1)));
    *(__nv_bfloat162*)(d1 + i + 2) = __nv_bfloat162(
        __float2bfloat16(v.z - __bfloat162float(h2)),
        __float2bfloat16(v.w - __bfloat162float(h3)));
}

__global__ __launch_bounds__(256)
void tsplit_kernel(const float* __restrict__ src, long long sb_in, int ldin,
                   bf16* __restrict__ d0, bf16* __restrict__ d1,
                   long long sb_out, int ldout)
{
    __shared__ float tile[32][33];
    int b = blockIdx.z;
    const float* s = src + (long long)b * sb_in;
    int m0 = blockIdx.y * 32, n0 = blockIdx.x * 32;
#pragma unroll
    for (int i = 0; i < 4; i++) {
        int m = m0 + threadIdx.y + i * 8;
        tile[threadIdx.y + i * 8][threadIdx.x] = s[(long long)m * ldin + n0 + threadIdx.x];
    }
    __syncthreads();
#pragma unroll
    for (int i = 0; i < 4; i++) {
        int n = n0 + threadIdx.y + i * 8;
        float v = tile[threadIdx.x][threadIdx.y + i * 8];
        long long o = (long long)b * sb_out + (long long)n * ldout + m0 + threadIdx.x;
        bf16 h = __float2bfloat16(v);
        d0[o] = h;
        d1[o] = __float2bfloat16(v - __bfloat162float(h));
    }
}

// combine 2 Bmat split-K partials -> split bf16 B0/B1
__global__ __launch_bounds__(256)
void combineB_kernel(const float* __restrict__ Bp,
                     bf16* __restrict__ B0, bf16* __restrict__ B1)
{
    int e = (blockIdx.x * 256 + threadIdx.x) * 4;
    int b = e / NBDM, j = e - b * NBDM;
    const float* base = Bp + (long long)b * 2 * NBDM + j;
    float4 v0 = *(const float4*)(base);
    float4 v1 = *(const float4*)(base + NBDM);
    float s0 = v0.x + v1.x, s1 = v0.y + v1.y;
    float s2 = v0.z + v1.z, s3 = v0.w + v1.w;
    long long o = (long long)b * NBDM + j;
    bf16 h0 = __float2bfloat16(s0), h1 = __float2bfloat16(s1);
    bf16 h2 = __float2bfloat16(s2), h3 = __float2bfloat16(s3);
    *(__nv_bfloat162*)(B0 + o)     = __nv_bfloat162(h0, h1);
    *(__nv_bfloat162*)(B0 + o + 2) = __nv_bfloat162(h2, h3);
    *(__nv_bfloat162*)(B1 + o) = __nv_bfloat162(
        __float2bfloat16(s0 - __bfloat162float(h0)),
        __float2bfloat16(s1 - __bfloat162float(h1)));
    *(__nv_bfloat162*)(B1 + o + 2) = __nv_bfloat162(
        __float2bfloat16(s2 - __bfloat162float(h2)),
        __float2bfloat16(s3 - __bfloat162float(h3)));
}

// V: sum 2 split-K partials + per-head transpose + split -> Vt[bh][d][n]
__global__ void vtrans_kernel(const float* __restrict__ Vp,
                              bf16* __restrict__ Vt0, bf16* __restrict__ Vt1)
{
    __shared__ float tile[32][33];
    int bh = blockIdx.z;
    int b = bh / NH, h = bh - b * NH;
    int n0 = blockIdx.x * 32, d0 = blockIdx.y * 32;
    const float* src = Vp + (long long)b * 2 * NBDM + h * DH;
#pragma unroll
    for (int i = 0; i < 4; i++) {
        int n = n0 + threadIdx.y + i * 8;
        long long o = (long long)n * DM + d0 + threadIdx.x;
        tile[threadIdx.y + i * 8][threadIdx.x] = src[o] + src[o + NBDM];
    }
    __syncthreads();
#pragma unroll
    for (int i = 0; i < 4; i++) {
        int d = d0 + threadIdx.y + i * 8;
        float v = tile[threadIdx.x][threadIdx.y + i * 8];
        long long o = ((long long)bh * DH + d) * NB + n0 + threadIdx.x;
        bf16 hh = __float2bfloat16(v);
        Vt0[o] = hh;
        Vt1[o] = __float2bfloat16(v - __bfloat162float(hh));
    }
}

// ---------------- split-bf16 tensor-core GEMM (K32, 80KB, reg-capped 2 CTA/SM) ----
#define LDS_ROW 40
#define TSZ     (128 * LDS_ROW)
#define STAGE_H (4 * TSZ)
#define GSMEM_BYTES (2 * STAGE_H * 2)

__global__ __launch_bounds__(256, 2)
void mma_gemm(int K,
              const bf16* __restrict__ A0, const bf16* __restrict__ A1,
              long long lda, long long sAb1, long long sAb2,
              const bf16* __restrict__ B0, const bf16* __restrict__ B1,
              long long ldb, long long sBb1, long long sBb2,
              float* __restrict__ C, bf16* __restrict__ C0, bf16* __restrict__ C1,
              long long ldc, long long sCb1, long long sCb2,
              int nz2, float alpha, int mode)
{
    extern __shared__ bf16 sm[];

    int z = blockIdx.z, z1 = z / nz2, z2 = z - z1 * nz2;
    A0 += z1 * sAb1 + z2 * sAb2;  A1 += z1 * sAb1 + z2 * sAb2;
    B0 += z1 * sBb1 + z2 * sBb2;  B1 += z1 * sBb1 + z2 * sBb2;
    const long long coff = z1 * sCb1 + z2 * sCb2;

    const int m0 = blockIdx.y * 128, n0 = blockIdx.x * 128;
    const int tid = threadIdx.x, lane = tid & 31, wid = tid >> 5;
    const int wm = (wid >> 2) * 64, wn = (wid & 3) * 32;

    float acc[4][4][4];
#pragma unroll
    for (int mt = 0; mt < 4; mt++)
#pragma unroll
        for (int nt = 0; nt < 4; nt++)
#pragma unroll
            for (int i = 0; i < 4; i++) acc[mt][nt][i] = 0.f;

    const int nstages = K >> 5;

    const int lrow = tid >> 2, lseg = tid & 3;
    auto load_stage = [&](int st, int k0) {
        bf16* base = sm + st * STAGE_H;
#pragma unroll
        for (int it = 0; it < 2; it++) {
            int row = lrow + it * 64;
            int so = row * LDS_ROW + lseg * 8;
            long long goA = (long long)(m0 + row) * lda + k0 + lseg * 8;
            long long goB = (long long)(n0 + row) * ldb + k0 + lseg * 8;
            cpa16(base + so,           A0 + goA);
            cpa16(base + TSZ + so,     A1 + goA);
            cpa16(base + 2 * TSZ + so, B0 + goB);
            cpa16(base + 3 * TSZ + so, B1 + goB);
        }
        asm volatile("cp.async.commit_group;");
    };

    load_stage(0, 0);

    const int arow = lane & 15, acol8 = (lane >> 4) * 8;
    const int brow = ((lane >> 4) << 3) + (lane & 7), bcol8 = ((lane >> 3) & 1) * 8;

    for (int s = 0; s < nstages; s++) {
        if (s + 1 < nstages) {
            load_stage((s + 1) & 1, (s + 1) << 5);
            asm volatile("cp.async.wait_group 1;");
        } else {
            asm volatile("cp.async.wait_group 0;");
        }
        __syncthreads();

        const bf16* As0 = sm + (s & 1) * STAGE_H;
        const bf16* As1 = As0 + TSZ;
        const bf16* Bs0 = As0 + 2 * TSZ;
        const bf16* Bs1 = As0 + 3 * TSZ;

#pragma unroll
        for (int kk = 0; kk < 2; kk++) {
            const int ac = kk * 16 + acol8;
            const int bc = kk * 16 + bcol8;
            uint32_t af[4][4], bf0[4][2], bf1[4][2];
#pragma unroll
            for (int mt = 0; mt < 4; mt++)
                ldsm4(af[mt], As0 + (wm + mt * 16 + arow) * LDS_ROW + ac);
#pragma unroll
            for (int np = 0; np < 2; np++) {
                uint32_t r[4];
                ldsm4(r, Bs0 + (wn + np * 16 + brow) * LDS_ROW + bc);
                bf0[np * 2][0] = r[0]; bf0[np * 2][1] = r[1];
                bf0[np * 2 + 1][0] = r[2]; bf0[np * 2 + 1][1] = r[3];
                ldsm4(r, Bs1 + (wn + np * 16 + brow) * LDS_ROW + bc);
                bf1[np * 2][0] = r[0]; bf1[np * 2][1] = r[1];
                bf1[np * 2 + 1][0] = r[2]; bf1[np * 2 + 1][1] = r[3];
            }
#pragma unroll
            for (int mt = 0; mt < 4; mt++)
#pragma unroll
                for (int nt = 0; nt < 4; nt++) mma16816(acc[mt][nt], af[mt], bf0[nt]);
#pragma unroll
            for (int mt = 0; mt < 4; mt++)
#pragma unroll
                for (int nt = 0; nt < 4; nt++) mma16816(acc[mt][nt], af[mt], bf1[nt]);
#pragma unroll
            for (int mt = 0; mt < 4; mt++)
                ldsm4(af[mt], As1 + (wm + mt * 16 + arow) * LDS_ROW + ac);
#pragma unroll
            for (int mt = 0; mt < 4; mt++)
#pragma unroll
                for (int nt = 0; nt < 4; nt++) mma16816(acc[mt][nt], af[mt], bf0[nt]);
        }
        __syncthreads();
    }

    const int g = lane >> 2, c2 = (lane & 3) * 2;
#pragma unroll
    for (int mt = 0; mt < 4; mt++) {
#pragma unroll
        for (int nt = 0; nt < 4; nt++) {
            int row = m0 + wm + mt * 16 + g;
            int col = n0 + wn + nt * 8 + c2;
            float v0 = alpha * acc[mt][nt][0], v1 = alpha * acc[mt][nt][1];
            float v2 = alpha * acc[mt][nt][2], v3 = alpha * acc[mt][nt][3];
            long long o0 = coff + (long long)row * ldc + col;
            long long o1 = coff + (long long)(row + 8) * ldc + col;
            if (mode == 0) {
                *(float2*)&C[o0] = make_float2(v0, v1);
                *(float2*)&C[o1] = make_float2(v2, v3);
            } else {
                bf16 h0 = __float2bfloat16(v0), h1 = __float2bfloat16(v1);
                bf16 h2 = __float2bfloat16(v2), h3 = __float2bfloat16(v3);
                bf16 l0 = __float2bfloat16(v0 - __bfloat162float(h0));
                bf16 l1 = __float2bfloat16(v1 - __bfloat162float(h1));
                bf16 l2 = __float2bfloat16(v2 - __bfloat162float(h2));
                bf16 l3 = __float2bfloat16(v3 - __bfloat162float(h3));
                *(__nv_bfloat162*)(C0 + o0) = __nv_bfloat162(h0, h1);
                *(__nv_bfloat162*)(C0 + o1) = __nv_bfloat162(h2, h3);
                *(__nv_bfloat162*)(C1 + o0) = __nv_bfloat162(l0, l1);
                *(__nv_bfloat162*)(C1 + o1) = __nv_bfloat162(l2, l3);
            }
        }
    }
}

// ---------------- A: c[b][s][j] = sum_n (B0+B1)[b][n][j] * w_s[n] ------------
__global__ __launch_bounds__(256)
void cvec_kernel(const bf16* __restrict__ B0, const bf16* __restrict__ B1,
                 const float* __restrict__ w_mu,
                 const float* __restrict__ w_sigma,
                 float* __restrict__ C)
{
    __shared__ float wm[NB], ws[NB];
    __shared__ float red[2][256];
    int tid = threadIdx.x;
    int b = blockIdx.y;
    int j = blockIdx.x * 128 + (tid & 127);
    int g = tid >> 7;
    if (tid < NB) { wm[tid] = w_mu[tid]; ws[tid] = w_sigma[tid]; }
    __syncthreads();

    const bf16* p0 = B0 + (long long)b * NBDM + j;
    const bf16* p1 = B1 + (long long)b * NBDM + j;
    float am = 0.f, as = 0.f;
    for (int n = g; n < NB; n += 2) {
        float xv = __bfloat162float(p0[(long long)n * DM]) +
                   __bfloat162float(p1[(long long)n * DM]);
        am += xv * wm[n];
        as += xv * ws[n];
    }
    red[0][tid] = am; red[1][tid] = as;
    __syncthreads();
    if (tid < 128) {
        C[(long long)b * 2 * DM + j]      = red[0][tid] + red[0][tid + 128];
        C[(long long)b * 2 * DM + DM + j] = red[1][tid] + red[1][tid + 128];
    }
}

// ---------------- B: kw[bs][i] = sum_j Wk[i][j] * c[bs][j] ----------------
__global__ __launch_bounds__(256)
void kw_kernel(const float* __restrict__ Wk, const float* __restrict__ C,
               float* __restrict__ KW)
{
    __shared__ float wt[64][65];
    __shared__ float cs[16][64];
    int tid = threadIdx.x;
    int i0 = blockIdx.x * 64;
    int i = tid & 63, qg = tid >> 6;
    float acc[4] = {0.f, 0.f, 0.f, 0.f};

    for (int jc = 0; jc < DM; jc += 64) {
#pragma unroll
        for (int t = 0; t < 16; t++) {
            int idx = tid + t * 256;
            wt[idx >> 6][idx & 63] = Wk[(long long)(i0 + (idx >> 6)) * DM + jc + (idx & 63)];
        }
#pragma unroll
        for (int t = 0; t < 4; t++) {
            int idx = tid + t * 256;
            cs[idx >> 6][idx & 63] = C[(long long)(idx >> 6) * DM + jc + (idx & 63)];
        }
        __syncthreads();
#pragma unroll
        for (int jj = 0; jj < 64; jj++) {
            float w = wt[i][jj];
            acc[0] += w * cs[qg][jj];
            acc[1] += w * cs[qg + 4][jj];
            acc[2] += w * cs[qg + 8][jj];
            acc[3] += w * cs[qg + 12][jj];
        }
        __syncthreads();
    }
#pragma unroll
    for (int t = 0; t < 4; t++)
        KW[(long long)(qg + t * 4) * DM + i0 + i] = acc[t];
}

// ---------------- C: T[b][h*2+s][j] = sum_i Wq[h*64+i][j] * kw[b][s][h*64+i] ----
__global__ __launch_bounds__(128)
void tvec_kernel(const float* __restrict__ Wq, const float* __restrict__ KW,
                 float* __restrict__ T)
{
    __shared__ float kws[16][64];
    int tid = threadIdx.x;
    int h = blockIdx.y;
    int j = blockIdx.x * 128 + tid;
#pragma unroll
    for (int t = 0; t < 8; t++) {
        int idx = tid + t * 128;
        kws[idx >> 6][idx & 63] = KW[(long long)(idx >> 6) * DM + h * 64 + (idx & 63)];
    }
    __syncthreads();
    float acc[16];
#pragma unroll
    for (int v = 0; v < 16; v++) acc[v] = 0.f;
    for (int ii = 0; ii < 64; ii++) {
        float w = Wq[(long long)(h * 64 + ii) * DM + j];
#pragma unroll
        for (int v = 0; v < 16; v++) acc[v] += w * kws[v][ii];
    }
#pragma unroll
    for (int v = 0; v < 16; v++) {
        int b = v >> 1, s = v & 1;
        T[((long long)b * 24 + h * 2 + s) * DM + j] = acc[v];
    }
}

// ---------------- D: mu/ss ----------------
__global__ __launch_bounds__(256)
void musig_kernel(const float* __restrict__ qin, const float* __restrict__ T,
                  float* __restrict__ mu_out, float* __restrict__ ss_out)
{
    __shared__ float Tc[24][132];
    int tid = threadIdx.x, lane = tid & 31, warp = tid >> 5;
    int rb = blockIdx.x * 8 + warp;
    int b = rb >> 10, qrow = rb & 1023;
    const float* qr = qin + (long long)qrow * (BATCH * DM) + (long long)b * DM;
    const float* Tb = T + (long long)b * 24 * DM;

    float acc[24];
#pragma unroll
    for (int v = 0; v < 24; v++) acc[v] = 0.f;

    for (int kc = 0; kc < 6; kc++) {
        __syncthreads();
#pragma unroll
        for (int t = 0; t < 12; t++) {
            int idx = tid + t * 256;
            Tc[idx >> 7][idx & 127] = Tb[(long long)(idx >> 7) * DM + kc * 128 + (idx & 127)];
        }
        __syncthreads();
        float4 qv = *(const float4*)(qr + kc * 128 + lane * 4);
#pragma unroll
        for (int v = 0; v < 24; v++) {
            float4 tv = *(const float4*)&Tc[v][lane * 4];
            acc[v] += qv.x * tv.x + qv.y * tv.y + qv.z * tv.z + qv.w * tv.w;
        }
    }
#pragma unroll
    for (int v = 0; v < 24; v++)
#pragma unroll
        for (int o = 16; o; o >>= 1)
            acc[v] += __shfl_xor_sync(0xffffffffu, acc[v], o);

    if (lane == 0) {
#pragma unroll
        for (int v = 0; v < 24; v++) {
            int h = v >> 1;
            float d = acc[v] * 0.125f;
            long long o = ((long long)b * NH + h) * LEN + qrow;
            if ((v & 1) == 0) mu_out[o] = 1.f / (1.f + __expf(-d));
            else              ss_out[o] = (d > 20.f) ? d : log1pf(__expf(d));
        }
    }
}

// ---------------- fused r + ctx = r@V : per-chunk-reseeded recurrence + mma --
__global__ __launch_bounds__(256)
void rv_mma_kernel(const float* __restrict__ mu,
                   const float* __restrict__ ss,
                   const float* __restrict__ mu_b,
                   const float* __restrict__ sigma_b,
                   const bf16* __restrict__ Vt0, const bf16* __restrict__ Vt1,
                   bf16* __restrict__ ctx0, bf16* __restrict__ ctx1)
{
    __shared__ __align__(16) bf16 rs0[128 * LDS_ROW];
    __shared__ __align__(16) bf16 rs1[128 * LDS_ROW];
    __shared__ __align__(16) bf16 vs0[64 * LDS_ROW];
    __shared__ __align__(16) bf16 vs1[64 * LDS_ROW];
    __shared__ float invs[128][2];
    __shared__ float mus[128];

    const int tid = threadIdx.x, lane = tid & 31, wid = tid >> 5;
    const int bh = blockIdx.y;
    const int b = bh / NH, h = bh - b * NH;
    const int m0 = blockIdx.x * 128;
    const int rowbase = bh * LEN + m0;

    if (tid < 128) mus[tid] = mu[rowbase + tid];
    {
        int row = tid >> 1, p = tid & 1;
        float sb = sigma_b[p];
        invs[row][p] = rsqrtf(sb * sb + ss[rowbase + row]);
    }
    __syncthreads();

    const float DELTA = 1.0f / 127.0f;
    const float C_PHI = 0.3989422804014327f;
    const int rm = tid >> 1, rp = tid & 1;
    const float r_mu = mus[rm];
    const float r_iv = invs[rm][rp];
    const float rscale = C_PHI * r_iv;
    const float ivd = r_iv * r_iv * DELTA;
    const float Wr = __expf(-ivd * DELTA);

    const int wm = (wid >> 1) * 32, wn = (wid & 1) * 32;
    float acc[2][4][4];
#pragma unroll
    for (int mt = 0; mt < 2; mt++)
#pragma unroll
        for (int nt = 0; nt < 4; nt++)
#pragma unroll
            for (int i = 0; i < 4; i++) acc[mt][nt][i] = 0.f;

    const bf16* vt0 = Vt0 + (long long)bh * DH * NB;
    const bf16* vt1 = Vt1 + (long long)bh * DH * NB;

    const int vrow = tid >> 2, vseg = tid & 3;

    const int brow = ((lane >> 4) << 3) + (lane & 7), bcol8 = ((lane >> 3) & 1) * 8;
    const int arow = lane & 15, acol8 = (lane >> 4) * 8;

    for (int nc = 0; nc < 8; nc++) {
        cpa16(vs0 + vrow * LDS_ROW + vseg * 8, vt0 + (long long)vrow * NB + nc * 32 + vseg * 8);
        cpa16(vs1 + vrow * LDS_ROW + vseg * 8, vt1 + (long long)vrow * NB + nc * 32 + vseg * 8);
        asm volatile("cp.async.commit_group;");

        float dmu = r_mu - (float)(nc * 16) * DELTA;
        float t0 = dmu * r_iv;
        float rv = rscale * __expf(-0.5f * t0 * t0);
        float rR = __expf(ivd * (dmu - 0.5f * DELTA));
        bf16* q0 = rs0 + rm * LDS_ROW + rp;
        bf16* q1 = rs1 + rm * LDS_ROW + rp;
#pragma unroll
        for (int jj = 0; jj < 16; jj++) {
            bf16 hh = __float2bfloat16(rv);
            q0[2 * jj] = hh;
            q1[2 * jj] = __float2bfloat16(rv - __bfloat162float(hh));
            rv *= rR;
            rR *= Wr;
        }
        asm volatile("cp.async.wait_group 0;");
        __syncthreads();

#pragma unroll
        for (int kk = 0; kk < 2; kk++) {
            const int ac = kk * 16 + acol8;
            const int bc = kk * 16 + bcol8;
            uint32_t a0[2][4], a1[2][4], b0[4][2], b1[4][2];
#pragma unroll
            for (int mt = 0; mt < 2; mt++) {
                ldsm4(a0[mt], rs0 + (wm + mt * 16 + arow) * LDS_ROW + ac);
                ldsm4(a1[mt], rs1 + (wm + mt * 16 + arow) * LDS_ROW + ac);
            }
#pragma unroll
            for (int np = 0; np < 2; np++) {
                uint32_t r[4];
                ldsm4(r, vs0 + (wn + np * 16 + brow) * LDS_ROW + bc);
                b0[np * 2][0] = r[0]; b0[np * 2][1] = r[1];
                b0[np * 2 + 1][0] = r[2]; b0[np * 2 + 1][1] = r[3];
                ldsm4(r, vs1 + (wn + np * 16 + brow) * LDS_ROW + bc);
                b1[np * 2][0] = r[0]; b1[np * 2][1] = r[1];
                b1[np * 2 + 1][0] = r[2]; b1[np * 2 + 1][1] = r[3];
            }
#pragma unroll
            for (int mt = 0; mt < 2; mt++)
#pragma unroll
                for (int nt = 0; nt < 4; nt++) {
                    mma16816(acc[mt][nt], a0[mt], b0[nt]);
                    mma16816(acc[mt][nt], a0[mt], b1[nt]);
                    mma16816(acc[mt][nt], a1[mt], b0[nt]);
                }
        }
        __syncthreads();
    }

    const int g = lane >> 2, c2 = (lane & 3) * 2;
#pragma unroll
    for (int mt = 0; mt < 2; mt++) {
#pragma unroll
        for (int nt = 0; nt < 4; nt++) {
            int row = m0 + wm + mt * 16 + g;
            int col = h * DH + wn + nt * 8 + c2;
            float v0 = acc[mt][nt][0], v1 = acc[mt][nt][1];
            float v2 = acc[mt][nt][2], v3 = acc[mt][nt][3];
            long long o0 = (long long)b * LDM_C + (long long)row * DM + col;
            long long o1 = o0 + 8LL * DM;
            bf16 h0 = __float2bfloat16(v0), h1 = __float2bfloat16(v1);
            bf16 h2 = __float2bfloat16(v2), h3 = __float2bfloat16(v3);
            bf16 l0 = __float2bfloat16(v0 - __bfloat162float(h0));
            bf16 l1 = __float2bfloat16(v1 - __bfloat162float(h1));
            bf16 l2 = __float2bfloat16(v2 - __bfloat162float(h2));
            bf16 l3 = __float2bfloat16(v3 - __bfloat162float(h3));
            *(__nv_bfloat162*)(ctx0 + o0) = __nv_bfloat162(h0, h1);
            *(__nv_bfloat162*)(ctx0 + o1) = __nv_bfloat162(h2, h3);
            *(__nv_bfloat162*)(ctx1 + o0) = __nv_bfloat162(l0, l1);
            *(__nv_bfloat162*)(ctx1 + o1) = __nv_bfloat162(l2, l3);
        }
    }
}

// ---------------- launch ----------------
extern "C" void kernel_launch(void* const* d_in, const int* in_sizes, int n_in,
                              void* d_out, int out_size)
{
    const float* x       = (const float*)d_in[0];
    const float* q       = (const float*)d_in[1];
    const float* Wq      = (const float*)d_in[2];
    const float* Wk      = (const float*)d_in[3];
    const float* Wv      = (const float*)d_in[4];
    const float* Wo      = (const float*)d_in[5];
    const float* w_mu    = (const float*)d_in[6];
    const float* w_sigma = (const float*)d_in[7];
    const float* mu_b    = (const float*)d_in[8];
    const float* sigma_b = (const float*)d_in[9];
    const float* G       = (const float*)d_in[10];
    float* out = (float*)d_out;

    cudaFuncSetAttribute(mma_gemm, cudaFuncAttributeMaxDynamicSharedMemorySize, GSMEM_BYTES);

    void *pxt0, *pxt1, *pGt0, *pGt1, *pWv0, *pWv1, *pWo0, *pWo1;
    void *pB0, *pB1, *pBp, *pVp, *pVt0, *pVt1;
    void *pC, *pKW, *pT, *pMu, *pSs, *pC0, *pC1;
    cudaGetSymbolAddress(&pxt0, g_xt0); cudaGetSymbolAddress(&pxt1, g_xt1);
    cudaGetSymbolAddress(&pGt0, g_Gt0); cudaGetSymbolAddress(&pGt1, g_Gt1);
    cudaGetSymbolAddress(&pWv0, g_Wv0); cudaGetSymbolAddress(&pWv1, g_Wv1);
    cudaGetSymbolAddress(&pWo0, g_Wo0); cudaGetSymbolAddress(&pWo1, g_Wo1);
    cudaGetSymbolAddress(&pB0, g_B0);   cudaGetSymbolAddress(&pB1, g_B1);
    cudaGetSymbolAddress(&pBp, g_Bp);   cudaGetSymbolAddress(&pVp, g_Vp);
    cudaGetSymbolAddress(&pVt0, g_Vt0); cudaGetSymbolAddress(&pVt1, g_Vt1);
    cudaGetSymbolAddress(&pC, g_C);     cudaGetSymbolAddress(&pKW, g_KW);
    cudaGetSymbolAddress(&pT, g_T);
    cudaGetSymbolAddress(&pMu, g_mu);   cudaGetSymbolAddress(&pSs, g_ss);
    cudaGetSymbolAddress(&pC0, g_ctx0); cudaGetSymbolAddress(&pC1, g_ctx1);

    const long long NBDMll = NBDM;
    const long long DMLN = (long long)DM * LEN;
    dim3 blk(256);

    // ---- 1-2. transposed splits (x, G) ----
    tsplit_kernel<<<dim3(DM / 32, LEN / 32, BATCH), dim3(32, 8)>>>(
        x, DM, BATCH * DM, (bf16*)pxt0, (bf16*)pxt1, DMLN, LEN);
    tsplit_kernel<<<dim3(NB / 32, LEN / 32, 1), dim3(32, 8)>>>(
        G, 0, NB, (bf16*)pGt0, (bf16*)pGt1, 0, LEN);

    // ---- 3. merged Wv/Wo split ----
    splitWW_kernel<<<dim3((DM * DM) / 1024, 2), blk>>>(
        Wv, Wo, (bf16*)pWv0, (bf16*)pWv1, (bf16*)pWo0, (bf16*)pWo1);

    // ---- 4. Bmat split-K=2 (fp32 partials, 192 CTAs) [ncu capture slot] ----
    mma_gemm<<<dim3(DM / 128, NB / 128, BATCH * 2), blk, GSMEM_BYTES>>>(
        512,
        (bf16*)pGt0, (bf16*)pGt1, LEN, 0, 512,
        (bf16*)pxt0, (bf16*)pxt1, LEN, DMLN, 512,
        (float*)pBp, nullptr, nullptr, DM, 2LL * NBDM, NBDMll,
        2, 1.0f, 0);
    combineB_kernel<<<(BATCH * NBDM) / 1024, blk>>>(
        (const float*)pBp, (bf16*)pB0, (bf16*)pB1);

    // ---- 5. V split-K=2 (fp32 partials, 192 CTAs) ----
    mma_gemm<<<dim3(DM / 128, NB / 128, BATCH * 2), blk, GSMEM_BYTES>>>(
        384,
        (bf16*)pB0, (bf16*)pB1, DM, NBDMll, 384,
        (bf16*)pWv0, (bf16*)pWv1, DM, 0, 384,
        (float*)pVp, nullptr, nullptr, DM, 2LL * NBDM, NBDMll,
        2, 1.0f, 0);

    // ---- 5b. V combine + transpose + split ----
    vtrans_kernel<<<dim3(NB / 32, DH / 32, BATCH * NH), dim3(32, 8)>>>(
        (const float*)pVp, (bf16*)pVt0, (bf16*)pVt1);

    // ---- 6-9. tiny fp32 chain ----
    cvec_kernel<<<dim3(DM / 128, BATCH), blk>>>(
        (const bf16*)pB0, (const bf16*)pB1, w_mu, w_sigma, (float*)pC);
    kw_kernel<<<DM / 64, blk>>>(Wk, (const float*)pC, (float*)pKW);
    tvec_kernel<<<dim3(DM / 128, NH), dim3(128)>>>(Wq, (const float*)pKW, (float*)pT);
    musig_kernel<<<(BATCH * LEN) / 8, blk>>>(q, (const float*)pT,
                                             (float*)pMu, (float*)pSs);

    // ---- 10. fused r + ctx = r @ V ----
    rv_mma_kernel<<<dim3(LEN / 128, BATCH * NH), blk>>>(
        (const float*)pMu, (const float*)pSs, mu_b, sigma_b,
        (const bf16*)pVt0, (const bf16*)pVt1, (bf16*)pC0, (bf16*)pC1);

    // ---- 11. out[b] = ctx_b @ Wo^T (fp32 out, 384 CTAs @ 2/SM) ----
    mma_gemm<<<dim3(DM / 128, LEN / 128, BATCH), blk, GSMEM_BYTES>>>(
        DM,
        (bf16*)pC0, (bf16*)pC1, DM, (long long)LDM_C, 0,
        (bf16*)pWo0, (bf16*)pWo1, DM, 0, 0,
        out, nullptr, nullptr, DM, (long long)LDM_C, 0,
        1, 1.0f, 0);
}

// round 12
// speedup vs baseline: 1.0945x; 1.0479x over previous
#include <cuda_runtime.h>
#include <cuda_bf16.h>
#include <math.h>
#include <stdint.h>

#define NH     12
#define DH     64
#define DM     768
#define NB     256
#define LEN    1024
#define BATCH  8

typedef __nv_bfloat16 bf16;

#define NBDM   (NB * DM)        // 196608
#define LDM_C  (LEN * DM)       // 786432

// ---------------- device scratch (static; no allocations) ----------------
__device__ __align__(16) bf16 g_xt0[BATCH * DM * LEN];
__device__ __align__(16) bf16 g_xt1[BATCH * DM * LEN];
__device__ __align__(16) bf16 g_Gt0[NB * LEN];
__device__ __align__(16) bf16 g_Gt1[NB * LEN];
__device__ __align__(16) bf16 g_Wv0[DM * DM]; __device__ __align__(16) bf16 g_Wv1[DM * DM];
__device__ __align__(16) bf16 g_Wo0[DM * DM]; __device__ __align__(16) bf16 g_Wo1[DM * DM];
__device__ __align__(16) bf16 g_B0 [BATCH * NBDM];
__device__ __align__(16) bf16 g_B1 [BATCH * NBDM];
__device__ __align__(16) float g_Bp[BATCH * 4 * NBDM];   // Bmat split-K partials
__device__ __align__(16) float g_Vp[BATCH * 4 * NBDM];   // V split-K partials
__device__ __align__(16) bf16 g_Vt0[BATCH * NH * DH * NB];
__device__ __align__(16) bf16 g_Vt1[BATCH * NH * DH * NB];
__device__ float g_C [BATCH * 2 * DM];
__device__ float g_KW[BATCH * 2 * DM];
__device__ float g_T [BATCH * 24 * DM];
__device__ float g_mu[BATCH * NH * LEN];
__device__ float g_ss[BATCH * NH * LEN];
__device__ __align__(16) bf16 g_ctx0[BATCH * LDM_C];
__device__ __align__(16) bf16 g_ctx1[BATCH * LDM_C];

// ---------------- helpers ----------------
__device__ __forceinline__ uint32_t smem_u32(const void* p)
{
    uint32_t a;
    asm("{ .reg .u64 t; cvta.to.shared.u64 t, %1; cvt.u32.u64 %0, t; }"
        : "=r"(a) : "l"(p));
    return a;
}
__device__ __forceinline__ void mma16816(float* c, const uint32_t* a, const uint32_t* b)
{
    asm volatile("mma.sync.aligned.m16n8k16.row.col.f32.bf16.bf16.f32 "
                 "{%0,%1,%2,%3}, {%4,%5,%6,%7}, {%8,%9}, {%0,%1,%2,%3};"
                 : "+f"(c[0]), "+f"(c[1]), "+f"(c[2]), "+f"(c[3])
                 : "r"(a[0]), "r"(a[1]), "r"(a[2]), "r"(a[3]), "r"(b[0]), "r"(b[1]));
}
__device__ __forceinline__ void ldsm4(uint32_t* r, const bf16* p)
{
    uint32_t a = smem_u32(p);
    asm volatile("ldmatrix.sync.aligned.m8n8.x4.shared.b16 {%0,%1,%2,%3}, [%4];"
                 : "=r"(r[0]), "=r"(r[1]), "=r"(r[2]), "=r"(r[3]) : "r"(a));
}
__device__ __forceinline__ void cpa16(bf16* s, const bf16* g)
{
    uint32_t sa = smem_u32(s);
    asm volatile("cp.async.cg.shared.global [%0], [%1], 16;" :: "r"(sa), "l"(g));
}

// ---------------- conversions ----------------
__global__ __launch_bounds__(256)
void splitWW_kernel(const float* __restrict__ Wv, const float* __restrict__ Wo,
                    bf16* __restrict__ v0, bf16* __restrict__ v1,
                    bf16* __restrict__ o0, bf16* __restrict__ o1)
{
    const float* src = blockIdx.y ? Wo : Wv;
    bf16* d0 = blockIdx.y ? o0 : v0;
    bf16* d1 = blockIdx.y ? o1 : v1;
    int i = (blockIdx.x * 256 + threadIdx.x) * 4;
    float4 v = *(const float4*)(src + i);
    bf16 h0 = __float2bfloat16(v.x), h1 = __float2bfloat16(v.y);
    bf16 h2 = __float2bfloat16(v.z), h3 = __float2bfloat16(v.w);
    *(__nv_bfloat162*)(d0 + i)     = __nv_bfloat162(h0, h1);
    *(__nv_bfloat162*)(d0 + i + 2) = __nv_bfloat162(h2, h3);
    *(__nv_bfloat162*)(d1 + i) = __nv_bfloat162(
        __float2bfloat16(v.x - __bfloat162float(h0)),
        __float2bfloat16(v.y - __bfloat162float(h1)));
    *(__nv_bfloat162*)(d1 + i + 2) = __nv_bfloat162(
        __float2bfloat16(v.z - __bfloat162float(h2)),
        __float2bfloat16(v.w - __bfloat162float(h3)));
}

__global__ __launch_bounds__(256)
void tsplit_kernel(const float* __restrict__ src, long long sb_in, int ldin,
                   bf16* __restrict__ d0, bf16* __restrict__ d1,
                   long long sb_out, int ldout)
{
    __shared__ float tile[32][33];
    int b = blockIdx.z;
    const float* s = src + (long long)b * sb_in;
    int m0 = blockIdx.y * 32, n0 = blockIdx.x * 32;
#pragma unroll
    for (int i = 0; i < 4; i++) {
        int m = m0 + threadIdx.y + i * 8;
        tile[threadIdx.y + i * 8][threadIdx.x] = s[(long long)m * ldin + n0 + threadIdx.x];
    }
    __syncthreads();
#pragma unroll
    for (int i = 0; i < 4; i++) {
        int n = n0 + threadIdx.y + i * 8;
        float v = tile[threadIdx.x][threadIdx.y + i * 8];
        long long o = (long long)b * sb_out + (long long)n * ldout + m0 + threadIdx.x;
        bf16 h = __float2bfloat16(v);
        d0[o] = h;
        d1[o] = __float2bfloat16(v - __bfloat162float(h));
    }
}

// combine 4 Bmat split-K partials -> split bf16 B0/B1
__global__ __launch_bounds__(256)
void combineB_kernel(const float* __restrict__ Bp,
                     bf16* __restrict__ B0, bf16* __restrict__ B1)
{
    int e = (blockIdx.x * 256 + threadIdx.x) * 4;
    int b = e / NBDM, j = e - b * NBDM;
    const float* base = Bp + (long long)b * 4 * NBDM + j;
    float4 v0 = *(const float4*)(base);
    float4 v1 = *(const float4*)(base + NBDM);
    float4 v2 = *(const float4*)(base + 2 * NBDM);
    float4 v3 = *(const float4*)(base + 3 * NBDM);
    float s0 = (v0.x + v1.x) + (v2.x + v3.x);
    float s1 = (v0.y + v1.y) + (v2.y + v3.y);
    float s2 = (v0.z + v1.z) + (v2.z + v3.z);
    float s3 = (v0.w + v1.w) + (v2.w + v3.w);
    long long o = (long long)b * NBDM + j;
    bf16 h0 = __float2bfloat16(s0), h1 = __float2bfloat16(s1);
    bf16 h2 = __float2bfloat16(s2), h3 = __float2bfloat16(s3);
    *(__nv_bfloat162*)(B0 + o)     = __nv_bfloat162(h0, h1);
    *(__nv_bfloat162*)(B0 + o + 2) = __nv_bfloat162(h2, h3);
    *(__nv_bfloat162*)(B1 + o) = __nv_bfloat162(
        __float2bfloat16(s0 - __bfloat162float(h0)),
        __float2bfloat16(s1 - __bfloat162float(h1)));
    *(__nv_bfloat162*)(B1 + o + 2) = __nv_bfloat162(
        __float2bfloat16(s2 - __bfloat162float(h2)),
        __float2bfloat16(s3 - __bfloat162float(h3)));
}

// V: sum 4 split-K partials + per-head transpose + split -> Vt[bh][d][n]
__global__ void vtrans_kernel(const float* __restrict__ Vp,
                              bf16* __restrict__ Vt0, bf16* __restrict__ Vt1)
{
    __shared__ float tile[32][33];
    int bh = blockIdx.z;
    int b = bh / NH, h = bh - b * NH;
    int n0 = blockIdx.x * 32, d0 = blockIdx.y * 32;
    const float* src = Vp + (long long)b * 4 * NBDM + h * DH;
#pragma unroll
    for (int i = 0; i < 4; i++) {
        int n = n0 + threadIdx.y + i * 8;
        long long o = (long long)n * DM + d0 + threadIdx.x;
        tile[threadIdx.y + i * 8][threadIdx.x] =
            (src[o] + src[o + NBDM]) + (src[o + 2 * NBDM] + src[o + 3 * NBDM]);
    }
    __syncthreads();
#pragma unroll
    for (int i = 0; i < 4; i++) {
        int d = d0 + threadIdx.y + i * 8;
        float v = tile[threadIdx.x][threadIdx.y + i * 8];
        long long o = ((long long)bh * DH + d) * NB + n0 + threadIdx.x;
        bf16 hh = __float2bfloat16(v);
        Vt0[o] = hh;
        Vt1[o] = __float2bfloat16(v - __bfloat162float(hh));
    }
}

// ---------------- split-bf16 tensor-core GEMM (K32, 80KB, reg-capped 2 CTA/SM) ----
#define LDS_ROW 40
#define TSZ     (128 * LDS_ROW)
#define STAGE_H (4 * TSZ)
#define GSMEM_BYTES (2 * STAGE_H * 2)

__global__ __launch_bounds__(256, 2)
void mma_gemm(int K,
              const bf16* __restrict__ A0, const bf16* __restrict__ A1,
              long long lda, long long sAb1, long long sAb2,
              const bf16* __restrict__ B0, const bf16* __restrict__ B1,
              long long ldb, long long sBb1, long long sBb2,
              float* __restrict__ C, bf16* __restrict__ C0, bf16* __restrict__ C1,
              long long ldc, long long sCb1, long long sCb2,
              int nz2, float alpha, int mode)
{
    extern __shared__ bf16 sm[];

    int z = blockIdx.z, z1 = z / nz2, z2 = z - z1 * nz2;
    A0 += z1 * sAb1 + z2 * sAb2;  A1 += z1 * sAb1 + z2 * sAb2;
    B0 += z1 * sBb1 + z2 * sBb2;  B1 += z1 * sBb1 + z2 * sBb2;
    const long long coff = z1 * sCb1 + z2 * sCb2;

    const int m0 = blockIdx.y * 128, n0 = blockIdx.x * 128;
    const int tid = threadIdx.x, lane = tid & 31, wid = tid >> 5;
    const int wm = (wid >> 2) * 64, wn = (wid & 3) * 32;

    float acc[4][4][4];
#pragma unroll
    for (int mt = 0; mt < 4; mt++)
#pragma unroll
        for (int nt = 0; nt < 4; nt++)
#pragma unroll
            for (int i = 0; i < 4; i++) acc[mt][nt][i] = 0.f;

    const int nstages = K >> 5;

    const int lrow = tid >> 2, lseg = tid & 3;
    auto load_stage = [&](int st, int k0) {
        bf16* base = sm + st * STAGE_H;
#pragma unroll
        for (int it = 0; it < 2; it++) {
            int row = lrow + it * 64;
            int so = row * LDS_ROW + lseg * 8;
            long long goA = (long long)(m0 + row) * lda + k0 + lseg * 8;
            long long goB = (long long)(n0 + row) * ldb + k0 + lseg * 8;
            cpa16(base + so,           A0 + goA);
            cpa16(base + TSZ + so,     A1 + goA);
            cpa16(base + 2 * TSZ + so, B0 + goB);
            cpa16(base + 3 * TSZ + so, B1 + goB);
        }
        asm volatile("cp.async.commit_group;");
    };

    load_stage(0, 0);

    const int arow = lane & 15, acol8 = (lane >> 4) * 8;
    const int brow = ((lane >> 4) << 3) + (lane & 7), bcol8 = ((lane >> 3) & 1) * 8;

    for (int s = 0; s < nstages; s++) {
        if (s + 1 < nstages) {
            load_stage((s + 1) & 1, (s + 1) << 5);
            asm volatile("cp.async.wait_group 1;");
        } else {
            asm volatile("cp.async.wait_group 0;");
        }
        __syncthreads();

        const bf16* As0 = sm + (s & 1) * STAGE_H;
        const bf16* As1 = As0 + TSZ;
        const bf16* Bs0 = As0 + 2 * TSZ;
        const bf16* Bs1 = As0 + 3 * TSZ;

#pragma unroll
        for (int kk = 0; kk < 2; kk++) {
            const int ac = kk * 16 + acol8;
            const int bc = kk * 16 + bcol8;
            uint32_t af[4][4], bf0[4][2], bf1[4][2];
#pragma unroll
            for (int mt = 0; mt < 4; mt++)
                ldsm4(af[mt], As0 + (wm + mt * 16 + arow) * LDS_ROW + ac);
#pragma unroll
            for (int np = 0; np < 2; np++) {
                uint32_t r[4];
                ldsm4(r, Bs0 + (wn + np * 16 + brow) * LDS_ROW + bc);
                bf0[np * 2][0] = r[0]; bf0[np * 2][1] = r[1];
                bf0[np * 2 + 1][0] = r[2]; bf0[np * 2 + 1][1] = r[3];
                ldsm4(r, Bs1 + (wn + np * 16 + brow) * LDS_ROW + bc);
                bf1[np * 2][0] = r[0]; bf1[np * 2][1] = r[1];
                bf1[np * 2 + 1][0] = r[2]; bf1[np * 2 + 1][1] = r[3];
            }
#pragma unroll
            for (int mt = 0; mt < 4; mt++)
#pragma unroll
                for (int nt = 0; nt < 4; nt++) mma16816(acc[mt][nt], af[mt], bf0[nt]);
#pragma unroll
            for (int mt = 0; mt < 4; mt++)
#pragma unroll
                for (int nt = 0; nt < 4; nt++) mma16816(acc[mt][nt], af[mt], bf1[nt]);
#pragma unroll
            for (int mt = 0; mt < 4; mt++)
                ldsm4(af[mt], As1 + (wm + mt * 16 + arow) * LDS_ROW + ac);
#pragma unroll
            for (int mt = 0; mt < 4; mt++)
#pragma unroll
                for (int nt = 0; nt < 4; nt++) mma16816(acc[mt][nt], af[mt], bf0[nt]);
        }
        __syncthreads();
    }

    const int g = lane >> 2, c2 = (lane & 3) * 2;
#pragma unroll
    for (int mt = 0; mt < 4; mt++) {
#pragma unroll
        for (int nt = 0; nt < 4; nt++) {
            int row = m0 + wm + mt * 16 + g;
            int col = n0 + wn + nt * 8 + c2;
            float v0 = alpha * acc[mt][nt][0], v1 = alpha * acc[mt][nt][1];
            float v2 = alpha * acc[mt][nt][2], v3 = alpha * acc[mt][nt][3];
            long long o0 = coff + (long long)row * ldc + col;
            long long o1 = coff + (long long)(row + 8) * ldc + col;
            if (mode == 0) {
                *(float2*)&C[o0] = make_float2(v0, v1);
                *(float2*)&C[o1] = make_float2(v2, v3);
            } else {
                bf16 h0 = __float2bfloat16(v0), h1 = __float2bfloat16(v1);
                bf16 h2 = __float2bfloat16(v2), h3 = __float2bfloat16(v3);
                bf16 l0 = __float2bfloat16(v0 - __bfloat162float(h0));
                bf16 l1 = __float2bfloat16(v1 - __bfloat162float(h1));
                bf16 l2 = __float2bfloat16(v2 - __bfloat162float(h2));
                bf16 l3 = __float2bfloat16(v3 - __bfloat162float(h3));
                *(__nv_bfloat162*)(C0 + o0) = __nv_bfloat162(h0, h1);
                *(__nv_bfloat162*)(C0 + o1) = __nv_bfloat162(h2, h3);
                *(__nv_bfloat162*)(C1 + o0) = __nv_bfloat162(l0, l1);
                *(__nv_bfloat162*)(C1 + o1) = __nv_bfloat162(l2, l3);
            }
        }
    }
}

// ---------------- A: c[b][s][j] = sum_n (B0+B1)[b][n][j] * w_s[n] ------------
__global__ __launch_bounds__(256)
void cvec_kernel(const bf16* __restrict__ B0, const bf16* __restrict__ B1,
                 const float* __restrict__ w_mu,
                 const float* __restrict__ w_sigma,
                 float* __restrict__ C)
{
    __shared__ float wm[NB], ws[NB];
    __shared__ float red[2][256];
    int tid = threadIdx.x;
    int b = blockIdx.y;
    int j = blockIdx.x * 128 + (tid & 127);
    int g = tid >> 7;
    if (tid < NB) { wm[tid] = w_mu[tid]; ws[tid] = w_sigma[tid]; }
    __syncthreads();

    const bf16* p0 = B0 + (long long)b * NBDM + j;
    const bf16* p1 = B1 + (long long)b * NBDM + j;
    float am = 0.f, as = 0.f;
    for (int n = g; n < NB; n += 2) {
        float xv = __bfloat162float(p0[(long long)n * DM]) +
                   __bfloat162float(p1[(long long)n * DM]);
        am += xv * wm[n];
        as += xv * ws[n];
    }
    red[0][tid] = am; red[1][tid] = as;
    __syncthreads();
    if (tid < 128) {
        C[(long long)b * 2 * DM + j]      = red[0][tid] + red[0][tid + 128];
        C[(long long)b * 2 * DM + DM + j] = red[1][tid] + red[1][tid + 128];
    }
}

// ---------------- B: kw[bs][i] = sum_j Wk[i][j] * c[bs][j] ----------------
__global__ __launch_bounds__(256)
void kw_kernel(const float* __restrict__ Wk, const float* __restrict__ C,
               float* __restrict__ KW)
{
    __shared__ float wt[64][65];
    __shared__ float cs[16][64];
    int tid = threadIdx.x;
    int i0 = blockIdx.x * 64;
    int i = tid & 63, qg = tid >> 6;
    float acc[4] = {0.f, 0.f, 0.f, 0.f};

    for (int jc = 0; jc < DM; jc += 64) {
#pragma unroll
        for (int t = 0; t < 16; t++) {
            int idx = tid + t * 256;
            wt[idx >> 6][idx & 63] = Wk[(long long)(i0 + (idx >> 6)) * DM + jc + (idx & 63)];
        }
#pragma unroll
        for (int t = 0; t < 4; t++) {
            int idx = tid + t * 256;
            cs[idx >> 6][idx & 63] = C[(long long)(idx >> 6) * DM + jc + (idx & 63)];
        }
        __syncthreads();
#pragma unroll
        for (int jj = 0; jj < 64; jj++) {
            float w = wt[i][jj];
            acc[0] += w * cs[qg][jj];
            acc[1] += w * cs[qg + 4][jj];
            acc[2] += w * cs[qg + 8][jj];
            acc[3] += w * cs[qg + 12][jj];
        }
        __syncthreads();
    }
#pragma unroll
    for (int t = 0; t < 4; t++)
        KW[(long long)(qg + t * 4) * DM + i0 + i] = acc[t];
}

// ---------------- C: T[b][h*2+s][j] = sum_i Wq[h*64+i][j] * kw[b][s][h*64+i] ----
__global__ __launch_bounds__(128)
void tvec_kernel(const float* __restrict__ Wq, const float* __restrict__ KW,
                 float* __restrict__ T)
{
    __shared__ float kws[16][64];
    int tid = threadIdx.x;
    int h = blockIdx.y;
    int j = blockIdx.x * 128 + tid;
#pragma unroll
    for (int t = 0; t < 8; t++) {
        int idx = tid + t * 128;
        kws[idx >> 6][idx & 63] = KW[(long long)(idx >> 6) * DM + h * 64 + (idx & 63)];
    }
    __syncthreads();
    float acc[16];
#pragma unroll
    for (int v = 0; v < 16; v++) acc[v] = 0.f;
    for (int ii = 0; ii < 64; ii++) {
        float w = Wq[(long long)(h * 64 + ii) * DM + j];
#pragma unroll
        for (int v = 0; v < 16; v++) acc[v] += w * kws[v][ii];
    }
#pragma unroll
    for (int v = 0; v < 16; v++) {
        int b = v >> 1, s = v & 1;
        T[((long long)b * 24 + h * 2 + s) * DM + j] = acc[v];
    }
}

// ---------------- D: mu/ss ----------------
__global__ __launch_bounds__(256)
void musig_kernel(const float* __restrict__ qin, const float* __restrict__ T,
                  float* __restrict__ mu_out, float* __restrict__ ss_out)
{
    __shared__ float Tc[24][132];
    int tid = threadIdx.x, lane = tid & 31, warp = tid >> 5;
    int rb = blockIdx.x * 8 + warp;
    int b = rb >> 10, qrow = rb & 1023;
    const float* qr = qin + (long long)qrow * (BATCH * DM) + (long long)b * DM;
    const float* Tb = T + (long long)b * 24 * DM;

    float acc[24];
#pragma unroll
    for (int v = 0; v < 24; v++) acc[v] = 0.f;

    for (int kc = 0; kc < 6; kc++) {
        __syncthreads();
#pragma unroll
        for (int t = 0; t < 12; t++) {
            int idx = tid + t * 256;
            Tc[idx >> 7][idx & 127] = Tb[(long long)(idx >> 7) * DM + kc * 128 + (idx & 127)];
        }
        __syncthreads();
        float4 qv = *(const float4*)(qr + kc * 128 + lane * 4);
#pragma unroll
        for (int v = 0; v < 24; v++) {
            float4 tv = *(const float4*)&Tc[v][lane * 4];
            acc[v] += qv.x * tv.x + qv.y * tv.y + qv.z * tv.z + qv.w * tv.w;
        }
    }
#pragma unroll
    for (int v = 0; v < 24; v++)
#pragma unroll
        for (int o = 16; o; o >>= 1)
            acc[v] += __shfl_xor_sync(0xffffffffu, acc[v], o);

    if (lane == 0) {
#pragma unroll
        for (int v = 0; v < 24; v++) {
            int h = v >> 1;
            float d = acc[v] * 0.125f;
            long long o = ((long long)b * NH + h) * LEN + qrow;
            if ((v & 1) == 0) mu_out[o] = 1.f / (1.f + __expf(-d));
            else              ss_out[o] = (d > 20.f) ? d : log1pf(__expf(d));
        }
    }
}

// ---------------- fused r + ctx = r@V : per-chunk-reseeded recurrence + mma --
__global__ __launch_bounds__(256)
void rv_mma_kernel(const float* __restrict__ mu,
                   const float* __restrict__ ss,
                   const float* __restrict__ mu_b,
                   const float* __restrict__ sigma_b,
                   const bf16* __restrict__ Vt0, const bf16* __restrict__ Vt1,
                   bf16* __restrict__ ctx0, bf16* __restrict__ ctx1)
{
    __shared__ __align__(16) bf16 rs0[128 * LDS_ROW];
    __shared__ __align__(16) bf16 rs1[128 * LDS_ROW];
    __shared__ __align__(16) bf16 vs0[64 * LDS_ROW];
    __shared__ __align__(16) bf16 vs1[64 * LDS_ROW];
    __shared__ float invs[128][2];
    __shared__ float mus[128];

    const int tid = threadIdx.x, lane = tid & 31, wid = tid >> 5;
    const int bh = blockIdx.y;
    const int b = bh / NH, h = bh - b * NH;
    const int m0 = blockIdx.x * 128;
    const int rowbase = bh * LEN + m0;

    if (tid < 128) mus[tid] = mu[rowbase + tid];
    {
        int row = tid >> 1, p = tid & 1;
        float sb = sigma_b[p];
        invs[row][p] = rsqrtf(sb * sb + ss[rowbase + row]);
    }
    __syncthreads();

    const float DELTA = 1.0f / 127.0f;
    const float C_PHI = 0.3989422804014327f;
    const int rm = tid >> 1, rp = tid & 1;
    const float r_mu = mus[rm];
    const float r_iv = invs[rm][rp];
    const float rscale = C_PHI * r_iv;
    const float ivd = r_iv * r_iv * DELTA;
    const float Wr = __expf(-ivd * DELTA);

    const int wm = (wid >> 1) * 32, wn = (wid & 1) * 32;
    float acc[2][4][4];
#pragma unroll
    for (int mt = 0; mt < 2; mt++)
#pragma unroll
        for (int nt = 0; nt < 4; nt++)
#pragma unroll
            for (int i = 0; i < 4; i++) acc[mt][nt][i] = 0.f;

    const bf16* vt0 = Vt0 + (long long)bh * DH * NB;
    const bf16* vt1 = Vt1 + (long long)bh * DH * NB;

    const int vrow = tid >> 2, vseg = tid & 3;

    const int brow = ((lane >> 4) << 3) + (lane & 7), bcol8 = ((lane >> 3) & 1) * 8;
    const int arow = lane & 15, acol8 = (lane >> 4) * 8;

    for (int nc = 0; nc < 8; nc++) {
        cpa16(vs0 + vrow * LDS_ROW + vseg * 8, vt0 + (long long)vrow * NB + nc * 32 + vseg * 8);
        cpa16(vs1 + vrow * LDS_ROW + vseg * 8, vt1 + (long long)vrow * NB + nc * 32 + vseg * 8);
        asm volatile("cp.async.commit_group;");

        float dmu = r_mu - (float)(nc * 16) * DELTA;
        float t0 = dmu * r_iv;
        float rv = rscale * __expf(-0.5f * t0 * t0);
        float rR = __expf(ivd * (dmu - 0.5f * DELTA));
        bf16* q0 = rs0 + rm * LDS_ROW + rp;
        bf16* q1 = rs1 + rm * LDS_ROW + rp;
#pragma unroll
        for (int jj = 0; jj < 16; jj++) {
            bf16 hh = __float2bfloat16(rv);
            q0[2 * jj] = hh;
            q1[2 * jj] = __float2bfloat16(rv - __bfloat162float(hh));
            rv *= rR;
            rR *= Wr;
        }
        asm volatile("cp.async.wait_group 0;");
        __syncthreads();

#pragma unroll
        for (int kk = 0; kk < 2; kk++) {
            const int ac = kk * 16 + acol8;
            const int bc = kk * 16 + bcol8;
            uint32_t a0[2][4], a1[2][4], b0[4][2], b1[4][2];
#pragma unroll
            for (int mt = 0; mt < 2; mt++) {
                ldsm4(a0[mt], rs0 + (wm + mt * 16 + arow) * LDS_ROW + ac);
                ldsm4(a1[mt], rs1 + (wm + mt * 16 + arow) * LDS_ROW + ac);
            }
#pragma unroll
            for (int np = 0; np < 2; np++) {
                uint32_t r[4];
                ldsm4(r, vs0 + (wn + np * 16 + brow) * LDS_ROW + bc);
                b0[np * 2][0] = r[0]; b0[np * 2][1] = r[1];
                b0[np * 2 + 1][0] = r[2]; b0[np * 2 + 1][1] = r[3];
                ldsm4(r, vs1 + (wn + np * 16 + brow) * LDS_ROW + bc);
                b1[np * 2][0] = r[0]; b1[np * 2][1] = r[1];
                b1[np * 2 + 1][0] = r[2]; b1[np * 2 + 1][1] = r[3];
            }
#pragma unroll
            for (int mt = 0; mt < 2; mt++)
#pragma unroll
                for (int nt = 0; nt < 4; nt++) {
                    mma16816(acc[mt][nt], a0[mt], b0[nt]);
                    mma16816(acc[mt][nt], a0[mt], b1[nt]);
                    mma16816(acc[mt][nt], a1[mt], b0[nt]);
                }
        }
        __syncthreads();
    }

    const int g = lane >> 2, c2 = (lane & 3) * 2;
#pragma unroll
    for (int mt = 0; mt < 2; mt++) {
#pragma unroll
        for (int nt = 0; nt < 4; nt++) {
            int row = m0 + wm + mt * 16 + g;
            int col = h * DH + wn + nt * 8 + c2;
            float v0 = acc[mt][nt][0], v1 = acc[mt][nt][1];
            float v2 = acc[mt][nt][2], v3 = acc[mt][nt][3];
            long long o0 = (long long)b * LDM_C + (long long)row * DM + col;
            long long o1 = o0 + 8LL * DM;
            bf16 h0 = __float2bfloat16(v0), h1 = __float2bfloat16(v1);
            bf16 h2 = __float2bfloat16(v2), h3 = __float2bfloat16(v3);
            bf16 l0 = __float2bfloat16(v0 - __bfloat162float(h0));
            bf16 l1 = __float2bfloat16(v1 - __bfloat162float(h1));
            bf16 l2 = __float2bfloat16(v2 - __bfloat162float(h2));
            bf16 l3 = __float2bfloat16(v3 - __bfloat162float(h3));
            *(__nv_bfloat162*)(ctx0 + o0) = __nv_bfloat162(h0, h1);
            *(__nv_bfloat162*)(ctx0 + o1) = __nv_bfloat162(h2, h3);
            *(__nv_bfloat162*)(ctx1 + o0) = __nv_bfloat162(l0, l1);
            *(__nv_bfloat162*)(ctx1 + o1) = __nv_bfloat162(l2, l3);
        }
    }
}

// ---------------- launch ----------------
extern "C" void kernel_launch(void* const* d_in, const int* in_sizes, int n_in,
                              void* d_out, int out_size)
{
    const float* x       = (const float*)d_in[0];
    const float* q       = (const float*)d_in[1];
    const float* Wq      = (const float*)d_in[2];
    const float* Wk      = (const float*)d_in[3];
    const float* Wv      = (const float*)d_in[4];
    const float* Wo      = (const float*)d_in[5];
    const float* w_mu    = (const float*)d_in[6];
    const float* w_sigma = (const float*)d_in[7];
    const float* mu_b    = (const float*)d_in[8];
    const float* sigma_b = (const float*)d_in[9];
    const float* G       = (const float*)d_in[10];
    float* out = (float*)d_out;

    cudaFuncSetAttribute(mma_gemm, cudaFuncAttributeMaxDynamicSharedMemorySize, GSMEM_BYTES);

    void *pxt0, *pxt1, *pGt0, *pGt1, *pWv0, *pWv1, *pWo0, *pWo1;
    void *pB0, *pB1, *pBp, *pVp, *pVt0, *pVt1;
    void *pC, *pKW, *pT, *pMu, *pSs, *pC0, *pC1;
    cudaGetSymbolAddress(&pxt0, g_xt0); cudaGetSymbolAddress(&pxt1, g_xt1);
    cudaGetSymbolAddress(&pGt0, g_Gt0); cudaGetSymbolAddress(&pGt1, g_Gt1);
    cudaGetSymbolAddress(&pWv0, g_Wv0); cudaGetSymbolAddress(&pWv1, g_Wv1);
    cudaGetSymbolAddress(&pWo0, g_Wo0); cudaGetSymbolAddress(&pWo1, g_Wo1);
    cudaGetSymbolAddress(&pB0, g_B0);   cudaGetSymbolAddress(&pB1, g_B1);
    cudaGetSymbolAddress(&pBp, g_Bp);   cudaGetSymbolAddress(&pVp, g_Vp);
    cudaGetSymbolAddress(&pVt0, g_Vt0); cudaGetSymbolAddress(&pVt1, g_Vt1);
    cudaGetSymbolAddress(&pC, g_C);     cudaGetSymbolAddress(&pKW, g_KW);
    cudaGetSymbolAddress(&pT, g_T);
    cudaGetSymbolAddress(&pMu, g_mu);   cudaGetSymbolAddress(&pSs, g_ss);
    cudaGetSymbolAddress(&pC0, g_ctx0); cudaGetSymbolAddress(&pC1, g_ctx1);

    const long long NBDMll = NBDM;
    const long long DMLN = (long long)DM * LEN;
    dim3 blk(256);

    // ---- 1-2. transposed splits (x, G) ----
    tsplit_kernel<<<dim3(DM / 32, LEN / 32, BATCH), dim3(32, 8)>>>(
        x, DM, BATCH * DM, (bf16*)pxt0, (bf16*)pxt1, DMLN, LEN);
    tsplit_kernel<<<dim3(NB / 32, LEN / 32, 1), dim3(32, 8)>>>(
        G, 0, NB, (bf16*)pGt0, (bf16*)pGt1, 0, LEN);

    // ---- 3. merged Wv/Wo split ----
    splitWW_kernel<<<dim3((DM * DM) / 1024, 2), blk>>>(
        Wv, Wo, (bf16*)pWv0, (bf16*)pWv1, (bf16*)pWo0, (bf16*)pWo1);

    // ---- 4. Bmat split-K=4 (fp32 partials, 384 CTAs @ 2/SM) [ncu slot] ----
    mma_gemm<<<dim3(DM / 128, NB / 128, BATCH * 4), blk, GSMEM_BYTES>>>(
        256,
        (bf16*)pGt0, (bf16*)pGt1, LEN, 0, 256,
        (bf16*)pxt0, (bf16*)pxt1, LEN, DMLN, 256,
        (float*)pBp, nullptr, nullptr, DM, 4LL * NBDM, NBDMll,
        4, 1.0f, 0);
    combineB_kernel<<<(BATCH * NBDM) / 1024, blk>>>(
        (const float*)pBp, (bf16*)pB0, (bf16*)pB1);

    // ---- 5. V split-K=4 (fp32 partials, 384 CTAs @ 2/SM) ----
    mma_gemm<<<dim3(DM / 128, NB / 128, BATCH * 4), blk, GSMEM_BYTES>>>(
        192,
        (bf16*)pB0, (bf16*)pB1, DM, NBDMll, 192,
        (bf16*)pWv0, (bf16*)pWv1, DM, 0, 192,
        (float*)pVp, nullptr, nullptr, DM, 4LL * NBDM, NBDMll,
        4, 1.0f, 0);

    // ---- 5b. V combine(4) + transpose + split ----
    vtrans_kernel<<<dim3(NB / 32, DH / 32, BATCH * NH), dim3(32, 8)>>>(
        (const float*)pVp, (bf16*)pVt0, (bf16*)pVt1);

    // ---- 6-9. tiny fp32 chain ----
    cvec_kernel<<<dim3(DM / 128, BATCH), blk>>>(
        (const bf16*)pB0, (const bf16*)pB1, w_mu, w_sigma, (float*)pC);
    kw_kernel<<<DM / 64, blk>>>(Wk, (const float*)pC, (float*)pKW);
    tvec_kernel<<<dim3(DM / 128, NH), dim3(128)>>>(Wq, (const float*)pKW, (float*)pT);
    musig_kernel<<<(BATCH * LEN) / 8, blk>>>(q, (const float*)pT,
                                             (float*)pMu, (float*)pSs);

    // ---- 10. fused r + ctx = r @ V ----
    rv_mma_kernel<<<dim3(LEN / 128, BATCH * NH), blk>>>(
        (const float*)pMu, (const float*)pSs, mu_b, sigma_b,
        (const bf16*)pVt0, (const bf16*)pVt1, (bf16*)pC0, (bf16*)pC1);

    // ---- 11. out[b] = ctx_b @ Wo^T (fp32 out, 384 CTAs @ 2/SM) ----
    mma_gemm<<<dim3(DM / 128, LEN / 128, BATCH), blk, GSMEM_BYTES>>>(
        DM,
        (bf16*)pC0, (bf16*)pC1, DM, (long long)LDM_C, 0,
        (bf16*)pWo0, (bf16*)pWo1, DM, 0, 0,
        out, nullptr, nullptr, DM, (long long)LDM_C, 0,
        1, 1.0f, 0);
}

// round 13
// speedup vs baseline: 1.1643x; 1.0637x over previous
#include <cuda_runtime.h>
#include <cuda_bf16.h>
#include <math.h>
#include <stdint.h>

#define NH     12
#define DH     64
#define DM     768
#define NB     256
#define LEN    1024
#define BATCH  8

typedef __nv_bfloat16 bf16;

#define NBDM   (NB * DM)        // 196608
#define LDM_C  (LEN * DM)       // 786432

// ---------------- device scratch (static; no allocations) ----------------
__device__ __align__(16) bf16 g_xt0[BATCH * DM * LEN];
__device__ __align__(16) bf16 g_xt1[BATCH * DM * LEN];
__device__ __align__(16) bf16 g_Gt0[NB * LEN];
__device__ __align__(16) bf16 g_Gt1[NB * LEN];
__device__ __align__(16) bf16 g_Wv0[DM * DM]; __device__ __align__(16) bf16 g_Wv1[DM * DM];
__device__ __align__(16) bf16 g_Wo0[DM * DM]; __device__ __align__(16) bf16 g_Wo1[DM * DM];
__device__ __align__(16) bf16 g_B0 [BATCH * NBDM];
__device__ __align__(16) bf16 g_B1 [BATCH * NBDM];
__device__ __align__(16) float g_Bp[BATCH * 4 * NBDM];
__device__ __align__(16) float g_Vp[BATCH * 4 * NBDM];
__device__ __align__(16) bf16 g_Vt0[BATCH * NH * DH * NB];
__device__ __align__(16) bf16 g_Vt1[BATCH * NH * DH * NB];
__device__ float g_C [BATCH * 2 * DM];
__device__ float g_KW[BATCH * 2 * DM];
__device__ float g_T [BATCH * 24 * DM];
__device__ float g_mu[BATCH * NH * LEN];
__device__ float g_ss[BATCH * NH * LEN];
__device__ __align__(16) bf16 g_ctx0[BATCH * LDM_C];
__device__ __align__(16) bf16 g_ctx1[BATCH * LDM_C];

// ---------------- helpers ----------------
__device__ __forceinline__ uint32_t smem_u32(const void* p)
{
    uint32_t a;
    asm("{ .reg .u64 t; cvta.to.shared.u64 t, %1; cvt.u32.u64 %0, t; }"
        : "=r"(a) : "l"(p));
    return a;
}
__device__ __forceinline__ void mma16816(float* c, const uint32_t* a, const uint32_t* b)
{
    asm volatile("mma.sync.aligned.m16n8k16.row.col.f32.bf16.bf16.f32 "
                 "{%0,%1,%2,%3}, {%4,%5,%6,%7}, {%8,%9}, {%0,%1,%2,%3};"
                 : "+f"(c[0]), "+f"(c[1]), "+f"(c[2]), "+f"(c[3])
                 : "r"(a[0]), "r"(a[1]), "r"(a[2]), "r"(a[3]), "r"(b[0]), "r"(b[1]));
}
__device__ __forceinline__ void ldsm4(uint32_t* r, const bf16* p)
{
    uint32_t a = smem_u32(p);
    asm volatile("ldmatrix.sync.aligned.m8n8.x4.shared.b16 {%0,%1,%2,%3}, [%4];"
                 : "=r"(r[0]), "=r"(r[1]), "=r"(r[2]), "=r"(r[3]) : "r"(a));
}
__device__ __forceinline__ void cpa16(bf16* s, const bf16* g)
{
    uint32_t sa = smem_u32(s);
    asm volatile("cp.async.cg.shared.global [%0], [%1], 16;" :: "r"(sa), "l"(g));
}

// ---------------- conversions ----------------
__global__ __launch_bounds__(256)
void splitWW_kernel(const float* __restrict__ Wv, const float* __restrict__ Wo,
                    bf16* __restrict__ v0, bf16* __restrict__ v1,
                    bf16* __restrict__ o0, bf16* __restrict__ o1)
{
    const float* src = blockIdx.y ? Wo : Wv;
    bf16* d0 = blockIdx.y ? o0 : v0;
    bf16* d1 = blockIdx.y ? o1 : v1;
    int i = (blockIdx.x * 256 + threadIdx.x) * 4;
    float4 v = *(const float4*)(src + i);
    bf16 h0 = __float2bfloat16(v.x), h1 = __float2bfloat16(v.y);
    bf16 h2 = __float2bfloat16(v.z), h3 = __float2bfloat16(v.w);
    *(__nv_bfloat162*)(d0 + i)     = __nv_bfloat162(h0, h1);
    *(__nv_bfloat162*)(d0 + i + 2) = __nv_bfloat162(h2, h3);
    *(__nv_bfloat162*)(d1 + i) = __nv_bfloat162(
        __float2bfloat16(v.x - __bfloat162float(h0)),
        __float2bfloat16(v.y - __bfloat162float(h1)));
    *(__nv_bfloat162*)(d1 + i + 2) = __nv_bfloat162(
        __float2bfloat16(v.z - __bfloat162float(h2)),
        __float2bfloat16(v.w - __bfloat162float(h3)));
}

__global__ __launch_bounds__(256)
void tsplit_kernel(const float* __restrict__ src, long long sb_in, int ldin,
                   bf16* __restrict__ d0, bf16* __restrict__ d1,
                   long long sb_out, int ldout)
{
    __shared__ float tile[32][33];
    int b = blockIdx.z;
    const float* s = src + (long long)b * sb_in;
    int m0 = blockIdx.y * 32, n0 = blockIdx.x * 32;
#pragma unroll
    for (int i = 0; i < 4; i++) {
        int m = m0 + threadIdx.y + i * 8;
        tile[threadIdx.y + i * 8][threadIdx.x] = s[(long long)m * ldin + n0 + threadIdx.x];
    }
    __syncthreads();
#pragma unroll
    for (int i = 0; i < 4; i++) {
        int n = n0 + threadIdx.y + i * 8;
        float v = tile[threadIdx.x][threadIdx.y + i * 8];
        long long o = (long long)b * sb_out + (long long)n * ldout + m0 + threadIdx.x;
        bf16 h = __float2bfloat16(v);
        d0[o] = h;
        d1[o] = __float2bfloat16(v - __bfloat162float(h));
    }
}

// combine 4 Bmat split-K partials -> split bf16 B0/B1
__global__ __launch_bounds__(256)
void combineB_kernel(const float* __restrict__ Bp,
                     bf16* __restrict__ B0, bf16* __restrict__ B1)
{
    int e = (blockIdx.x * 256 + threadIdx.x) * 4;
    int b = e / NBDM, j = e - b * NBDM;
    const float* base = Bp + (long long)b * 4 * NBDM + j;
    float4 v0 = *(const float4*)(base);
    float4 v1 = *(const float4*)(base + NBDM);
    float4 v2 = *(const float4*)(base + 2 * NBDM);
    float4 v3 = *(const float4*)(base + 3 * NBDM);
    float s0 = (v0.x + v1.x) + (v2.x + v3.x);
    float s1 = (v0.y + v1.y) + (v2.y + v3.y);
    float s2 = (v0.z + v1.z) + (v2.z + v3.z);
    float s3 = (v0.w + v1.w) + (v2.w + v3.w);
    long long o = (long long)b * NBDM + j;
    bf16 h0 = __float2bfloat16(s0), h1 = __float2bfloat16(s1);
    bf16 h2 = __float2bfloat16(s2), h3 = __float2bfloat16(s3);
    *(__nv_bfloat162*)(B0 + o)     = __nv_bfloat162(h0, h1);
    *(__nv_bfloat162*)(B0 + o + 2) = __nv_bfloat162(h2, h3);
    *(__nv_bfloat162*)(B1 + o) = __nv_bfloat162(
        __float2bfloat16(s0 - __bfloat162float(h0)),
        __float2bfloat16(s1 - __bfloat162float(h1)));
    *(__nv_bfloat162*)(B1 + o + 2) = __nv_bfloat162(
        __float2bfloat16(s2 - __bfloat162float(h2)),
        __float2bfloat16(s3 - __bfloat162float(h3)));
}

// V: sum 4 split-K partials + per-head transpose + split -> Vt[bh][d][n]
__global__ void vtrans_kernel(const float* __restrict__ Vp,
                              bf16* __restrict__ Vt0, bf16* __restrict__ Vt1)
{
    __shared__ float tile[32][33];
    int bh = blockIdx.z;
    int b = bh / NH, h = bh - b * NH;
    int n0 = blockIdx.x * 32, d0 = blockIdx.y * 32;
    const float* src = Vp + (long long)b * 4 * NBDM + h * DH;
#pragma unroll
    for (int i = 0; i < 4; i++) {
        int n = n0 + threadIdx.y + i * 8;
        long long o = (long long)n * DM + d0 + threadIdx.x;
        tile[threadIdx.y + i * 8][threadIdx.x] =
            (src[o] + src[o + NBDM]) + (src[o + 2 * NBDM] + src[o + 3 * NBDM]);
    }
    __syncthreads();
#pragma unroll
    for (int i = 0; i < 4; i++) {
        int d = d0 + threadIdx.y + i * 8;
        float v = tile[threadIdx.x][threadIdx.y + i * 8];
        long long o = ((long long)bh * DH + d) * NB + n0 + threadIdx.x;
        bf16 hh = __float2bfloat16(v);
        Vt0[o] = hh;
        Vt1[o] = __float2bfloat16(v - __bfloat162float(hh));
    }
}

// ---------------- split-bf16 tensor-core GEMM ----------------
// K32 stages, XOR-swizzled 64B rows (no pad), 3-buffer ring, 1 sync/stage,
// reg-capped 2 CTA/SM. Swizzle: 16B chunk index ^= (row>>1)&3.
#define TROW    32                      // halves per tile row (64 B)
#define TSZ_G   (128 * TROW)            // 4096 halves / tile
#define STG_G   (4 * TSZ_G)             // A0,A1,B0,B1 = 32 KB
#define GSMEM_BYTES (3 * STG_G * 2)     // 98304 B

#define SWZ(base, row, colh) \
    ((base) + (row) * TROW + (((((colh) >> 3) ^ (((row) >> 1) & 3))) << 3))

__global__ __launch_bounds__(256, 2)
void mma_gemm(int K,
              const bf16* __restrict__ A0, const bf16* __restrict__ A1,
              long long lda, long long sAb1, long long sAb2,
              const bf16* __restrict__ B0, const bf16* __restrict__ B1,
              long long ldb, long long sBb1, long long sBb2,
              float* __restrict__ C, bf16* __restrict__ C0, bf16* __restrict__ C1,
              long long ldc, long long sCb1, long long sCb2,
              int nz2, float alpha, int mode)
{
    extern __shared__ bf16 sm[];

    int z = blockIdx.z, z1 = z / nz2, z2 = z - z1 * nz2;
    A0 += z1 * sAb1 + z2 * sAb2;  A1 += z1 * sAb1 + z2 * sAb2;
    B0 += z1 * sBb1 + z2 * sBb2;  B1 += z1 * sBb1 + z2 * sBb2;
    const long long coff = z1 * sCb1 + z2 * sCb2;

    const int m0 = blockIdx.y * 128, n0 = blockIdx.x * 128;
    const int tid = threadIdx.x, lane = tid & 31, wid = tid >> 5;
    const int wm = (wid >> 2) * 64, wn = (wid & 3) * 32;

    float acc[4][4][4];
#pragma unroll
    for (int mt = 0; mt < 4; mt++)
#pragma unroll
        for (int nt = 0; nt < 4; nt++)
#pragma unroll
            for (int i = 0; i < 4; i++) acc[mt][nt][i] = 0.f;

    const int nstages = K >> 5;

    const int lrow = tid >> 2, lseg = tid & 3;
    auto load_stage = [&](int s) {
        bf16* base = sm + (s % 3) * STG_G;
        long long k0 = (long long)s << 5;
#pragma unroll
        for (int it = 0; it < 2; it++) {
            int row = lrow + it * 64;
            int so = row * TROW + ((lseg ^ ((row >> 1) & 3)) << 3);
            long long ko = k0 + lseg * 8;
            cpa16(base + so,             A0 + (long long)(m0 + row) * lda + ko);
            cpa16(base + TSZ_G + so,     A1 + (long long)(m0 + row) * lda + ko);
            cpa16(base + 2 * TSZ_G + so, B0 + (long long)(n0 + row) * ldb + ko);
            cpa16(base + 3 * TSZ_G + so, B1 + (long long)(n0 + row) * ldb + ko);
        }
        asm volatile("cp.async.commit_group;");
    };

    load_stage(0);
    if (nstages > 1) load_stage(1);

    const int arow = lane & 15, acol8 = (lane >> 4) * 8;
    const int brow = ((lane >> 4) << 3) + (lane & 7), bcol8 = ((lane >> 3) & 1) * 8;

    for (int s = 0; s < nstages; s++) {
        if (s + 1 < nstages) asm volatile("cp.async.wait_group 1;");
        else                 asm volatile("cp.async.wait_group 0;");
        __syncthreads();
        // safe: buffer (s+2)%3 == (s-1)%3 was last read in stage s-1, and all
        // warps passed the sync above only after finishing stage s-1.
        if (s + 2 < nstages) load_stage(s + 2);

        const bf16* As0 = sm + (s % 3) * STG_G;
        const bf16* As1 = As0 + TSZ_G;
        const bf16* Bs0 = As0 + 2 * TSZ_G;
        const bf16* Bs1 = As0 + 3 * TSZ_G;

#pragma unroll
        for (int kk = 0; kk < 2; kk++) {
            const int ac = kk * 16 + acol8;
            const int bc = kk * 16 + bcol8;
            uint32_t af[4][4], bf0[4][2], bf1[4][2];
#pragma unroll
            for (int mt = 0; mt < 4; mt++)
                ldsm4(af[mt], SWZ(As0, wm + mt * 16 + arow, ac));
#pragma unroll
            for (int np = 0; np < 2; np++) {
                uint32_t r[4];
                ldsm4(r, SWZ(Bs0, wn + np * 16 + brow, bc));
                bf0[np * 2][0] = r[0]; bf0[np * 2][1] = r[1];
                bf0[np * 2 + 1][0] = r[2]; bf0[np * 2 + 1][1] = r[3];
                ldsm4(r, SWZ(Bs1, wn + np * 16 + brow, bc));
                bf1[np * 2][0] = r[0]; bf1[np * 2][1] = r[1];
                bf1[np * 2 + 1][0] = r[2]; bf1[np * 2 + 1][1] = r[3];
            }
#pragma unroll
            for (int mt = 0; mt < 4; mt++)
#pragma unroll
                for (int nt = 0; nt < 4; nt++) mma16816(acc[mt][nt], af[mt], bf0[nt]);
#pragma unroll
            for (int mt = 0; mt < 4; mt++)
#pragma unroll
                for (int nt = 0; nt < 4; nt++) mma16816(acc[mt][nt], af[mt], bf1[nt]);
#pragma unroll
            for (int mt = 0; mt < 4; mt++)
                ldsm4(af[mt], SWZ(As1, wm + mt * 16 + arow, ac));
#pragma unroll
            for (int mt = 0; mt < 4; mt++)
#pragma unroll
                for (int nt = 0; nt < 4; nt++) mma16816(acc[mt][nt], af[mt], bf0[nt]);
        }
    }

    __syncthreads();
    const int g = lane >> 2, c2 = (lane & 3) * 2;
#pragma unroll
    for (int mt = 0; mt < 4; mt++) {
#pragma unroll
        for (int nt = 0; nt < 4; nt++) {
            int row = m0 + wm + mt * 16 + g;
            int col = n0 + wn + nt * 8 + c2;
            float v0 = alpha * acc[mt][nt][0], v1 = alpha * acc[mt][nt][1];
            float v2 = alpha * acc[mt][nt][2], v3 = alpha * acc[mt][nt][3];
            long long o0 = coff + (long long)row * ldc + col;
            long long o1 = coff + (long long)(row + 8) * ldc + col;
            if (mode == 0) {
                *(float2*)&C[o0] = make_float2(v0, v1);
                *(float2*)&C[o1] = make_float2(v2, v3);
            } else {
                bf16 h0 = __float2bfloat16(v0), h1 = __float2bfloat16(v1);
                bf16 h2 = __float2bfloat16(v2), h3 = __float2bfloat16(v3);
                bf16 l0 = __float2bfloat16(v0 - __bfloat162float(h0));
                bf16 l1 = __float2bfloat16(v1 - __bfloat162float(h1));
                bf16 l2 = __float2bfloat16(v2 - __bfloat162float(h2));
                bf16 l3 = __float2bfloat16(v3 - __bfloat162float(h3));
                *(__nv_bfloat162*)(C0 + o0) = __nv_bfloat162(h0, h1);
                *(__nv_bfloat162*)(C0 + o1) = __nv_bfloat162(h2, h3);
                *(__nv_bfloat162*)(C1 + o0) = __nv_bfloat162(l0, l1);
                *(__nv_bfloat162*)(C1 + o1) = __nv_bfloat162(l2, l3);
            }
        }
    }
}

// ---------------- A: c[b][s][j] = sum_n (B0+B1)[b][n][j] * w_s[n] ------------
__global__ __launch_bounds__(256)
void cvec_kernel(const bf16* __restrict__ B0, const bf16* __restrict__ B1,
                 const float* __restrict__ w_mu,
                 const float* __restrict__ w_sigma,
                 float* __restrict__ C)
{
    __shared__ float wm[NB], ws[NB];
    __shared__ float red[2][256];
    int tid = threadIdx.x;
    int b = blockIdx.y;
    int j = blockIdx.x * 128 + (tid & 127);
    int g = tid >> 7;
    if (tid < NB) { wm[tid] = w_mu[tid]; ws[tid] = w_sigma[tid]; }
    __syncthreads();

    const bf16* p0 = B0 + (long long)b * NBDM + j;
    const bf16* p1 = B1 + (long long)b * NBDM + j;
    float am = 0.f, as = 0.f;
    for (int n = g; n < NB; n += 2) {
        float xv = __bfloat162float(p0[(long long)n * DM]) +
                   __bfloat162float(p1[(long long)n * DM]);
        am += xv * wm[n];
        as += xv * ws[n];
    }
    red[0][tid] = am; red[1][tid] = as;
    __syncthreads();
    if (tid < 128) {
        C[(long long)b * 2 * DM + j]      = red[0][tid] + red[0][tid + 128];
        C[(long long)b * 2 * DM + DM + j] = red[1][tid] + red[1][tid + 128];
    }
}

// ---------------- B: kw[bs][i] = sum_j Wk[i][j] * c[bs][j] ----------------
__global__ __launch_bounds__(256)
void kw_kernel(const float* __restrict__ Wk, const float* __restrict__ C,
               float* __restrict__ KW)
{
    __shared__ float wt[64][65];
    __shared__ float cs[16][64];
    int tid = threadIdx.x;
    int i0 = blockIdx.x * 64;
    int i = tid & 63, qg = tid >> 6;
    float acc[4] = {0.f, 0.f, 0.f, 0.f};

    for (int jc = 0; jc < DM; jc += 64) {
#pragma unroll
        for (int t = 0; t < 16; t++) {
            int idx = tid + t * 256;
            wt[idx >> 6][idx & 63] = Wk[(long long)(i0 + (idx >> 6)) * DM + jc + (idx & 63)];
        }
#pragma unroll
        for (int t = 0; t < 4; t++) {
            int idx = tid + t * 256;
            cs[idx >> 6][idx & 63] = C[(long long)(idx >> 6) * DM + jc + (idx & 63)];
        }
        __syncthreads();
#pragma unroll
        for (int jj = 0; jj < 64; jj++) {
            float w = wt[i][jj];
            acc[0] += w * cs[qg][jj];
            acc[1] += w * cs[qg + 4][jj];
            acc[2] += w * cs[qg + 8][jj];
            acc[3] += w * cs[qg + 12][jj];
        }
        __syncthreads();
    }
#pragma unroll
    for (int t = 0; t < 4; t++)
        KW[(long long)(qg + t * 4) * DM + i0 + i] = acc[t];
}

// ---------------- C: T[b][h*2+s][j] = sum_i Wq[h*64+i][j] * kw[b][s][h*64+i] ----
__global__ __launch_bounds__(128)
void tvec_kernel(const float* __restrict__ Wq, const float* __restrict__ KW,
                 float* __restrict__ T)
{
    __shared__ float kws[16][64];
    int tid = threadIdx.x;
    int h = blockIdx.y;
    int j = blockIdx.x * 128 + tid;
#pragma unroll
    for (int t = 0; t < 8; t++) {
        int idx = tid + t * 128;
        kws[idx >> 6][idx & 63] = KW[(long long)(idx >> 6) * DM + h * 64 + (idx & 63)];
    }
    __syncthreads();
    float acc[16];
#pragma unroll
    for (int v = 0; v < 16; v++) acc[v] = 0.f;
    for (int ii = 0; ii < 64; ii++) {
        float w = Wq[(long long)(h * 64 + ii) * DM + j];
#pragma unroll
        for (int v = 0; v < 16; v++) acc[v] += w * kws[v][ii];
    }
#pragma unroll
    for (int v = 0; v < 16; v++) {
        int b = v >> 1, s = v & 1;
        T[((long long)b * 24 + h * 2 + s) * DM + j] = acc[v];
    }
}

// ---------------- D: mu/ss ----------------
__global__ __launch_bounds__(256)
void musig_kernel(const float* __restrict__ qin, const float* __restrict__ T,
                  float* __restrict__ mu_out, float* __restrict__ ss_out)
{
    __shared__ float Tc[24][132];
    int tid = threadIdx.x, lane = tid & 31, warp = tid >> 5;
    int rb = blockIdx.x * 8 + warp;
    int b = rb >> 10, qrow = rb & 1023;
    const float* qr = qin + (long long)qrow * (BATCH * DM) + (long long)b * DM;
    const float* Tb = T + (long long)b * 24 * DM;

    float acc[24];
#pragma unroll
    for (int v = 0; v < 24; v++) acc[v] = 0.f;

    for (int kc = 0; kc < 6; kc++) {
        __syncthreads();
#pragma unroll
        for (int t = 0; t < 12; t++) {
            int idx = tid + t * 256;
            Tc[idx >> 7][idx & 127] = Tb[(long long)(idx >> 7) * DM + kc * 128 + (idx & 127)];
        }
        __syncthreads();
        float4 qv = *(const float4*)(qr + kc * 128 + lane * 4);
#pragma unroll
        for (int v = 0; v < 24; v++) {
            float4 tv = *(const float4*)&Tc[v][lane * 4];
            acc[v] += qv.x * tv.x + qv.y * tv.y + qv.z * tv.z + qv.w * tv.w;
        }
    }
#pragma unroll
    for (int v = 0; v < 24; v++)
#pragma unroll
        for (int o = 16; o; o >>= 1)
            acc[v] += __shfl_xor_sync(0xffffffffu, acc[v], o);

    if (lane == 0) {
#pragma unroll
        for (int v = 0; v < 24; v++) {
            int h = v >> 1;
            float d = acc[v] * 0.125f;
            long long o = ((long long)b * NH + h) * LEN + qrow;
            if ((v & 1) == 0) mu_out[o] = 1.f / (1.f + __expf(-d));
            else              ss_out[o] = (d > 20.f) ? d : log1pf(__expf(d));
        }
    }
}

// ---------------- fused r + ctx = r@V (unchanged; own pad layout) ------------
#define LDS_ROW 40
__global__ __launch_bounds__(256)
void rv_mma_kernel(const float* __restrict__ mu,
                   const float* __restrict__ ss,
                   const float* __restrict__ mu_b,
                   const float* __restrict__ sigma_b,
                   const bf16* __restrict__ Vt0, const bf16* __restrict__ Vt1,
                   bf16* __restrict__ ctx0, bf16* __restrict__ ctx1)
{
    __shared__ __align__(16) bf16 rs0[128 * LDS_ROW];
    __shared__ __align__(16) bf16 rs1[128 * LDS_ROW];
    __shared__ __align__(16) bf16 vs0[64 * LDS_ROW];
    __shared__ __align__(16) bf16 vs1[64 * LDS_ROW];
    __shared__ float invs[128][2];
    __shared__ float mus[128];

    const int tid = threadIdx.x, lane = tid & 31, wid = tid >> 5;
    const int bh = blockIdx.y;
    const int b = bh / NH, h = bh - b * NH;
    const int m0 = blockIdx.x * 128;
    const int rowbase = bh * LEN + m0;

    if (tid < 128) mus[tid] = mu[rowbase + tid];
    {
        int row = tid >> 1, p = tid & 1;
        float sb = sigma_b[p];
        invs[row][p] = rsqrtf(sb * sb + ss[rowbase + row]);
    }
    __syncthreads();

    const float DELTA = 1.0f / 127.0f;
    const float C_PHI = 0.3989422804014327f;
    const int rm = tid >> 1, rp = tid & 1;
    const float r_mu = mus[rm];
    const float r_iv = invs[rm][rp];
    const float rscale = C_PHI * r_iv;
    const float ivd = r_iv * r_iv * DELTA;
    const float Wr = __expf(-ivd * DELTA);

    const int wm = (wid >> 1) * 32, wn = (wid & 1) * 32;
    float acc[2][4][4];
#pragma unroll
    for (int mt = 0; mt < 2; mt++)
#pragma unroll
        for (int nt = 0; nt < 4; nt++)
#pragma unroll
            for (int i = 0; i < 4; i++) acc[mt][nt][i] = 0.f;

    const bf16* vt0 = Vt0 + (long long)bh * DH * NB;
    const bf16* vt1 = Vt1 + (long long)bh * DH * NB;

    const int vrow = tid >> 2, vseg = tid & 3;

    const int brow = ((lane >> 4) << 3) + (lane & 7), bcol8 = ((lane >> 3) & 1) * 8;
    const int arow = lane & 15, acol8 = (lane >> 4) * 8;

    for (int nc = 0; nc < 8; nc++) {
        cpa16(vs0 + vrow * LDS_ROW + vseg * 8, vt0 + (long long)vrow * NB + nc * 32 + vseg * 8);
        cpa16(vs1 + vrow * LDS_ROW + vseg * 8, vt1 + (long long)vrow * NB + nc * 32 + vseg * 8);
        asm volatile("cp.async.commit_group;");

        float dmu = r_mu - (float)(nc * 16) * DELTA;
        float t0 = dmu * r_iv;
        float rv = rscale * __expf(-0.5f * t0 * t0);
        float rR = __expf(ivd * (dmu - 0.5f * DELTA));
        bf16* q0 = rs0 + rm * LDS_ROW + rp;
        bf16* q1 = rs1 + rm * LDS_ROW + rp;
#pragma unroll
        for (int jj = 0; jj < 16; jj++) {
            bf16 hh = __float2bfloat16(rv);
            q0[2 * jj] = hh;
            q1[2 * jj] = __float2bfloat16(rv - __bfloat162float(hh));
            rv *= rR;
            rR *= Wr;
        }
        asm volatile("cp.async.wait_group 0;");
        __syncthreads();

#pragma unroll
        for (int kk = 0; kk < 2; kk++) {
            const int ac = kk * 16 + acol8;
            const int bc = kk * 16 + bcol8;
            uint32_t a0[2][4], a1[2][4], b0[4][2], b1[4][2];
#pragma unroll
            for (int mt = 0; mt < 2; mt++) {
                ldsm4(a0[mt], rs0 + (wm + mt * 16 + arow) * LDS_ROW + ac);
                ldsm4(a1[mt], rs1 + (wm + mt * 16 + arow) * LDS_ROW + ac);
            }
#pragma unroll
            for (int np = 0; np < 2; np++) {
                uint32_t r[4];
                ldsm4(r, vs0 + (wn + np * 16 + brow) * LDS_ROW + bc);
                b0[np * 2][0] = r[0]; b0[np * 2][1] = r[1];
                b0[np * 2 + 1][0] = r[2]; b0[np * 2 + 1][1] = r[3];
                ldsm4(r, vs1 + (wn + np * 16 + brow) * LDS_ROW + bc);
                b1[np * 2][0] = r[0]; b1[np * 2][1] = r[1];
                b1[np * 2 + 1][0] = r[2]; b1[np * 2 + 1][1] = r[3];
            }
#pragma unroll
            for (int mt = 0; mt < 2; mt++)
#pragma unroll
                for (int nt = 0; nt < 4; nt++) {
                    mma16816(acc[mt][nt], a0[mt], b0[nt]);
                    mma16816(acc[mt][nt], a0[mt], b1[nt]);
                    mma16816(acc[mt][nt], a1[mt], b0[nt]);
                }
        }
        __syncthreads();
    }

    const int g = lane >> 2, c2 = (lane & 3) * 2;
#pragma unroll
    for (int mt = 0; mt < 2; mt++) {
#pragma unroll
        for (int nt = 0; nt < 4; nt++) {
            int row = m0 + wm + mt * 16 + g;
            int col = h * DH + wn + nt * 8 + c2;
            float v0 = acc[mt][nt][0], v1 = acc[mt][nt][1];
            float v2 = acc[mt][nt][2], v3 = acc[mt][nt][3];
            long long o0 = (long long)b * LDM_C + (long long)row * DM + col;
            long long o1 = o0 + 8LL * DM;
            bf16 h0 = __float2bfloat16(v0), h1 = __float2bfloat16(v1);
            bf16 h2 = __float2bfloat16(v2), h3 = __float2bfloat16(v3);
            bf16 l0 = __float2bfloat16(v0 - __bfloat162float(h0));
            bf16 l1 = __float2bfloat16(v1 - __bfloat162float(h1));
            bf16 l2 = __float2bfloat16(v2 - __bfloat162float(h2));
            bf16 l3 = __float2bfloat16(v3 - __bfloat162float(h3));
            *(__nv_bfloat162*)(ctx0 + o0) = __nv_bfloat162(h0, h1);
            *(__nv_bfloat162*)(ctx0 + o1) = __nv_bfloat162(h2, h3);
            *(__nv_bfloat162*)(ctx1 + o0) = __nv_bfloat162(l0, l1);
            *(__nv_bfloat162*)(ctx1 + o1) = __nv_bfloat162(l2, l3);
        }
    }
}

// ---------------- launch ----------------
extern "C" void kernel_launch(void* const* d_in, const int* in_sizes, int n_in,
                              void* d_out, int out_size)
{
    const float* x       = (const float*)d_in[0];
    const float* q       = (const float*)d_in[1];
    const float* Wq      = (const float*)d_in[2];
    const float* Wk      = (const float*)d_in[3];
    const float* Wv      = (const float*)d_in[4];
    const float* Wo      = (const float*)d_in[5];
    const float* w_mu    = (const float*)d_in[6];
    const float* w_sigma = (const float*)d_in[7];
    const float* mu_b    = (const float*)d_in[8];
    const float* sigma_b = (const float*)d_in[9];
    const float* G       = (const float*)d_in[10];
    float* out = (float*)d_out;

    cudaFuncSetAttribute(mma_gemm, cudaFuncAttributeMaxDynamicSharedMemorySize, GSMEM_BYTES);

    void *pxt0, *pxt1, *pGt0, *pGt1, *pWv0, *pWv1, *pWo0, *pWo1;
    void *pB0, *pB1, *pBp, *pVp, *pVt0, *pVt1;
    void *pC, *pKW, *pT, *pMu, *pSs, *pC0, *pC1;
    cudaGetSymbolAddress(&pxt0, g_xt0); cudaGetSymbolAddress(&pxt1, g_xt1);
    cudaGetSymbolAddress(&pGt0, g_Gt0); cudaGetSymbolAddress(&pGt1, g_Gt1);
    cudaGetSymbolAddress(&pWv0, g_Wv0); cudaGetSymbolAddress(&pWv1, g_Wv1);
    cudaGetSymbolAddress(&pWo0, g_Wo0); cudaGetSymbolAddress(&pWo1, g_Wo1);
    cudaGetSymbolAddress(&pB0, g_B0);   cudaGetSymbolAddress(&pB1, g_B1);
    cudaGetSymbolAddress(&pBp, g_Bp);   cudaGetSymbolAddress(&pVp, g_Vp);
    cudaGetSymbolAddress(&pVt0, g_Vt0); cudaGetSymbolAddress(&pVt1, g_Vt1);
    cudaGetSymbolAddress(&pC, g_C);     cudaGetSymbolAddress(&pKW, g_KW);
    cudaGetSymbolAddress(&pT, g_T);
    cudaGetSymbolAddress(&pMu, g_mu);   cudaGetSymbolAddress(&pSs, g_ss);
    cudaGetSymbolAddress(&pC0, g_ctx0); cudaGetSymbolAddress(&pC1, g_ctx1);

    const long long NBDMll = NBDM;
    const long long DMLN = (long long)DM * LEN;
    dim3 blk(256);

    // ---- 1-2. transposed splits (x, G) ----
    tsplit_kernel<<<dim3(DM / 32, LEN / 32, BATCH), dim3(32, 8)>>>(
        x, DM, BATCH * DM, (bf16*)pxt0, (bf16*)pxt1, DMLN, LEN);
    tsplit_kernel<<<dim3(NB / 32, LEN / 32, 1), dim3(32, 8)>>>(
        G, 0, NB, (bf16*)pGt0, (bf16*)pGt1, 0, LEN);

    // ---- 3. merged Wv/Wo split ----
    splitWW_kernel<<<dim3((DM * DM) / 1024, 2), blk>>>(
        Wv, Wo, (bf16*)pWv0, (bf16*)pWv1, (bf16*)pWo0, (bf16*)pWo1);

    // ---- 4. Bmat split-K=4 (fp32 partials, 384 CTAs @ 2/SM) [ncu slot] ----
    mma_gemm<<<dim3(DM / 128, NB / 128, BATCH * 4), blk, GSMEM_BYTES>>>(
        256,
        (bf16*)pGt0, (bf16*)pGt1, LEN, 0, 256,
        (bf16*)pxt0, (bf16*)pxt1, LEN, DMLN, 256,
        (float*)pBp, nullptr, nullptr, DM, 4LL * NBDM, NBDMll,
        4, 1.0f, 0);
    combineB_kernel<<<(BATCH * NBDM) / 1024, blk>>>(
        (const float*)pBp, (bf16*)pB0, (bf16*)pB1);

    // ---- 5. V split-K=4 (fp32 partials, 384 CTAs @ 2/SM) ----
    mma_gemm<<<dim3(DM / 128, NB / 128, BATCH * 4), blk, GSMEM_BYTES>>>(
        192,
        (bf16*)pB0, (bf16*)pB1, DM, NBDMll, 192,
        (bf16*)pWv0, (bf16*)pWv1, DM, 0, 192,
        (float*)pVp, nullptr, nullptr, DM, 4LL * NBDM, NBDMll,
        4, 1.0f, 0);

    // ---- 5b. V combine(4) + transpose + split ----
    vtrans_kernel<<<dim3(NB / 32, DH / 32, BATCH * NH), dim3(32, 8)>>>(
        (const float*)pVp, (bf16*)pVt0, (bf16*)pVt1);

    // ---- 6-9. tiny fp32 chain ----
    cvec_kernel<<<dim3(DM / 128, BATCH), blk>>>(
        (const bf16*)pB0, (const bf16*)pB1, w_mu, w_sigma, (float*)pC);
    kw_kernel<<<DM / 64, blk>>>(Wk, (const float*)pC, (float*)pKW);
    tvec_kernel<<<dim3(DM / 128, NH), dim3(128)>>>(Wq, (const float*)pKW, (float*)pT);
    musig_kernel<<<(BATCH * LEN) / 8, blk>>>(q, (const float*)pT,
                                             (float*)pMu, (float*)pSs);

    // ---- 10. fused r + ctx = r @ V ----
    rv_mma_kernel<<<dim3(LEN / 128, BATCH * NH), blk>>>(
        (const float*)pMu, (const float*)pSs, mu_b, sigma_b,
        (const bf16*)pVt0, (const bf16*)pVt1, (bf16*)pC0, (bf16*)pC1);

    // ---- 11. out[b] = ctx_b @ Wo^T (fp32 out, 384 CTAs @ 2/SM) ----
    mma_gemm<<<dim3(DM / 128, LEN / 128, BATCH), blk, GSMEM_BYTES>>>(
        DM,
        (bf16*)pC0, (bf16*)pC1, DM, (long long)LDM_C, 0,
        (bf16*)pWo0, (bf16*)pWo1, DM, 0, 0,
        out, nullptr, nullptr, DM, (long long)LDM_C, 0,
        1, 1.0f, 0);
}

// round 14
// speedup vs baseline: 1.2788x; 1.0983x over previous
#include <cuda_runtime.h>
#include <cuda_bf16.h>
#include <math.h>
#include <stdint.h>

#define NH     12
#define DH     64
#define DM     768
#define NB     256
#define LEN    1024
#define BATCH  8

typedef __nv_bfloat16 bf16;

#define NBDM   (NB * DM)        // 196608
#define LDM_C  (LEN * DM)       // 786432

// ---------------- device scratch (static; no allocations) ----------------
__device__ __align__(16) bf16 g_xt0[BATCH * DM * LEN];
__device__ __align__(16) bf16 g_xt1[BATCH * DM * LEN];
__device__ __align__(16) bf16 g_Gt0[NB * LEN];
__device__ __align__(16) bf16 g_Gt1[NB * LEN];
__device__ __align__(16) bf16 g_Wv0[DM * DM]; __device__ __align__(16) bf16 g_Wv1[DM * DM];
__device__ __align__(16) bf16 g_Wo0[DM * DM]; __device__ __align__(16) bf16 g_Wo1[DM * DM];
__device__ __align__(16) bf16 g_B0 [BATCH * NBDM];
__device__ __align__(16) bf16 g_B1 [BATCH * NBDM];
__device__ __align__(16) float g_Bp[BATCH * 4 * NBDM];
__device__ __align__(16) float g_Vp[BATCH * 4 * NBDM];
__device__ __align__(16) bf16 g_Vt0[BATCH * NH * DH * NB];
__device__ __align__(16) bf16 g_Vt1[BATCH * NH * DH * NB];
__device__ float g_C [BATCH * 2 * DM];
__device__ float g_KW[BATCH * 2 * DM];
__device__ float g_T [BATCH * 24 * DM];
__device__ float g_mu[BATCH * NH * LEN];
__device__ float g_ss[BATCH * NH * LEN];
__device__ __align__(16) bf16 g_ctx0[BATCH * LDM_C];
__device__ __align__(16) bf16 g_ctx1[BATCH * LDM_C];

// ---------------- helpers ----------------
__device__ __forceinline__ uint32_t smem_u32(const void* p)
{
    uint32_t a;
    asm("{ .reg .u64 t; cvta.to.shared.u64 t, %1; cvt.u32.u64 %0, t; }"
        : "=r"(a) : "l"(p));
    return a;
}
__device__ __forceinline__ void mma16816(float* c, const uint32_t* a, const uint32_t* b)
{
    asm volatile("mma.sync.aligned.m16n8k16.row.col.f32.bf16.bf16.f32 "
                 "{%0,%1,%2,%3}, {%4,%5,%6,%7}, {%8,%9}, {%0,%1,%2,%3};"
                 : "+f"(c[0]), "+f"(c[1]), "+f"(c[2]), "+f"(c[3])
                 : "r"(a[0]), "r"(a[1]), "r"(a[2]), "r"(a[3]), "r"(b[0]), "r"(b[1]));
}
__device__ __forceinline__ void ldsm4(uint32_t* r, const bf16* p)
{
    uint32_t a = smem_u32(p);
    asm volatile("ldmatrix.sync.aligned.m8n8.x4.shared.b16 {%0,%1,%2,%3}, [%4];"
                 : "=r"(r[0]), "=r"(r[1]), "=r"(r[2]), "=r"(r[3]) : "r"(a));
}
__device__ __forceinline__ void cpa16(bf16* s, const bf16* g)
{
    uint32_t sa = smem_u32(s);
    asm volatile("cp.async.cg.shared.global [%0], [%1], 16;" :: "r"(sa), "l"(g));
}

// ---------------- conversions ----------------
__global__ __launch_bounds__(256)
void splitWW_kernel(const float* __restrict__ Wv, const float* __restrict__ Wo,
                    bf16* __restrict__ v0, bf16* __restrict__ v1,
                    bf16* __restrict__ o0, bf16* __restrict__ o1)
{
    const float* src = blockIdx.y ? Wo : Wv;
    bf16* d0 = blockIdx.y ? o0 : v0;
    bf16* d1 = blockIdx.y ? o1 : v1;
    int i = (blockIdx.x * 256 + threadIdx.x) * 4;
    float4 v = *(const float4*)(src + i);
    bf16 h0 = __float2bfloat16(v.x), h1 = __float2bfloat16(v.y);
    bf16 h2 = __float2bfloat16(v.z), h3 = __float2bfloat16(v.w);
    *(__nv_bfloat162*)(d0 + i)     = __nv_bfloat162(h0, h1);
    *(__nv_bfloat162*)(d0 + i + 2) = __nv_bfloat162(h2, h3);
    *(__nv_bfloat162*)(d1 + i) = __nv_bfloat162(
        __float2bfloat16(v.x - __bfloat162float(h0)),
        __float2bfloat16(v.y - __bfloat162float(h1)));
    *(__nv_bfloat162*)(d1 + i + 2) = __nv_bfloat162(
        __float2bfloat16(v.z - __bfloat162float(h2)),
        __float2bfloat16(v.w - __bfloat162float(h3)));
}

__global__ __launch_bounds__(256)
void tsplit_kernel(const float* __restrict__ src, long long sb_in, int ldin,
                   bf16* __restrict__ d0, bf16* __restrict__ d1,
                   long long sb_out, int ldout)
{
    __shared__ float tile[32][33];
    int b = blockIdx.z;
    const float* s = src + (long long)b * sb_in;
    int m0 = blockIdx.y * 32, n0 = blockIdx.x * 32;
#pragma unroll
    for (int i = 0; i < 4; i++) {
        int m = m0 + threadIdx.y + i * 8;
        tile[threadIdx.y + i * 8][threadIdx.x] = s[(long long)m * ldin + n0 + threadIdx.x];
    }
    __syncthreads();
#pragma unroll
    for (int i = 0; i < 4; i++) {
        int n = n0 + threadIdx.y + i * 8;
        float v = tile[threadIdx.x][threadIdx.y + i * 8];
        long long o = (long long)b * sb_out + (long long)n * ldout + m0 + threadIdx.x;
        bf16 h = __float2bfloat16(v);
        d0[o] = h;
        d1[o] = __float2bfloat16(v - __bfloat162float(h));
    }
}

// combine 4 Bmat split-K partials -> split bf16 B0/B1
__global__ __launch_bounds__(256)
void combineB_kernel(const float* __restrict__ Bp,
                     bf16* __restrict__ B0, bf16* __restrict__ B1)
{
    int e = (blockIdx.x * 256 + threadIdx.x) * 4;
    int b = e / NBDM, j = e - b * NBDM;
    const float* base = Bp + (long long)b * 4 * NBDM + j;
    float4 v0 = *(const float4*)(base);
    float4 v1 = *(const float4*)(base + NBDM);
    float4 v2 = *(const float4*)(base + 2 * NBDM);
    float4 v3 = *(const float4*)(base + 3 * NBDM);
    float s0 = (v0.x + v1.x) + (v2.x + v3.x);
    float s1 = (v0.y + v1.y) + (v2.y + v3.y);
    float s2 = (v0.z + v1.z) + (v2.z + v3.z);
    float s3 = (v0.w + v1.w) + (v2.w + v3.w);
    long long o = (long long)b * NBDM + j;
    bf16 h0 = __float2bfloat16(s0), h1 = __float2bfloat16(s1);
    bf16 h2 = __float2bfloat16(s2), h3 = __float2bfloat16(s3);
    *(__nv_bfloat162*)(B0 + o)     = __nv_bfloat162(h0, h1);
    *(__nv_bfloat162*)(B0 + o + 2) = __nv_bfloat162(h2, h3);
    *(__nv_bfloat162*)(B1 + o) = __nv_bfloat162(
        __float2bfloat16(s0 - __bfloat162float(h0)),
        __float2bfloat16(s1 - __bfloat162float(h1)));
    *(__nv_bfloat162*)(B1 + o + 2) = __nv_bfloat162(
        __float2bfloat16(s2 - __bfloat162float(h2)),
        __float2bfloat16(s3 - __bfloat162float(h3)));
}

// V: sum 4 split-K partials + per-head transpose + split -> Vt[bh][d][n]
__global__ void vtrans_kernel(const float* __restrict__ Vp,
                              bf16* __restrict__ Vt0, bf16* __restrict__ Vt1)
{
    __shared__ float tile[32][33];
    int bh = blockIdx.z;
    int b = bh / NH, h = bh - b * NH;
    int n0 = blockIdx.x * 32, d0 = blockIdx.y * 32;
    const float* src = Vp + (long long)b * 4 * NBDM + h * DH;
#pragma unroll
    for (int i = 0; i < 4; i++) {
        int n = n0 + threadIdx.y + i * 8;
        long long o = (long long)n * DM + d0 + threadIdx.x;
        tile[threadIdx.y + i * 8][threadIdx.x] =
            (src[o] + src[o + NBDM]) + (src[o + 2 * NBDM] + src[o + 3 * NBDM]);
    }
    __syncthreads();
#pragma unroll
    for (int i = 0; i < 4; i++) {
        int d = d0 + threadIdx.y + i * 8;
        float v = tile[threadIdx.x][threadIdx.y + i * 8];
        long long o = ((long long)bh * DH + d) * NB + n0 + threadIdx.x;
        bf16 hh = __float2bfloat16(v);
        Vt0[o] = hh;
        Vt1[o] = __float2bfloat16(v - __bfloat162float(hh));
    }
}

// ---------------- split-bf16 tensor-core GEMM ----------------
// K32 stages, XOR-swizzled 64B rows, 3-buffer ring, 1 sync/stage, 2 CTA/SM.
#define TROW    32
#define TSZ_G   (128 * TROW)
#define STG_G   (4 * TSZ_G)
#define GSMEM_BYTES (3 * STG_G * 2)

#define SWZ(base, row, colh) \
    ((base) + (row) * TROW + (((((colh) >> 3) ^ (((row) >> 1) & 3))) << 3))

__global__ __launch_bounds__(256, 2)
void mma_gemm(int K,
              const bf16* __restrict__ A0, const bf16* __restrict__ A1,
              long long lda, long long sAb1, long long sAb2,
              const bf16* __restrict__ B0, const bf16* __restrict__ B1,
              long long ldb, long long sBb1, long long sBb2,
              float* __restrict__ C, bf16* __restrict__ C0, bf16* __restrict__ C1,
              long long ldc, long long sCb1, long long sCb2,
              int nz2, float alpha, int mode)
{
    extern __shared__ bf16 sm[];

    int z = blockIdx.z, z1 = z / nz2, z2 = z - z1 * nz2;
    A0 += z1 * sAb1 + z2 * sAb2;  A1 += z1 * sAb1 + z2 * sAb2;
    B0 += z1 * sBb1 + z2 * sBb2;  B1 += z1 * sBb1 + z2 * sBb2;
    const long long coff = z1 * sCb1 + z2 * sCb2;

    const int m0 = blockIdx.y * 128, n0 = blockIdx.x * 128;
    const int tid = threadIdx.x, lane = tid & 31, wid = tid >> 5;
    const int wm = (wid >> 2) * 64, wn = (wid & 3) * 32;

    float acc[4][4][4];
#pragma unroll
    for (int mt = 0; mt < 4; mt++)
#pragma unroll
        for (int nt = 0; nt < 4; nt++)
#pragma unroll
            for (int i = 0; i < 4; i++) acc[mt][nt][i] = 0.f;

    const int nstages = K >> 5;

    const int lrow = tid >> 2, lseg = tid & 3;
    auto load_stage = [&](int s) {
        bf16* base = sm + (s % 3) * STG_G;
        long long k0 = (long long)s << 5;
#pragma unroll
        for (int it = 0; it < 2; it++) {
            int row = lrow + it * 64;
            int so = row * TROW + ((lseg ^ ((row >> 1) & 3)) << 3);
            long long ko = k0 + lseg * 8;
            cpa16(base + so,             A0 + (long long)(m0 + row) * lda + ko);
            cpa16(base + TSZ_G + so,     A1 + (long long)(m0 + row) * lda + ko);
            cpa16(base + 2 * TSZ_G + so, B0 + (long long)(n0 + row) * ldb + ko);
            cpa16(base + 3 * TSZ_G + so, B1 + (long long)(n0 + row) * ldb + ko);
        }
        asm volatile("cp.async.commit_group;");
    };

    load_stage(0);
    if (nstages > 1) load_stage(1);

    const int arow = lane & 15, acol8 = (lane >> 4) * 8;
    const int brow = ((lane >> 4) << 3) + (lane & 7), bcol8 = ((lane >> 3) & 1) * 8;

    for (int s = 0; s < nstages; s++) {
        if (s + 1 < nstages) asm volatile("cp.async.wait_group 1;");
        else                 asm volatile("cp.async.wait_group 0;");
        __syncthreads();
        if (s + 2 < nstages) load_stage(s + 2);

        const bf16* As0 = sm + (s % 3) * STG_G;
        const bf16* As1 = As0 + TSZ_G;
        const bf16* Bs0 = As0 + 2 * TSZ_G;
        const bf16* Bs1 = As0 + 3 * TSZ_G;

#pragma unroll
        for (int kk = 0; kk < 2; kk++) {
            const int ac = kk * 16 + acol8;
            const int bc = kk * 16 + bcol8;
            uint32_t af[4][4], bf0[4][2], bf1[4][2];
#pragma unroll
            for (int mt = 0; mt < 4; mt++)
                ldsm4(af[mt], SWZ(As0, wm + mt * 16 + arow, ac));
#pragma unroll
            for (int np = 0; np < 2; np++) {
                uint32_t r[4];
                ldsm4(r, SWZ(Bs0, wn + np * 16 + brow, bc));
                bf0[np * 2][0] = r[0]; bf0[np * 2][1] = r[1];
                bf0[np * 2 + 1][0] = r[2]; bf0[np * 2 + 1][1] = r[3];
                ldsm4(r, SWZ(Bs1, wn + np * 16 + brow, bc));
                bf1[np * 2][0] = r[0]; bf1[np * 2][1] = r[1];
                bf1[np * 2 + 1][0] = r[2]; bf1[np * 2 + 1][1] = r[3];
            }
#pragma unroll
            for (int mt = 0; mt < 4; mt++)
#pragma unroll
                for (int nt = 0; nt < 4; nt++) mma16816(acc[mt][nt], af[mt], bf0[nt]);
#pragma unroll
            for (int mt = 0; mt < 4; mt++)
#pragma unroll
                for (int nt = 0; nt < 4; nt++) mma16816(acc[mt][nt], af[mt], bf1[nt]);
#pragma unroll
            for (int mt = 0; mt < 4; mt++)
                ldsm4(af[mt], SWZ(As1, wm + mt * 16 + arow, ac));
#pragma unroll
            for (int mt = 0; mt < 4; mt++)
#pragma unroll
                for (int nt = 0; nt < 4; nt++) mma16816(acc[mt][nt], af[mt], bf0[nt]);
        }
    }

    __syncthreads();
    const int g = lane >> 2, c2 = (lane & 3) * 2;
#pragma unroll
    for (int mt = 0; mt < 4; mt++) {
#pragma unroll
        for (int nt = 0; nt < 4; nt++) {
            int row = m0 + wm + mt * 16 + g;
            int col = n0 + wn + nt * 8 + c2;
            float v0 = alpha * acc[mt][nt][0], v1 = alpha * acc[mt][nt][1];
            float v2 = alpha * acc[mt][nt][2], v3 = alpha * acc[mt][nt][3];
            long long o0 = coff + (long long)row * ldc + col;
            long long o1 = coff + (long long)(row + 8) * ldc + col;
            if (mode == 0) {
                *(float2*)&C[o0] = make_float2(v0, v1);
                *(float2*)&C[o1] = make_float2(v2, v3);
            } else {
                bf16 h0 = __float2bfloat16(v0), h1 = __float2bfloat16(v1);
                bf16 h2 = __float2bfloat16(v2), h3 = __float2bfloat16(v3);
                bf16 l0 = __float2bfloat16(v0 - __bfloat162float(h0));
                bf16 l1 = __float2bfloat16(v1 - __bfloat162float(h1));
                bf16 l2 = __float2bfloat16(v2 - __bfloat162float(h2));
                bf16 l3 = __float2bfloat16(v3 - __bfloat162float(h3));
                *(__nv_bfloat162*)(C0 + o0) = __nv_bfloat162(h0, h1);
                *(__nv_bfloat162*)(C0 + o1) = __nv_bfloat162(h2, h3);
                *(__nv_bfloat162*)(C1 + o0) = __nv_bfloat162(l0, l1);
                *(__nv_bfloat162*)(C1 + o1) = __nv_bfloat162(l2, l3);
            }
        }
    }
}

// ---------------- A: c[b][s][j] = sum_n (B0+B1)[b][n][j] * w_s[n] ------------
__global__ __launch_bounds__(256)
void cvec_kernel(const bf16* __restrict__ B0, const bf16* __restrict__ B1,
                 const float* __restrict__ w_mu,
                 const float* __restrict__ w_sigma,
                 float* __restrict__ C)
{
    __shared__ float wm[NB], ws[NB];
    __shared__ float red[2][256];
    int tid = threadIdx.x;
    int b = blockIdx.y;
    int j = blockIdx.x * 128 + (tid & 127);
    int g = tid >> 7;
    if (tid < NB) { wm[tid] = w_mu[tid]; ws[tid] = w_sigma[tid]; }
    __syncthreads();

    const bf16* p0 = B0 + (long long)b * NBDM + j;
    const bf16* p1 = B1 + (long long)b * NBDM + j;
    float am = 0.f, as = 0.f;
    for (int n = g; n < NB; n += 2) {
        float xv = __bfloat162float(p0[(long long)n * DM]) +
                   __bfloat162float(p1[(long long)n * DM]);
        am += xv * wm[n];
        as += xv * ws[n];
    }
    red[0][tid] = am; red[1][tid] = as;
    __syncthreads();
    if (tid < 128) {
        C[(long long)b * 2 * DM + j]      = red[0][tid] + red[0][tid + 128];
        C[(long long)b * 2 * DM + DM + j] = red[1][tid] + red[1][tid + 128];
    }
}

// ---------------- B: kw[bs][i] = sum_j Wk[i][j] * c[bs][j] ----------------
__global__ __launch_bounds__(256)
void kw_kernel(const float* __restrict__ Wk, const float* __restrict__ C,
               float* __restrict__ KW)
{
    __shared__ float wt[64][65];
    __shared__ float cs[16][64];
    int tid = threadIdx.x;
    int i0 = blockIdx.x * 64;
    int i = tid & 63, qg = tid >> 6;
    float acc[4] = {0.f, 0.f, 0.f, 0.f};

    for (int jc = 0; jc < DM; jc += 64) {
#pragma unroll
        for (int t = 0; t < 16; t++) {
            int idx = tid + t * 256;
            wt[idx >> 6][idx & 63] = Wk[(long long)(i0 + (idx >> 6)) * DM + jc + (idx & 63)];
        }
#pragma unroll
        for (int t = 0; t < 4; t++) {
            int idx = tid + t * 256;
            cs[idx >> 6][idx & 63] = C[(long long)(idx >> 6) * DM + jc + (idx & 63)];
        }
        __syncthreads();
#pragma unroll
        for (int jj = 0; jj < 64; jj++) {
            float w = wt[i][jj];
            acc[0] += w * cs[qg][jj];
            acc[1] += w * cs[qg + 4][jj];
            acc[2] += w * cs[qg + 8][jj];
            acc[3] += w * cs[qg + 12][jj];
        }
        __syncthreads();
    }
#pragma unroll
    for (int t = 0; t < 4; t++)
        KW[(long long)(qg + t * 4) * DM + i0 + i] = acc[t];
}

// ---------------- C: T[b][h*2+s][j] = sum_i Wq[h*64+i][j] * kw[b][s][h*64+i] ----
__global__ __launch_bounds__(128)
void tvec_kernel(const float* __restrict__ Wq, const float* __restrict__ KW,
                 float* __restrict__ T)
{
    __shared__ float kws[16][64];
    int tid = threadIdx.x;
    int h = blockIdx.y;
    int j = blockIdx.x * 128 + tid;
#pragma unroll
    for (int t = 0; t < 8; t++) {
        int idx = tid + t * 128;
        kws[idx >> 6][idx & 63] = KW[(long long)(idx >> 6) * DM + h * 64 + (idx & 63)];
    }
    __syncthreads();
    float acc[16];
#pragma unroll
    for (int v = 0; v < 16; v++) acc[v] = 0.f;
    for (int ii = 0; ii < 64; ii++) {
        float w = Wq[(long long)(h * 64 + ii) * DM + j];
#pragma unroll
        for (int v = 0; v < 16; v++) acc[v] += w * kws[v][ii];
    }
#pragma unroll
    for (int v = 0; v < 16; v++) {
        int b = v >> 1, s = v & 1;
        T[((long long)b * 24 + h * 2 + s) * DM + j] = acc[v];
    }
}

// ---------------- D: mu/ss ----------------
__global__ __launch_bounds__(256)
void musig_kernel(const float* __restrict__ qin, const float* __restrict__ T,
                  float* __restrict__ mu_out, float* __restrict__ ss_out)
{
    __shared__ float Tc[24][132];
    int tid = threadIdx.x, lane = tid & 31, warp = tid >> 5;
    int rb = blockIdx.x * 8 + warp;
    int b = rb >> 10, qrow = rb & 1023;
    const float* qr = qin + (long long)qrow * (BATCH * DM) + (long long)b * DM;
    const float* Tb = T + (long long)b * 24 * DM;

    float acc[24];
#pragma unroll
    for (int v = 0; v < 24; v++) acc[v] = 0.f;

    for (int kc = 0; kc < 6; kc++) {
        __syncthreads();
#pragma unroll
        for (int t = 0; t < 12; t++) {
            int idx = tid + t * 256;
            Tc[idx >> 7][idx & 127] = Tb[(long long)(idx >> 7) * DM + kc * 128 + (idx & 127)];
        }
        __syncthreads();
        float4 qv = *(const float4*)(qr + kc * 128 + lane * 4);
#pragma unroll
        for (int v = 0; v < 24; v++) {
            float4 tv = *(const float4*)&Tc[v][lane * 4];
            acc[v] += qv.x * tv.x + qv.y * tv.y + qv.z * tv.z + qv.w * tv.w;
        }
    }
#pragma unroll
    for (int v = 0; v < 24; v++)
#pragma unroll
        for (int o = 16; o; o >>= 1)
            acc[v] += __shfl_xor_sync(0xffffffffu, acc[v], o);

    if (lane == 0) {
#pragma unroll
        for (int v = 0; v < 24; v++) {
            int h = v >> 1;
            float d = acc[v] * 0.125f;
            long long o = ((long long)b * NH + h) * LEN + qrow;
            if ((v & 1) == 0) mu_out[o] = 1.f / (1.f + __expf(-d));
            else              ss_out[o] = (d > 20.f) ? d : log1pf(__expf(d));
        }
    }
}

// ---------------- fused r + ctx = r@V ----------------
#define LDS_ROW 40
__global__ __launch_bounds__(256)
void rv_mma_kernel(const float* __restrict__ mu,
                   const float* __restrict__ ss,
                   const float* __restrict__ mu_b,
                   const float* __restrict__ sigma_b,
                   const bf16* __restrict__ Vt0, const bf16* __restrict__ Vt1,
                   bf16* __restrict__ ctx0, bf16* __restrict__ ctx1)
{
    __shared__ __align__(16) bf16 rs0[128 * LDS_ROW];
    __shared__ __align__(16) bf16 rs1[128 * LDS_ROW];
    __shared__ __align__(16) bf16 vs0[64 * LDS_ROW];
    __shared__ __align__(16) bf16 vs1[64 * LDS_ROW];
    __shared__ float invs[128][2];
    __shared__ float mus[128];

    const int tid = threadIdx.x, lane = tid & 31, wid = tid >> 5;
    const int bh = blockIdx.y;
    const int b = bh / NH, h = bh - b * NH;
    const int m0 = blockIdx.x * 128;
    const int rowbase = bh * LEN + m0;

    if (tid < 128) mus[tid] = mu[rowbase + tid];
    {
        int row = tid >> 1, p = tid & 1;
        float sb = sigma_b[p];
        invs[row][p] = rsqrtf(sb * sb + ss[rowbase + row]);
    }
    __syncthreads();

    const float DELTA = 1.0f / 127.0f;
    const float C_PHI = 0.3989422804014327f;
    const int rm = tid >> 1, rp = tid & 1;
    const float r_mu = mus[rm];
    const float r_iv = invs[rm][rp];
    const float rscale = C_PHI * r_iv;
    const float ivd = r_iv * r_iv * DELTA;
    const float Wr = __expf(-ivd * DELTA);

    const int wm = (wid >> 1) * 32, wn = (wid & 1) * 32;
    float acc[2][4][4];
#pragma unroll
    for (int mt = 0; mt < 2; mt++)
#pragma unroll
        for (int nt = 0; nt < 4; nt++)
#pragma unroll
            for (int i = 0; i < 4; i++) acc[mt][nt][i] = 0.f;

    const bf16* vt0 = Vt0 + (long long)bh * DH * NB;
    const bf16* vt1 = Vt1 + (long long)bh * DH * NB;

    const int vrow = tid >> 2, vseg = tid & 3;

    const int brow = ((lane >> 4) << 3) + (lane & 7), bcol8 = ((lane >> 3) & 1) * 8;
    const int arow = lane & 15, acol8 = (lane >> 4) * 8;

    for (int nc = 0; nc < 8; nc++) {
        cpa16(vs0 + vrow * LDS_ROW + vseg * 8, vt0 + (long long)vrow * NB + nc * 32 + vseg * 8);
        cpa16(vs1 + vrow * LDS_ROW + vseg * 8, vt1 + (long long)vrow * NB + nc * 32 + vseg * 8);
        asm volatile("cp.async.commit_group;");

        float dmu = r_mu - (float)(nc * 16) * DELTA;
        float t0 = dmu * r_iv;
        float rv = rscale * __expf(-0.5f * t0 * t0);
        float rR = __expf(ivd * (dmu - 0.5f * DELTA));
        bf16* q0 = rs0 + rm * LDS_ROW + rp;
        bf16* q1 = rs1 + rm * LDS_ROW + rp;
#pragma unroll
        for (int jj = 0; jj < 16; jj++) {
            bf16 hh = __float2bfloat16(rv);
            q0[2 * jj] = hh;
            q1[2 * jj] = __float2bfloat16(rv - __bfloat162float(hh));
            rv *= rR;
            rR *= Wr;
        }
        asm volatile("cp.async.wait_group 0;");
        __syncthreads();

#pragma unroll
        for (int kk = 0; kk < 2; kk++) {
            const int ac = kk * 16 + acol8;
            const int bc = kk * 16 + bcol8;
            uint32_t a0[2][4], a1[2][4], b0[4][2], b1[4][2];
#pragma unroll
            for (int mt = 0; mt < 2; mt++) {
                ldsm4(a0[mt], rs0 + (wm + mt * 16 + arow) * LDS_ROW + ac);
                ldsm4(a1[mt], rs1 + (wm + mt * 16 + arow) * LDS_ROW + ac);
            }
#pragma unroll
            for (int np = 0; np < 2; np++) {
                uint32_t r[4];
                ldsm4(r, vs0 + (wn + np * 16 + brow) * LDS_ROW + bc);
                b0[np * 2][0] = r[0]; b0[np * 2][1] = r[1];
                b0[np * 2 + 1][0] = r[2]; b0[np * 2 + 1][1] = r[3];
                ldsm4(r, vs1 + (wn + np * 16 + brow) * LDS_ROW + bc);
                b1[np * 2][0] = r[0]; b1[np * 2][1] = r[1];
                b1[np * 2 + 1][0] = r[2]; b1[np * 2 + 1][1] = r[3];
            }
#pragma unroll
            for (int mt = 0; mt < 2; mt++)
#pragma unroll
                for (int nt = 0; nt < 4; nt++) {
                    mma16816(acc[mt][nt], a0[mt], b0[nt]);
                    mma16816(acc[mt][nt], a0[mt], b1[nt]);
                    mma16816(acc[mt][nt], a1[mt], b0[nt]);
                }
        }
        __syncthreads();
    }

    const int g = lane >> 2, c2 = (lane & 3) * 2;
#pragma unroll
    for (int mt = 0; mt < 2; mt++) {
#pragma unroll
        for (int nt = 0; nt < 4; nt++) {
            int row = m0 + wm + mt * 16 + g;
            int col = h * DH + wn + nt * 8 + c2;
            float v0 = acc[mt][nt][0], v1 = acc[mt][nt][1];
            float v2 = acc[mt][nt][2], v3 = acc[mt][nt][3];
            long long o0 = (long long)b * LDM_C + (long long)row * DM + col;
            long long o1 = o0 + 8LL * DM;
            bf16 h0 = __float2bfloat16(v0), h1 = __float2bfloat16(v1);
            bf16 h2 = __float2bfloat16(v2), h3 = __float2bfloat16(v3);
            bf16 l0 = __float2bfloat16(v0 - __bfloat162float(h0));
            bf16 l1 = __float2bfloat16(v1 - __bfloat162float(h1));
            bf16 l2 = __float2bfloat16(v2 - __bfloat162float(h2));
            bf16 l3 = __float2bfloat16(v3 - __bfloat162float(h3));
            *(__nv_bfloat162*)(ctx0 + o0) = __nv_bfloat162(h0, h1);
            *(__nv_bfloat162*)(ctx0 + o1) = __nv_bfloat162(h2, h3);
            *(__nv_bfloat162*)(ctx1 + o0) = __nv_bfloat162(l0, l1);
            *(__nv_bfloat162*)(ctx1 + o1) = __nv_bfloat162(l2, l3);
        }
    }
}

// ---------------- launch (2-stream overlap via capture-safe fork/join) -------
extern "C" void kernel_launch(void* const* d_in, const int* in_sizes, int n_in,
                              void* d_out, int out_size)
{
    const float* x       = (const float*)d_in[0];
    const float* q       = (const float*)d_in[1];
    const float* Wq      = (const float*)d_in[2];
    const float* Wk      = (const float*)d_in[3];
    const float* Wv      = (const float*)d_in[4];
    const float* Wo      = (const float*)d_in[5];
    const float* w_mu    = (const float*)d_in[6];
    const float* w_sigma = (const float*)d_in[7];
    const float* mu_b    = (const float*)d_in[8];
    const float* sigma_b = (const float*)d_in[9];
    const float* G       = (const float*)d_in[10];
    float* out = (float*)d_out;

    cudaFuncSetAttribute(mma_gemm, cudaFuncAttributeMaxDynamicSharedMemorySize, GSMEM_BYTES);

    void *pxt0, *pxt1, *pGt0, *pGt1, *pWv0, *pWv1, *pWo0, *pWo1;
    void *pB0, *pB1, *pBp, *pVp, *pVt0, *pVt1;
    void *pC, *pKW, *pT, *pMu, *pSs, *pC0, *pC1;
    cudaGetSymbolAddress(&pxt0, g_xt0); cudaGetSymbolAddress(&pxt1, g_xt1);
    cudaGetSymbolAddress(&pGt0, g_Gt0); cudaGetSymbolAddress(&pGt1, g_Gt1);
    cudaGetSymbolAddress(&pWv0, g_Wv0); cudaGetSymbolAddress(&pWv1, g_Wv1);
    cudaGetSymbolAddress(&pWo0, g_Wo0); cudaGetSymbolAddress(&pWo1, g_Wo1);
    cudaGetSymbolAddress(&pB0, g_B0);   cudaGetSymbolAddress(&pB1, g_B1);
    cudaGetSymbolAddress(&pBp, g_Bp);   cudaGetSymbolAddress(&pVp, g_Vp);
    cudaGetSymbolAddress(&pVt0, g_Vt0); cudaGetSymbolAddress(&pVt1, g_Vt1);
    cudaGetSymbolAddress(&pC, g_C);     cudaGetSymbolAddress(&pKW, g_KW);
    cudaGetSymbolAddress(&pT, g_T);
    cudaGetSymbolAddress(&pMu, g_mu);   cudaGetSymbolAddress(&pSs, g_ss);
    cudaGetSymbolAddress(&pC0, g_ctx0); cudaGetSymbolAddress(&pC1, g_ctx1);

    const long long NBDMll = NBDM;
    const long long DMLN = (long long)DM * LEN;
    dim3 blk(256);

    // side stream + events (host objects; created once, reused every call)
    static cudaStream_t aux = nullptr;
    static cudaEvent_t ev0 = nullptr, evWW = nullptr, evB = nullptr, evMS = nullptr;
    if (aux == nullptr) {
        cudaStreamCreateWithFlags(&aux, cudaStreamNonBlocking);
        cudaEventCreateWithFlags(&ev0,  cudaEventDisableTiming);
        cudaEventCreateWithFlags(&evWW, cudaEventDisableTiming);
        cudaEventCreateWithFlags(&evB,  cudaEventDisableTiming);
        cudaEventCreateWithFlags(&evMS, cudaEventDisableTiming);
    }

    // ---- main stream: transposed splits (x, G) ----
    tsplit_kernel<<<dim3(DM / 32, LEN / 32, BATCH), dim3(32, 8)>>>(
        x, DM, BATCH * DM, (bf16*)pxt0, (bf16*)pxt1, DMLN, LEN);
    tsplit_kernel<<<dim3(NB / 32, LEN / 32, 1), dim3(32, 8)>>>(
        G, 0, NB, (bf16*)pGt0, (bf16*)pGt1, 0, LEN);

    // fork aux stream
    cudaEventRecord(ev0, 0);
    cudaStreamWaitEvent(aux, ev0, 0);

    // ---- aux: Wv/Wo split (independent of everything until V/out GEMMs) ----
    splitWW_kernel<<<dim3((DM * DM) / 1024, 2), blk, 0, aux>>>(
        Wv, Wo, (bf16*)pWv0, (bf16*)pWv1, (bf16*)pWo0, (bf16*)pWo1);
    cudaEventRecord(evWW, aux);

    // ---- main: Bmat split-K=4 (fp32 partials, 384 CTAs @ 2/SM) ----
    mma_gemm<<<dim3(DM / 128, NB / 128, BATCH * 4), blk, GSMEM_BYTES>>>(
        256,
        (bf16*)pGt0, (bf16*)pGt1, LEN, 0, 256,
        (bf16*)pxt0, (bf16*)pxt1, LEN, DMLN, 256,
        (float*)pBp, nullptr, nullptr, DM, 4LL * NBDM, NBDMll,
        4, 1.0f, 0);
    combineB_kernel<<<(BATCH * NBDM) / 1024, blk>>>(
        (const float*)pBp, (bf16*)pB0, (bf16*)pB1);

    // fork: aux runs the mu/sigma chain while main does V GEMM + vtrans
    cudaEventRecord(evB, 0);
    cudaStreamWaitEvent(aux, evB, 0);
    cvec_kernel<<<dim3(DM / 128, BATCH), blk, 0, aux>>>(
        (const bf16*)pB0, (const bf16*)pB1, w_mu, w_sigma, (float*)pC);
    kw_kernel<<<DM / 64, blk, 0, aux>>>(Wk, (const float*)pC, (float*)pKW);
    tvec_kernel<<<dim3(DM / 128, NH), dim3(128), 0, aux>>>(
        Wq, (const float*)pKW, (float*)pT);
    musig_kernel<<<(BATCH * LEN) / 8, blk, 0, aux>>>(
        q, (const float*)pT, (float*)pMu, (float*)pSs);
    cudaEventRecord(evMS, aux);

    // ---- main: V split-K=4 (needs Wv from aux) ----
    cudaStreamWaitEvent(0, evWW, 0);
    mma_gemm<<<dim3(DM / 128, NB / 128, BATCH * 4), blk, GSMEM_BYTES>>>(
        192,
        (bf16*)pB0, (bf16*)pB1, DM, NBDMll, 192,
        (bf16*)pWv0, (bf16*)pWv1, DM, 0, 192,
        (float*)pVp, nullptr, nullptr, DM, 4LL * NBDM, NBDMll,
        4, 1.0f, 0);
    vtrans_kernel<<<dim3(NB / 32, DH / 32, BATCH * NH), dim3(32, 8)>>>(
        (const float*)pVp, (bf16*)pVt0, (bf16*)pVt1);

    // join: rv needs vtrans (main) + musig (aux)
    cudaStreamWaitEvent(0, evMS, 0);
    rv_mma_kernel<<<dim3(LEN / 128, BATCH * NH), blk>>>(
        (const float*)pMu, (const float*)pSs, mu_b, sigma_b,
        (const bf16*)pVt0, (const bf16*)pVt1, (bf16*)pC0, (bf16*)pC1);

    // ---- main: out = ctx @ Wo^T ----
    mma_gemm<<<dim3(DM / 128, LEN / 128, BATCH), blk, GSMEM_BYTES>>>(
        DM,
        (bf16*)pC0, (bf16*)pC1, DM, (long long)LDM_C, 0,
        (bf16*)pWo0, (bf16*)pWo1, DM, 0, 0,
        out, nullptr, nullptr, DM, (long long)LDM_C, 0,
        1, 1.0f, 0);
}